// round 5
// baseline (speedup 1.0000x reference)
#include <cuda_runtime.h>
#include <math.h>

#define NB 8
#define NS 512
#define NL 4096
#define NE 768
#define NHD 384
#define NGE 32

// ---------------------------------------------------------------------------
// Static device scratch
// ---------------------------------------------------------------------------
__device__ float g_Q  [NB * NS * NE];
__device__ float g_Kf [NB * NL * NE];
__device__ float g_Vt [NB * NE * NL];      // V transposed: [b][e][l]
__device__ float g_Sc [NB * 2 * NS * NL];  // scores; reused for split-K partials
__device__ float g_O  [NB * NS * NE];
__device__ float g_WqT[NE * NE];
__device__ float g_WkT[NE * NGE];
__device__ float g_WvT[NE * NGE];
__device__ float g_WoT[NE * NE];
__device__ unsigned char g_qm[NB * NS];
__device__ unsigned char g_km[NB * NL];
__device__ float g_lam;
__device__ int   g_mode;

// ---------------------------------------------------------------------------
// Small helper kernels
// ---------------------------------------------------------------------------
__global__ void detect_mode_kernel(const unsigned int* __restrict__ w, int nwords)
{
    __shared__ int bad_i32, bad_f32, any_nz;
    if (threadIdx.x == 0) { bad_i32 = 0; bad_f32 = 0; any_nz = 0; }
    __syncthreads();
    for (int i = threadIdx.x; i < nwords; i += blockDim.x) {
        unsigned int v = w[i];
        if (v != 0u) {
            atomicOr(&any_nz, 1);
            if (v != 1u)           atomicOr(&bad_i32, 1);
            if (v != 0x3F800000u)  atomicOr(&bad_f32, 1);
        }
    }
    __syncthreads();
    if (threadIdx.x == 0) {
        int mode = 0;
        if (any_nz && !bad_i32)      mode = 1;
        else if (any_nz && !bad_f32) mode = 2;
        g_mode = mode;
    }
}

__device__ __forceinline__ unsigned char read_mask(const void* p, int i, int mode)
{
    if (mode == 1) return ((const int*)p)[i] != 0;
    if (mode == 2) return ((const float*)p)[i] != 0.0f;
    return ((const unsigned char*)p)[i] != 0;
}

__global__ void expand_masks_kernel(const void* __restrict__ qmask,
                                    const void* __restrict__ kmask)
{
    int i = blockIdx.x * blockDim.x + threadIdx.x;
    int mode = g_mode;
    if (i < NB * NS) g_qm[i] = read_mask(qmask, i, mode);
    if (i < NB * NL) g_km[i] = read_mask(kmask, i, mode);
}

__global__ void lam_kernel(const float* __restrict__ lq1, const float* __restrict__ lk1,
                           const float* __restrict__ lq2, const float* __restrict__ lk2)
{
    __shared__ float r1[256], r2[256];
    int t = threadIdx.x;
    float a = 0.f, b = 0.f;
    for (int i = t; i < NHD; i += 256) { a += lq1[i] * lk1[i]; b += lq2[i] * lk2[i]; }
    r1[t] = a; r2[t] = b; __syncthreads();
    for (int s = 128; s > 0; s >>= 1) {
        if (t < s) { r1[t] += r1[t + s]; r2[t] += r2[t + s]; }
        __syncthreads();
    }
    if (t == 0) g_lam = expf(r1[0]) - expf(r2[0]) + 0.2f;
}

// in[rows][cols] -> out[cols][rows]
__global__ void transpose_kernel(const float* __restrict__ in, float* __restrict__ out,
                                 int rows, int cols)
{
    __shared__ float tile[32][33];
    int c0 = blockIdx.x * 32, r0 = blockIdx.y * 32;
    int x = threadIdx.x, y = threadIdx.y;   // block (32, 8)
    for (int i = 0; i < 32; i += 8) {
        int r = r0 + y + i, c = c0 + x;
        if (r < rows && c < cols) tile[y + i][x] = in[(long)r * cols + c];
    }
    __syncthreads();
    for (int i = 0; i < 32; i += 8) {
        int r = c0 + y + i, c = r0 + x;
        if (r < cols && c < rows) out[(long)r * rows + c] = tile[x][y + i];
    }
}

// ---------------------------------------------------------------------------
// tf32 NT GEMM: C[M,N] = alpha * A[M,K] * B[N,K]^T  (both row-major)
//   128x128 block tile, BK=32, 256 threads (8 warps, 32x64 warp tiles),
//   4-stage cp.async pipeline, ldmatrix fragments, cvt.rna.tf32 at frag load.
//   EPI 0: alpha*acc   EPI 1: scores mask   EPI 2: transposed V write
// ---------------------------------------------------------------------------
#define STAGES 4
#define AS_FLOATS 4608                       // 128*36 per stage
#define B_BASE (STAGES * AS_FLOATS)          // 18432 floats
#define SMEM_BYTES (2 * STAGES * AS_FLOATS * 4)   // 147456 B

__device__ __forceinline__ unsigned cvt_tf32(unsigned x)
{
    unsigned o;
    asm("cvt.rna.tf32.f32 %0, %1;" : "=r"(o) : "f"(__uint_as_float(x)));
    return o;
}

__device__ __forceinline__ void cpa16(unsigned dst, const void* src)
{
    asm volatile("cp.async.cg.shared.global [%0], [%1], 16;" :: "r"(dst), "l"(src));
}

__device__ __forceinline__ void ldm4(unsigned& r0, unsigned& r1, unsigned& r2, unsigned& r3,
                                     unsigned addr)
{
    asm volatile("ldmatrix.sync.aligned.m8n8.x4.shared.b16 {%0,%1,%2,%3}, [%4];"
                 : "=r"(r0), "=r"(r1), "=r"(r2), "=r"(r3) : "r"(addr));
}

__device__ __forceinline__ void mma8(float* d, const unsigned* a, const unsigned* b)
{
    asm volatile(
        "mma.sync.aligned.m16n8k8.row.col.f32.tf32.tf32.f32 "
        "{%0,%1,%2,%3}, {%4,%5,%6,%7}, {%8,%9}, {%0,%1,%2,%3};"
        : "+f"(d[0]), "+f"(d[1]), "+f"(d[2]), "+f"(d[3])
        : "r"(a[0]), "r"(a[1]), "r"(a[2]), "r"(a[3]), "r"(b[0]), "r"(b[1]));
}

template<int EPI>
__device__ __forceinline__ void gemm_nt(
    const float* __restrict__ A, const float* __restrict__ B, float* __restrict__ C,
    int K, int lda, int ldb, int ldc, float alpha,
    const unsigned char* __restrict__ qm, const unsigned char* __restrict__ km)
{
    extern __shared__ float smdyn[];
    const unsigned smb = (unsigned)__cvta_generic_to_shared(smdyn);

    const int tid  = threadIdx.x;
    const int lane = tid & 31;
    const int wid  = tid >> 5;
    const int wm   = wid & 3;
    const int wn   = wid >> 2;
    const int lc   = lane & 3;
    const int lr   = lane >> 2;
    const int bm   = blockIdx.y * 128;
    const int bn   = blockIdx.x * 128;

    // cp.async addressing (per thread, 4 A rows + 4 B rows of 16B each)
    const int ldrow = tid >> 3;            // 0..31, +32 per i
    const int ldc4  = (tid & 7) << 2;      // 0,4,..,28
    const unsigned a_dst0 = smb + (unsigned)(ldrow * 36 + ldc4) * 4u;
    const unsigned b_dst0 = smb + (unsigned)(B_BASE + ldrow * 36 + ldc4) * 4u;

    // ldmatrix lane addresses (bytes, relative to stage 0)
    const unsigned a_lane = smb +
        (unsigned)((wm * 32 + ((lane >> 3) & 1) * 8 + (lane & 7)) * 36 + (lane >> 4) * 4) * 4u;
    const unsigned b_lane = smb +
        (unsigned)(B_BASE + (wn * 64 + ((lane >> 4) & 1) * 8 + (lane & 7)) * 36
                   + ((lane >> 3) & 1) * 4) * 4u;

    float d[2][8][4];
#pragma unroll
    for (int mt = 0; mt < 2; mt++)
#pragma unroll
        for (int nt = 0; nt < 8; nt++)
#pragma unroll
            for (int i = 0; i < 4; i++) d[mt][nt][i] = 0.f;

    const int ntile = K >> 5;

#define ISSUE_TILE(T, ST)                                                          \
    do {                                                                           \
        const int k0_ = (T) << 5;                                                  \
        const float* Ap_ = A + (long)(bm + ldrow) * lda + (k0_ + ldc4);            \
        const float* Bp_ = B + (long)(bn + ldrow) * ldb + (k0_ + ldc4);            \
        const unsigned ad_ = a_dst0 + (unsigned)(ST) * (AS_FLOATS * 4);            \
        const unsigned bd_ = b_dst0 + (unsigned)(ST) * (AS_FLOATS * 4);            \
        _Pragma("unroll")                                                          \
        for (int i_ = 0; i_ < 4; i_++) {                                           \
            cpa16(ad_ + i_ * (32 * 36 * 4), Ap_ + (long)i_ * 32 * lda);            \
            cpa16(bd_ + i_ * (32 * 36 * 4), Bp_ + (long)i_ * 32 * ldb);            \
        }                                                                          \
    } while (0)

    // prologue: prefetch up to 3 tiles
#pragma unroll
    for (int s = 0; s < STAGES - 1; s++) {
        if (s < ntile) ISSUE_TILE(s, s);
        asm volatile("cp.async.commit_group;");
    }

    for (int t = 0; t < ntile; t++) {
        asm volatile("cp.async.wait_group %0;" :: "n"(STAGES - 2));
        __syncthreads();
        if (t + STAGES - 1 < ntile) ISSUE_TILE(t + STAGES - 1, (t + STAGES - 1) & (STAGES - 1));
        asm volatile("cp.async.commit_group;");

        const int st = t & (STAGES - 1);
        const unsigned sa = a_lane + (unsigned)st * (AS_FLOATS * 4);
        const unsigned sb = b_lane + (unsigned)st * (AS_FLOATS * 4);
#pragma unroll
        for (int kk = 0; kk < 4; kk++) {
            unsigned af[2][4];
#pragma unroll
            for (int mt = 0; mt < 2; mt++) {
                unsigned a0, a1, a2, a3;
                ldm4(a0, a1, a2, a3, sa + mt * (16 * 36 * 4) + kk * 32);
                af[mt][0] = cvt_tf32(a0); af[mt][1] = cvt_tf32(a1);
                af[mt][2] = cvt_tf32(a2); af[mt][3] = cvt_tf32(a3);
            }
#pragma unroll
            for (int p = 0; p < 4; p++) {
                unsigned b0, b1, b2, b3;
                ldm4(b0, b1, b2, b3, sb + p * (16 * 36 * 4) + kk * 32);
                unsigned bf0[2] = { cvt_tf32(b0), cvt_tf32(b1) };
                unsigned bf1[2] = { cvt_tf32(b2), cvt_tf32(b3) };
                mma8(d[0][2 * p + 0], af[0], bf0);
                mma8(d[0][2 * p + 1], af[0], bf1);
                mma8(d[1][2 * p + 0], af[1], bf0);
                mma8(d[1][2 * p + 1], af[1], bf1);
            }
        }
    }
#undef ISSUE_TILE

    // epilogue
#pragma unroll
    for (int mt = 0; mt < 2; mt++) {
        const int m0 = bm + wm * 32 + mt * 16 + lr;
        const bool qa = (EPI == 1) ? (qm[m0] != 0)     : true;
        const bool qb = (EPI == 1) ? (qm[m0 + 8] != 0) : true;
#pragma unroll
        for (int nt = 0; nt < 8; nt++) {
            const int n0 = bn + wn * 64 + nt * 8 + lc * 2;
            if (EPI == 0) {
                float2 v01 = make_float2(alpha * d[mt][nt][0], alpha * d[mt][nt][1]);
                float2 v23 = make_float2(alpha * d[mt][nt][2], alpha * d[mt][nt][3]);
                *(float2*)(C + (long)m0 * ldc + n0)       = v01;
                *(float2*)(C + (long)(m0 + 8) * ldc + n0) = v23;
            } else if (EPI == 1) {
                const bool k0m = km[n0] != 0;
                const bool k1m = km[n0 + 1] != 0;
                float2 v01, v23;
                v01.x = (qa && k0m) ? d[mt][nt][0] : -1e20f;
                v01.y = (qa && k1m) ? d[mt][nt][1] : -1e20f;
                v23.x = (qb && k0m) ? d[mt][nt][2] : -1e20f;
                v23.y = (qb && k1m) ? d[mt][nt][3] : -1e20f;
                *(float2*)(C + (long)m0 * ldc + n0)       = v01;
                *(float2*)(C + (long)(m0 + 8) * ldc + n0) = v23;
            } else {
                // transposed V write: row m -> (b, l), col n -> e
                const int b = m0 >> 12;
                const int l = m0 & (NL - 1);
                float* vt = C + (long)b * NE * NL;
                vt[(long)(n0 + 0) * NL + l]     = d[mt][nt][0];
                vt[(long)(n0 + 1) * NL + l]     = d[mt][nt][1];
                vt[(long)(n0 + 0) * NL + l + 8] = d[mt][nt][2];
                vt[(long)(n0 + 1) * NL + l + 8] = d[mt][nt][3];
            }
        }
    }
}

// Entry points --------------------------------------------------------------
__global__ void __launch_bounds__(256) k_gemm(
    const float* __restrict__ A, const float* __restrict__ B, float* __restrict__ C,
    int K, int lda, int ldb, int ldc, float alpha)
{
    gemm_nt<0>(A, B, C, K, lda, ldb, ldc, alpha, nullptr, nullptr);
}

__global__ void __launch_bounds__(256) k_vproj(const float* __restrict__ key)
{
    gemm_nt<2>(key, g_WvT, g_Vt, NGE, NGE, NGE, 0, 1.0f, nullptr, nullptr);
}

__global__ void __launch_bounds__(256) k_scores()
{
    const int z = blockIdx.z, b = z >> 1, h = z & 1;
    gemm_nt<1>(g_Q + (long)b * NS * NE + h * NHD,
               g_Kf + (long)b * NL * NE + h * NHD,
               g_Sc + (long)z * NS * NL,
               NHD, NE, NE, NL, 1.0f,
               g_qm + b * NS, g_km + b * NL);
}

__global__ void __launch_bounds__(256) k_dwv(const float* __restrict__ dw,
                                             float* __restrict__ part)
{
    const int z = blockIdx.z, b = z >> 2, c = z & 3;
    gemm_nt<0>(dw + (long)b * NS * NL + c * 1024,
               g_Vt + (long)b * NE * NL + c * 1024,
               part + (long)z * NS * NE,
               1024, NL, NL, NE, 1.0f, nullptr, nullptr);
}

// ---------------------------------------------------------------------------
// Dual softmax -> differential weights
// ---------------------------------------------------------------------------
__global__ void __launch_bounds__(256) softmax_dw_kernel(float* __restrict__ dw_out)
{
    __shared__ float s0[NL];
    __shared__ float s1[NL];
    __shared__ float red[256];
    const int row = blockIdx.x;
    const int b = row >> 9;
    const int t = threadIdx.x;
    const float* r0 = g_Sc + ((long)(b * 2 + 0) * NS + (row & (NS - 1))) * NL;
    const float* r1 = g_Sc + ((long)(b * 2 + 1) * NS + (row & (NS - 1))) * NL;

    float m0 = -3.4e38f, m1 = -3.4e38f;
    for (int i = t * 4; i < NL; i += 1024) {
        float4 v0 = *(const float4*)(r0 + i);
        float4 v1 = *(const float4*)(r1 + i);
        *(float4*)&s0[i] = v0; *(float4*)&s1[i] = v1;
        m0 = fmaxf(m0, fmaxf(fmaxf(v0.x, v0.y), fmaxf(v0.z, v0.w)));
        m1 = fmaxf(m1, fmaxf(fmaxf(v1.x, v1.y), fmaxf(v1.z, v1.w)));
    }
    red[t] = m0; __syncthreads();
    for (int s = 128; s > 0; s >>= 1) { if (t < s) red[t] = fmaxf(red[t], red[t + s]); __syncthreads(); }
    m0 = red[0]; __syncthreads();
    red[t] = m1; __syncthreads();
    for (int s = 128; s > 0; s >>= 1) { if (t < s) red[t] = fmaxf(red[t], red[t + s]); __syncthreads(); }
    m1 = red[0]; __syncthreads();

    float sum0 = 0.f, sum1 = 0.f;
    for (int i = t; i < NL; i += 256) {
        float e0 = expf(s0[i] - m0); s0[i] = e0; sum0 += e0;
        float e1 = expf(s1[i] - m1); s1[i] = e1; sum1 += e1;
    }
    red[t] = sum0; __syncthreads();
    for (int s = 128; s > 0; s >>= 1) { if (t < s) red[t] += red[t + s]; __syncthreads(); }
    sum0 = red[0]; __syncthreads();
    red[t] = sum1; __syncthreads();
    for (int s = 128; s > 0; s >>= 1) { if (t < s) red[t] += red[t + s]; __syncthreads(); }
    sum1 = red[0]; __syncthreads();

    const float inv0 = 1.f / (sum0 + 1e-8f);
    const float inv1 = 1.f / (sum1 + 1e-8f);
    const float lam = g_lam;
    float mn = 3.4e38f;
    for (int i = t; i < NL; i += 256) {
        float v = s0[i] * inv0 - lam * (s1[i] * inv1);
        s0[i] = v;
        mn = fminf(mn, v);
    }
    red[t] = mn; __syncthreads();
    for (int s = 128; s > 0; s >>= 1) { if (t < s) red[t] = fminf(red[t], red[t + s]); __syncthreads(); }
    mn = red[0]; __syncthreads();

    const unsigned char qv = g_qm[row];
    const unsigned char* km = g_km + b * NL;
    float* o = dw_out + (long)row * NL;
    for (int i = t; i < NL; i += 256) {
        float v = s0[i] - mn + 1e-5f;
        if (!qv || !km[i]) v = 0.f;
        o[i] = v;
    }
}

// ---------------------------------------------------------------------------
// Sum 4 split-K partials + RMSNorm * rms_w * (1 - LAMBDA_INIT)
// ---------------------------------------------------------------------------
__global__ void __launch_bounds__(256) rmsnorm4_kernel(const float* __restrict__ part,
                                                       float* __restrict__ O,
                                                       const float* __restrict__ w)
{
    __shared__ float red[256];
    __shared__ float buf[NE];
    const int row = blockIdx.x;
    const int b = row >> 9, s = row & (NS - 1);
    const int t = threadIdx.x;
    const long base0 = ((long)(b * 4 + 0) * NS + s) * NE;
    const long base1 = ((long)(b * 4 + 1) * NS + s) * NE;
    const long base2 = ((long)(b * 4 + 2) * NS + s) * NE;
    const long base3 = ((long)(b * 4 + 3) * NS + s) * NE;
    float ss = 0.f;
    for (int i = t; i < NE; i += 256) {
        float v = part[base0 + i] + part[base1 + i] + part[base2 + i] + part[base3 + i];
        buf[i] = v;
        ss += v * v;
    }
    red[t] = ss; __syncthreads();
    for (int st = 128; st > 0; st >>= 1) { if (t < st) red[t] += red[t + st]; __syncthreads(); }
    const float sc = (1.0f / sqrtf(red[0] / (float)NE + 1e-5f)) * 0.8f;
    float* o = O + (long)row * NE;
    for (int i = t; i < NE; i += 256) o[i] = buf[i] * sc * w[i];
}

// ---------------------------------------------------------------------------
// Launch
// ---------------------------------------------------------------------------
extern "C" void kernel_launch(void* const* d_in, const int* in_sizes, int n_in,
                              void* d_out, int out_size)
{
    const float* query = (const float*)d_in[0];
    const float* key   = (const float*)d_in[1];
    const void*  qmask = d_in[2];
    const void*  kmask = d_in[3];
    const float* Wq    = (const float*)d_in[4];
    const float* Wk    = (const float*)d_in[5];
    const float* Wv    = (const float*)d_in[6];
    const float* Wout  = (const float*)d_in[7];
    const float* lq1   = (const float*)d_in[8];
    const float* lk1   = (const float*)d_in[9];
    const float* lq2   = (const float*)d_in[10];
    const float* lk2   = (const float*)d_in[11];
    const float* rms_w = (const float*)d_in[12];

    float* out = (float*)d_out;
    float* dw  = out + (long)NB * NS * NE;

    void* p;
    float *Qp, *Op, *Scp, *WqTp, *WkTp, *WvTp, *WoTp;
    cudaGetSymbolAddress(&p, g_Q);   Qp   = (float*)p;
    cudaGetSymbolAddress(&p, g_O);   Op   = (float*)p;
    cudaGetSymbolAddress(&p, g_Sc);  Scp  = (float*)p;
    cudaGetSymbolAddress(&p, g_WqT); WqTp = (float*)p;
    cudaGetSymbolAddress(&p, g_WkT); WkTp = (float*)p;
    cudaGetSymbolAddress(&p, g_WvT); WvTp = (float*)p;
    cudaGetSymbolAddress(&p, g_WoT); WoTp = (float*)p;
    float *Kfp;
    cudaGetSymbolAddress(&p, g_Kf);  Kfp  = (float*)p;

    cudaFuncSetAttribute(k_gemm,   cudaFuncAttributeMaxDynamicSharedMemorySize, SMEM_BYTES);
    cudaFuncSetAttribute(k_vproj,  cudaFuncAttributeMaxDynamicSharedMemorySize, SMEM_BYTES);
    cudaFuncSetAttribute(k_scores, cudaFuncAttributeMaxDynamicSharedMemorySize, SMEM_BYTES);
    cudaFuncSetAttribute(k_dwv,    cudaFuncAttributeMaxDynamicSharedMemorySize, SMEM_BYTES);

    // 0) weight transposes (all GEMMs become NT)
    dim3 tb(32, 8);
    transpose_kernel<<<dim3(24, 24), tb>>>(Wq,   WqTp, NE, NE);
    transpose_kernel<<<dim3(24, 1),  tb>>>(Wk,   WkTp, NGE, NE);
    transpose_kernel<<<dim3(24, 1),  tb>>>(Wv,   WvTp, NGE, NE);
    transpose_kernel<<<dim3(24, 24), tb>>>(Wout, WoTp, NE, NE);

    // 1) masks + lambda
    detect_mode_kernel<<<1, 256>>>((const unsigned int*)kmask, (NB * NL) / 4);
    expand_masks_kernel<<<(NB * NL + 255) / 256, 256>>>(qmask, kmask);
    lam_kernel<<<1, 256>>>(lq1, lk1, lq2, lk2);

    // 2) projections
    const float qscale = 1.0f / sqrtf((float)NHD);
    k_gemm<<<dim3(NE / 128, (NB * NS) / 128), 256, SMEM_BYTES>>>(
        query, WqTp, Qp, NE, NE, NE, NE, qscale);
    k_gemm<<<dim3(NE / 128, (NB * NL) / 128), 256, SMEM_BYTES>>>(
        key, WkTp, Kfp, NGE, NGE, NGE, NE, 1.0f);
    k_vproj<<<dim3(NE / 128, (NB * NL) / 128), 256, SMEM_BYTES>>>(key);

    // 3) masked scores (both heads)
    k_scores<<<dim3(NL / 128, NS / 128, NB * 2), 256, SMEM_BYTES>>>();

    // 4) dual softmax -> differential weights (direct to d_out)
    softmax_dw_kernel<<<NB * NS, 256>>>(dw);

    // 5) o = dw @ V (split-K=4 over L, partials in g_Sc)
    k_dwv<<<dim3(NE / 128, NS / 128, NB * 4), 256, SMEM_BYTES>>>(dw, Scp);

    // 6) reduce + RMSNorm
    rmsnorm4_kernel<<<NB * NS, 256>>>(Scp, Op, rms_w);

    // 7) out = o @ Wout
    k_gemm<<<dim3(NE / 128, (NB * NS) / 128), 256, SMEM_BYTES>>>(
        Op, WoTp, out, NE, NE, NE, NE, 1.0f);
}

// round 6
// speedup vs baseline: 1.1383x; 1.1383x over previous
#include <cuda_runtime.h>
#include <math.h>

#define NB 8
#define NS 512
#define NL 4096
#define NE 768
#define NHD 384
#define NGE 32

// ---------------------------------------------------------------------------
// Static device scratch
// ---------------------------------------------------------------------------
__device__ float g_Q  [NB * NS * NE];
__device__ float g_Kf [NB * NL * NE];
__device__ float g_Vf [NB * NL * NE];      // V row-major [b*L + l][e]
__device__ float g_Sc [NB * 2 * NS * NL];  // scores; reused for split-K partials
__device__ float g_O  [NB * NS * NE];
__device__ float g_WqT[NE * NE];
__device__ float g_WkT[NE * NGE];
__device__ float g_WvT[NE * NGE];
__device__ float g_WoT[NE * NE];
__device__ unsigned char g_qm[NB * NS];
__device__ unsigned char g_km[NB * NL];
__device__ float g_lam;
__device__ int   g_mode;

// ---------------------------------------------------------------------------
// Small helper kernels
// ---------------------------------------------------------------------------
__global__ void detect_mode_kernel(const unsigned int* __restrict__ w, int nwords)
{
    __shared__ int bad_i32, bad_f32, any_nz;
    if (threadIdx.x == 0) { bad_i32 = 0; bad_f32 = 0; any_nz = 0; }
    __syncthreads();
    for (int i = threadIdx.x; i < nwords; i += blockDim.x) {
        unsigned int v = w[i];
        if (v != 0u) {
            atomicOr(&any_nz, 1);
            if (v != 1u)           atomicOr(&bad_i32, 1);
            if (v != 0x3F800000u)  atomicOr(&bad_f32, 1);
        }
    }
    __syncthreads();
    if (threadIdx.x == 0) {
        int mode = 0;
        if (any_nz && !bad_i32)      mode = 1;
        else if (any_nz && !bad_f32) mode = 2;
        g_mode = mode;
    }
}

__device__ __forceinline__ unsigned char read_mask(const void* p, int i, int mode)
{
    if (mode == 1) return ((const int*)p)[i] != 0;
    if (mode == 2) return ((const float*)p)[i] != 0.0f;
    return ((const unsigned char*)p)[i] != 0;
}

__global__ void expand_masks_kernel(const void* __restrict__ qmask,
                                    const void* __restrict__ kmask)
{
    int i = blockIdx.x * blockDim.x + threadIdx.x;
    int mode = g_mode;
    if (i < NB * NS) g_qm[i] = read_mask(qmask, i, mode);
    if (i < NB * NL) g_km[i] = read_mask(kmask, i, mode);
}

__global__ void lam_kernel(const float* __restrict__ lq1, const float* __restrict__ lk1,
                           const float* __restrict__ lq2, const float* __restrict__ lk2)
{
    __shared__ float r1[256], r2[256];
    int t = threadIdx.x;
    float a = 0.f, b = 0.f;
    for (int i = t; i < NHD; i += 256) { a += lq1[i] * lk1[i]; b += lq2[i] * lk2[i]; }
    r1[t] = a; r2[t] = b; __syncthreads();
    for (int s = 128; s > 0; s >>= 1) {
        if (t < s) { r1[t] += r1[t + s]; r2[t] += r2[t + s]; }
        __syncthreads();
    }
    if (t == 0) g_lam = expf(r1[0]) - expf(r2[0]) + 0.2f;
}

__global__ void transpose_kernel(const float* __restrict__ in, float* __restrict__ out,
                                 int rows, int cols)
{
    __shared__ float tile[32][33];
    int c0 = blockIdx.x * 32, r0 = blockIdx.y * 32;
    int x = threadIdx.x, y = threadIdx.y;
    for (int i = 0; i < 32; i += 8) {
        int r = r0 + y + i, c = c0 + x;
        if (r < rows && c < cols) tile[y + i][x] = in[(long)r * cols + c];
    }
    __syncthreads();
    for (int i = 0; i < 32; i += 8) {
        int r = c0 + y + i, c = r0 + x;
        if (r < cols && c < rows) out[(long)r * rows + c] = tile[x][y + i];
    }
}

// ---------------------------------------------------------------------------
// tf32 GEMM core. 128x128 tiles, BK=32, 256 threads, 3-stage cp.async,
// 2 CTAs/SM. TRANSB=1: C = A[M,K] * B[N,K]^T. TRANSB=0: C = A[M,K] * B[K,N].
// EPI 0: alpha*acc.  EPI 1: scores mask epilogue.
// ---------------------------------------------------------------------------
#define STAGES 3
#define STG_FLOATS 9216          // A: 128*36, B: 4608 floats reserved
#define B_OFF 4608
#define SMEM_BYTES (STAGES * STG_FLOATS * 4)   // 110592 B

__device__ __forceinline__ unsigned cvt_tf32(unsigned x)
{
    unsigned o;
    asm("cvt.rna.tf32.f32 %0, %1;" : "=r"(o) : "f"(__uint_as_float(x)));
    return o;
}
__device__ __forceinline__ float cvt_tf32f(float x)
{
    unsigned o;
    asm("cvt.rna.tf32.f32 %0, %1;" : "=r"(o) : "f"(x));
    return __uint_as_float(o);
}

__device__ __forceinline__ void cpa16(unsigned dst, const void* src)
{
    asm volatile("cp.async.cg.shared.global [%0], [%1], 16;" :: "r"(dst), "l"(src));
}

__device__ __forceinline__ void ldm4(unsigned& r0, unsigned& r1, unsigned& r2, unsigned& r3,
                                     unsigned addr)
{
    asm volatile("ldmatrix.sync.aligned.m8n8.x4.shared.b16 {%0,%1,%2,%3}, [%4];"
                 : "=r"(r0), "=r"(r1), "=r"(r2), "=r"(r3) : "r"(addr));
}

__device__ __forceinline__ void mma8(float* d, const unsigned* a, const unsigned* b)
{
    asm volatile(
        "mma.sync.aligned.m16n8k8.row.col.f32.tf32.tf32.f32 "
        "{%0,%1,%2,%3}, {%4,%5,%6,%7}, {%8,%9}, {%0,%1,%2,%3};"
        : "+f"(d[0]), "+f"(d[1]), "+f"(d[2]), "+f"(d[3])
        : "r"(a[0]), "r"(a[1]), "r"(a[2]), "r"(a[3]), "r"(b[0]), "r"(b[1]));
}

template<bool TRANSB, int EPI>
__device__ __forceinline__ void gemm_core(
    const float* __restrict__ A, const float* __restrict__ B, float* __restrict__ C,
    int K, int lda, int ldb, int ldc, float alpha,
    const unsigned char* __restrict__ qm, const unsigned char* __restrict__ km)
{
    extern __shared__ float smf[];
    const unsigned smb = (unsigned)__cvta_generic_to_shared(smf);

    const int tid  = threadIdx.x;
    const int lane = tid & 31;
    const int wid  = tid >> 5;
    const int wm   = wid & 3;
    const int wn   = wid >> 2;
    const int lc   = lane & 3;
    const int lr   = lane >> 2;
    const int bm   = blockIdx.y * 128;
    const int bn   = blockIdx.x * 128;

    // cp.async thread mapping
    const int ldrow = tid >> 3;            // 0..31
    const int ldc4  = (tid & 7) << 2;      // 0..28 step 4

    // ldmatrix lane byte addrs (stage 0)
    const unsigned a_lane = smb +
        (unsigned)((wm * 32 + ((lane >> 3) & 1) * 8 + (lane & 7)) * 36 + (lane >> 4) * 4) * 4u;
    const unsigned b_lane = smb +
        (unsigned)(B_OFF + (wn * 64 + ((lane >> 4) & 1) * 8 + (lane & 7)) * 36
                   + ((lane >> 3) & 1) * 4) * 4u;

    float d[2][8][4];
#pragma unroll
    for (int mt = 0; mt < 2; mt++)
#pragma unroll
        for (int nt = 0; nt < 8; nt++)
#pragma unroll
            for (int i = 0; i < 4; i++) d[mt][nt][i] = 0.f;

    const int ntile = K >> 5;

#define ISSUE_TILE(T, ST)                                                           \
    do {                                                                            \
        const int k0_ = (T) << 5;                                                   \
        const unsigned sg_ = smb + (unsigned)(ST) * (STG_FLOATS * 4);               \
        const float* Ap_ = A + (long)(bm + ldrow) * lda + (k0_ + ldc4);             \
        const unsigned ad_ = sg_ + (unsigned)(ldrow * 36 + ldc4) * 4u;              \
        _Pragma("unroll")                                                           \
        for (int i_ = 0; i_ < 4; i_++)                                              \
            cpa16(ad_ + i_ * (32 * 36 * 4), Ap_ + (long)i_ * 32 * lda);             \
        if (TRANSB) {                                                               \
            const float* Bp_ = B + (long)(bn + ldrow) * ldb + (k0_ + ldc4);         \
            const unsigned bd_ = sg_ + (unsigned)(B_OFF + ldrow * 36 + ldc4) * 4u;  \
            _Pragma("unroll")                                                       \
            for (int i_ = 0; i_ < 4; i_++)                                          \
                cpa16(bd_ + i_ * (32 * 36 * 4), Bp_ + (long)i_ * 32 * ldb);         \
        } else {                                                                    \
            const float* Bp_ = B + (long)(k0_ + ldrow) * ldb + (bn + ldc4);         \
            const unsigned bd_ = sg_ + (unsigned)(B_OFF + ldrow * 136 + ldc4) * 4u; \
            _Pragma("unroll")                                                       \
            for (int i_ = 0; i_ < 4; i_++)                                          \
                cpa16(bd_ + i_ * 128, Bp_ + i_ * 32);                               \
        }                                                                           \
    } while (0)

    // prologue: prefetch 2 tiles
#pragma unroll
    for (int s = 0; s < STAGES - 1; s++) {
        if (s < ntile) ISSUE_TILE(s, s);
        asm volatile("cp.async.commit_group;");
    }

    int stq = 0;  // stage of tile t (cycles 0,1,2)
    for (int t = 0; t < ntile; t++) {
        asm volatile("cp.async.wait_group %0;" :: "n"(STAGES - 2));
        __syncthreads();
        {
            int tp = t + STAGES - 1;
            if (tp < ntile) {
                int stp = stq + STAGES - 1; if (stp >= STAGES) stp -= STAGES;
                ISSUE_TILE(tp, stp);
            }
        }
        asm volatile("cp.async.commit_group;");

        const unsigned sgb = (unsigned)stq * (STG_FLOATS * 4);
        const unsigned sa = a_lane + sgb;
        const unsigned sb = b_lane + sgb;
        const int bbase = stq * STG_FLOATS + B_OFF;
#pragma unroll
        for (int kk = 0; kk < 4; kk++) {
            unsigned af[2][4];
#pragma unroll
            for (int mt = 0; mt < 2; mt++) {
                unsigned a0, a1, a2, a3;
                ldm4(a0, a1, a2, a3, sa + mt * (16 * 36 * 4) + kk * 32);
                af[mt][0] = cvt_tf32(a0); af[mt][1] = cvt_tf32(a1);
                af[mt][2] = cvt_tf32(a2); af[mt][3] = cvt_tf32(a3);
            }
            if (TRANSB) {
#pragma unroll
                for (int p = 0; p < 4; p++) {
                    unsigned b0, b1, b2, b3;
                    ldm4(b0, b1, b2, b3, sb + p * (16 * 36 * 4) + kk * 32);
                    unsigned bf0[2] = { cvt_tf32(b0), cvt_tf32(b1) };
                    unsigned bf1[2] = { cvt_tf32(b2), cvt_tf32(b3) };
                    mma8(d[0][2 * p + 0], af[0], bf0);
                    mma8(d[0][2 * p + 1], af[0], bf1);
                    mma8(d[1][2 * p + 0], af[1], bf0);
                    mma8(d[1][2 * p + 1], af[1], bf1);
                }
            } else {
                const int kb = (kk << 3) + lc;
#pragma unroll
                for (int nt = 0; nt < 8; nt++) {
                    const int n = wn * 64 + nt * 8 + lr;
                    unsigned bf[2];
                    bf[0] = __float_as_uint(cvt_tf32f(smf[bbase + kb * 136 + n]));
                    bf[1] = __float_as_uint(cvt_tf32f(smf[bbase + (kb + 4) * 136 + n]));
                    mma8(d[0][nt], af[0], bf);
                    mma8(d[1][nt], af[1], bf);
                }
            }
        }
        if (++stq == STAGES) stq = 0;
    }
#undef ISSUE_TILE

    // epilogue
#pragma unroll
    for (int mt = 0; mt < 2; mt++) {
        const int m0 = bm + wm * 32 + mt * 16 + lr;
        const bool qa = (EPI == 1) ? (qm[m0] != 0)     : true;
        const bool qb = (EPI == 1) ? (qm[m0 + 8] != 0) : true;
#pragma unroll
        for (int nt = 0; nt < 8; nt++) {
            const int n0 = bn + wn * 64 + nt * 8 + lc * 2;
            if (EPI == 0) {
                float2 v01 = make_float2(alpha * d[mt][nt][0], alpha * d[mt][nt][1]);
                float2 v23 = make_float2(alpha * d[mt][nt][2], alpha * d[mt][nt][3]);
                *(float2*)(C + (long)m0 * ldc + n0)       = v01;
                *(float2*)(C + (long)(m0 + 8) * ldc + n0) = v23;
            } else {
                const bool k0m = km[n0] != 0;
                const bool k1m = km[n0 + 1] != 0;
                float2 v01, v23;
                v01.x = (qa && k0m) ? d[mt][nt][0] : -1e20f;
                v01.y = (qa && k1m) ? d[mt][nt][1] : -1e20f;
                v23.x = (qb && k0m) ? d[mt][nt][2] : -1e20f;
                v23.y = (qb && k1m) ? d[mt][nt][3] : -1e20f;
                *(float2*)(C + (long)m0 * ldc + n0)       = v01;
                *(float2*)(C + (long)(m0 + 8) * ldc + n0) = v23;
            }
        }
    }
}

// Entry points --------------------------------------------------------------
__global__ void __launch_bounds__(256, 2) k_gemm(
    const float* __restrict__ A, const float* __restrict__ B, float* __restrict__ C,
    int K, int lda, int ldb, int ldc, float alpha)
{
    gemm_core<true, 0>(A, B, C, K, lda, ldb, ldc, alpha, nullptr, nullptr);
}

__global__ void __launch_bounds__(256, 2) k_scores()
{
    const int z = blockIdx.z, b = z >> 1, h = z & 1;
    gemm_core<true, 1>(g_Q + (long)b * NS * NE + h * NHD,
                       g_Kf + (long)b * NL * NE + h * NHD,
                       g_Sc + (long)z * NS * NL,
                       NHD, NE, NE, NL, 1.0f,
                       g_qm + b * NS, g_km + b * NL);
}

__global__ void __launch_bounds__(256, 2) k_dwv(const float* __restrict__ dw,
                                                float* __restrict__ part)
{
    const int z = blockIdx.z, b = z >> 2, c = z & 3;
    gemm_core<false, 0>(dw + (long)b * NS * NL + c * 1024,
                        g_Vf + ((long)b * NL + c * 1024) * NE,
                        part + (long)z * NS * NE,
                        1024, NL, NE, NE, 1.0f, nullptr, nullptr);
}

// ---------------------------------------------------------------------------
// Dual softmax -> differential weights
// ---------------------------------------------------------------------------
__global__ void __launch_bounds__(256) softmax_dw_kernel(float* __restrict__ dw_out)
{
    __shared__ float s0[NL];
    __shared__ float s1[NL];
    __shared__ float red[256];
    const int row = blockIdx.x;
    const int b = row >> 9;
    const int t = threadIdx.x;
    const float* r0 = g_Sc + ((long)(b * 2 + 0) * NS + (row & (NS - 1))) * NL;
    const float* r1 = g_Sc + ((long)(b * 2 + 1) * NS + (row & (NS - 1))) * NL;

    float m0 = -3.4e38f, m1 = -3.4e38f;
    for (int i = t * 4; i < NL; i += 1024) {
        float4 v0 = *(const float4*)(r0 + i);
        float4 v1 = *(const float4*)(r1 + i);
        *(float4*)&s0[i] = v0; *(float4*)&s1[i] = v1;
        m0 = fmaxf(m0, fmaxf(fmaxf(v0.x, v0.y), fmaxf(v0.z, v0.w)));
        m1 = fmaxf(m1, fmaxf(fmaxf(v1.x, v1.y), fmaxf(v1.z, v1.w)));
    }
    red[t] = m0; __syncthreads();
    for (int s = 128; s > 0; s >>= 1) { if (t < s) red[t] = fmaxf(red[t], red[t + s]); __syncthreads(); }
    m0 = red[0]; __syncthreads();
    red[t] = m1; __syncthreads();
    for (int s = 128; s > 0; s >>= 1) { if (t < s) red[t] = fmaxf(red[t], red[t + s]); __syncthreads(); }
    m1 = red[0]; __syncthreads();

    float sum0 = 0.f, sum1 = 0.f;
    for (int i = t; i < NL; i += 256) {
        float e0 = expf(s0[i] - m0); s0[i] = e0; sum0 += e0;
        float e1 = expf(s1[i] - m1); s1[i] = e1; sum1 += e1;
    }
    red[t] = sum0; __syncthreads();
    for (int s = 128; s > 0; s >>= 1) { if (t < s) red[t] += red[t + s]; __syncthreads(); }
    sum0 = red[0]; __syncthreads();
    red[t] = sum1; __syncthreads();
    for (int s = 128; s > 0; s >>= 1) { if (t < s) red[t] += red[t + s]; __syncthreads(); }
    sum1 = red[0]; __syncthreads();

    const float inv0 = 1.f / (sum0 + 1e-8f);
    const float inv1 = 1.f / (sum1 + 1e-8f);
    const float lam = g_lam;
    float mn = 3.4e38f;
    for (int i = t; i < NL; i += 256) {
        float v = s0[i] * inv0 - lam * (s1[i] * inv1);
        s0[i] = v;
        mn = fminf(mn, v);
    }
    red[t] = mn; __syncthreads();
    for (int s = 128; s > 0; s >>= 1) { if (t < s) red[t] = fminf(red[t], red[t + s]); __syncthreads(); }
    mn = red[0]; __syncthreads();

    const unsigned char qv = g_qm[row];
    const unsigned char* km = g_km + b * NL;
    float* o = dw_out + (long)row * NL;
    for (int i = t; i < NL; i += 256) {
        float v = s0[i] - mn + 1e-5f;
        if (!qv || !km[i]) v = 0.f;
        o[i] = v;
    }
}

// ---------------------------------------------------------------------------
// Sum 4 split-K partials + RMSNorm * rms_w * (1 - LAMBDA_INIT)
// ---------------------------------------------------------------------------
__global__ void __launch_bounds__(256) rmsnorm4_kernel(const float* __restrict__ part,
                                                       float* __restrict__ O,
                                                       const float* __restrict__ w)
{
    __shared__ float red[256];
    __shared__ float buf[NE];
    const int row = blockIdx.x;
    const int b = row >> 9, s = row & (NS - 1);
    const int t = threadIdx.x;
    const long base0 = ((long)(b * 4 + 0) * NS + s) * NE;
    const long base1 = ((long)(b * 4 + 1) * NS + s) * NE;
    const long base2 = ((long)(b * 4 + 2) * NS + s) * NE;
    const long base3 = ((long)(b * 4 + 3) * NS + s) * NE;
    float ss = 0.f;
    for (int i = t; i < NE; i += 256) {
        float v = part[base0 + i] + part[base1 + i] + part[base2 + i] + part[base3 + i];
        buf[i] = v;
        ss += v * v;
    }
    red[t] = ss; __syncthreads();
    for (int st = 128; st > 0; st >>= 1) { if (t < st) red[t] += red[t + st]; __syncthreads(); }
    const float sc = (1.0f / sqrtf(red[0] / (float)NE + 1e-5f)) * 0.8f;
    float* o = O + (long)row * NE;
    for (int i = t; i < NE; i += 256) o[i] = buf[i] * sc * w[i];
}

// ---------------------------------------------------------------------------
// Launch
// ---------------------------------------------------------------------------
extern "C" void kernel_launch(void* const* d_in, const int* in_sizes, int n_in,
                              void* d_out, int out_size)
{
    const float* query = (const float*)d_in[0];
    const float* key   = (const float*)d_in[1];
    const void*  qmask = d_in[2];
    const void*  kmask = d_in[3];
    const float* Wq    = (const float*)d_in[4];
    const float* Wk    = (const float*)d_in[5];
    const float* Wv    = (const float*)d_in[6];
    const float* Wout  = (const float*)d_in[7];
    const float* lq1   = (const float*)d_in[8];
    const float* lk1   = (const float*)d_in[9];
    const float* lq2   = (const float*)d_in[10];
    const float* lk2   = (const float*)d_in[11];
    const float* rms_w = (const float*)d_in[12];

    float* out = (float*)d_out;
    float* dw  = out + (long)NB * NS * NE;

    void* p;
    float *Qp, *Kfp, *Vfp, *Op, *Scp, *WqTp, *WkTp, *WvTp, *WoTp;
    cudaGetSymbolAddress(&p, g_Q);   Qp   = (float*)p;
    cudaGetSymbolAddress(&p, g_Kf);  Kfp  = (float*)p;
    cudaGetSymbolAddress(&p, g_Vf);  Vfp  = (float*)p;
    cudaGetSymbolAddress(&p, g_O);   Op   = (float*)p;
    cudaGetSymbolAddress(&p, g_Sc);  Scp  = (float*)p;
    cudaGetSymbolAddress(&p, g_WqT); WqTp = (float*)p;
    cudaGetSymbolAddress(&p, g_WkT); WkTp = (float*)p;
    cudaGetSymbolAddress(&p, g_WvT); WvTp = (float*)p;
    cudaGetSymbolAddress(&p, g_WoT); WoTp = (float*)p;

    cudaFuncSetAttribute(k_gemm,   cudaFuncAttributeMaxDynamicSharedMemorySize, SMEM_BYTES);
    cudaFuncSetAttribute(k_scores, cudaFuncAttributeMaxDynamicSharedMemorySize, SMEM_BYTES);
    cudaFuncSetAttribute(k_dwv,    cudaFuncAttributeMaxDynamicSharedMemorySize, SMEM_BYTES);

    // 0) weight transposes (projection/Wout GEMMs are NT)
    dim3 tb(32, 8);
    transpose_kernel<<<dim3(24, 24), tb>>>(Wq,   WqTp, NE, NE);
    transpose_kernel<<<dim3(24, 1),  tb>>>(Wk,   WkTp, NGE, NE);
    transpose_kernel<<<dim3(24, 1),  tb>>>(Wv,   WvTp, NGE, NE);
    transpose_kernel<<<dim3(24, 24), tb>>>(Wout, WoTp, NE, NE);

    // 1) masks + lambda
    detect_mode_kernel<<<1, 256>>>((const unsigned int*)kmask, (NB * NL) / 4);
    expand_masks_kernel<<<(NB * NL + 255) / 256, 256>>>(qmask, kmask);
    lam_kernel<<<1, 256>>>(lq1, lk1, lq2, lk2);

    // 2) projections
    const float qscale = 1.0f / sqrtf((float)NHD);
    k_gemm<<<dim3(NE / 128, (NB * NS) / 128), 256, SMEM_BYTES>>>(
        query, WqTp, Qp, NE, NE, NE, NE, qscale);
    k_gemm<<<dim3(NE / 128, (NB * NL) / 128), 256, SMEM_BYTES>>>(
        key, WkTp, Kfp, NGE, NGE, NGE, NE, 1.0f);
    k_gemm<<<dim3(NE / 128, (NB * NL) / 128), 256, SMEM_BYTES>>>(
        key, WvTp, Vfp, NGE, NGE, NGE, NE, 1.0f);

    // 3) masked scores (both heads)
    k_scores<<<dim3(NL / 128, NS / 128, NB * 2), 256, SMEM_BYTES>>>();

    // 4) dual softmax -> differential weights (direct to d_out)
    softmax_dw_kernel<<<NB * NS, 256>>>(dw);

    // 5) o = dw @ V (NN, split-K=4 over L, partials in g_Sc)
    k_dwv<<<dim3(NE / 128, NS / 128, NB * 4), 256, SMEM_BYTES>>>(dw, Scp);

    // 6) reduce + RMSNorm
    rmsnorm4_kernel<<<NB * NS, 256>>>(Scp, Op, rms_w);

    // 7) out = o @ Wout
    k_gemm<<<dim3(NE / 128, (NB * NS) / 128), 256, SMEM_BYTES>>>(
        Op, WoTp, out, NE, NE, NE, NE, 1.0f);
}

// round 9
// speedup vs baseline: 1.2569x; 1.1042x over previous
#include <cuda_runtime.h>
#include <math.h>

#define NB 8
#define NS 512
#define NL 4096
#define NE 768
#define NHD 384
#define NGE 32

// ---------------------------------------------------------------------------
// Static device scratch
// ---------------------------------------------------------------------------
__device__ float g_Qin[NB * NS * NE];      // tf32-rounded query
__device__ float g_Kin[NB * NL * NGE];     // tf32-rounded key
__device__ float g_Q  [NB * NS * NE];      // tf32-rounded Q projection
__device__ float g_Kf [NB * NL * NE];      // tf32-rounded K projection
__device__ float g_Vf [NB * NL * NE];      // tf32-rounded V projection (row-major)
__device__ float g_Sc [NB * 2 * NS * NL];  // scores; reused for split-K partials
__device__ float g_O  [NB * NS * NE];      // tf32-rounded RMSNorm output
__device__ float g_WqT[NE * NE];           // all transposed weights tf32-rounded
__device__ float g_WkT[NE * NGE];
__device__ float g_WvT[NE * NGE];
__device__ float g_WoT[NE * NE];
__device__ unsigned char g_qm[NB * NS];
__device__ unsigned char g_km[NB * NL];
__device__ float g_lam;
__device__ int   g_mode;

// ---------------------------------------------------------------------------
// Common PTX helpers
// ---------------------------------------------------------------------------
__device__ __forceinline__ unsigned cvt_tf32(unsigned x)
{
    unsigned o;
    asm("cvt.rna.tf32.f32 %0, %1;" : "=r"(o) : "f"(__uint_as_float(x)));
    return o;
}
__device__ __forceinline__ float cvt_tf32f(float x)
{
    unsigned o;
    asm("cvt.rna.tf32.f32 %0, %1;" : "=r"(o) : "f"(x));
    return __uint_as_float(o);
}
__device__ __forceinline__ void cpa16(unsigned dst, const void* src)
{
    asm volatile("cp.async.cg.shared.global [%0], [%1], 16;" :: "r"(dst), "l"(src));
}
__device__ __forceinline__ void ldm4(unsigned& r0, unsigned& r1, unsigned& r2, unsigned& r3,
                                     unsigned addr)
{
    asm volatile("ldmatrix.sync.aligned.m8n8.x4.shared.b16 {%0,%1,%2,%3}, [%4];"
                 : "=r"(r0), "=r"(r1), "=r"(r2), "=r"(r3) : "r"(addr));
}
__device__ __forceinline__ void mma8(float* d, const unsigned* a, const unsigned* b)
{
    asm volatile(
        "mma.sync.aligned.m16n8k8.row.col.f32.tf32.tf32.f32 "
        "{%0,%1,%2,%3}, {%4,%5,%6,%7}, {%8,%9}, {%0,%1,%2,%3};"
        : "+f"(d[0]), "+f"(d[1]), "+f"(d[2]), "+f"(d[3])
        : "r"(a[0]), "r"(a[1]), "r"(a[2]), "r"(a[3]), "r"(b[0]), "r"(b[1]));
}

// ---------------------------------------------------------------------------
// Small helper kernels
// ---------------------------------------------------------------------------
__global__ void detect_mode_kernel(const unsigned int* __restrict__ w, int nwords)
{
    __shared__ int bad_i32, bad_f32, any_nz;
    if (threadIdx.x == 0) { bad_i32 = 0; bad_f32 = 0; any_nz = 0; }
    __syncthreads();
    for (int i = threadIdx.x; i < nwords; i += blockDim.x) {
        unsigned int v = w[i];
        if (v != 0u) {
            atomicOr(&any_nz, 1);
            if (v != 1u)           atomicOr(&bad_i32, 1);
            if (v != 0x3F800000u)  atomicOr(&bad_f32, 1);
        }
    }
    __syncthreads();
    if (threadIdx.x == 0) {
        int mode = 0;
        if (any_nz && !bad_i32)      mode = 1;
        else if (any_nz && !bad_f32) mode = 2;
        g_mode = mode;
    }
}

__device__ __forceinline__ unsigned char read_mask(const void* p, int i, int mode)
{
    if (mode == 1) return ((const int*)p)[i] != 0;
    if (mode == 2) return ((const float*)p)[i] != 0.0f;
    return ((const unsigned char*)p)[i] != 0;
}

__global__ void expand_masks_kernel(const void* __restrict__ qmask,
                                    const void* __restrict__ kmask)
{
    int i = blockIdx.x * blockDim.x + threadIdx.x;
    int mode = g_mode;
    if (i < NB * NS) g_qm[i] = read_mask(qmask, i, mode);
    if (i < NB * NL) g_km[i] = read_mask(kmask, i, mode);
}

__global__ void lam_kernel(const float* __restrict__ lq1, const float* __restrict__ lk1,
                           const float* __restrict__ lq2, const float* __restrict__ lk2)
{
    __shared__ float r1[256], r2[256];
    int t = threadIdx.x;
    float a = 0.f, b = 0.f;
    for (int i = t; i < NHD; i += 256) { a += lq1[i] * lk1[i]; b += lq2[i] * lk2[i]; }
    r1[t] = a; r2[t] = b; __syncthreads();
    for (int s = 128; s > 0; s >>= 1) {
        if (t < s) { r1[t] += r1[t + s]; r2[t] += r2[t + s]; }
        __syncthreads();
    }
    if (t == 0) g_lam = expf(r1[0]) - expf(r2[0]) + 0.2f;
}

// elementwise tf32 round (float4)
__global__ void round_copy_kernel(const float* __restrict__ in, float* __restrict__ out,
                                  int n4)
{
    int i = blockIdx.x * blockDim.x + threadIdx.x;
    if (i < n4) {
        float4 v = ((const float4*)in)[i];
        v.x = cvt_tf32f(v.x); v.y = cvt_tf32f(v.y);
        v.z = cvt_tf32f(v.z); v.w = cvt_tf32f(v.w);
        ((float4*)out)[i] = v;
    }
}

// in[rows][cols] -> out[cols][rows], tf32-rounded
__global__ void transpose_kernel(const float* __restrict__ in, float* __restrict__ out,
                                 int rows, int cols)
{
    __shared__ float tile[32][33];
    int c0 = blockIdx.x * 32, r0 = blockIdx.y * 32;
    int x = threadIdx.x, y = threadIdx.y;
    for (int i = 0; i < 32; i += 8) {
        int r = r0 + y + i, c = c0 + x;
        if (r < rows && c < cols) tile[y + i][x] = in[(long)r * cols + c];
    }
    __syncthreads();
    for (int i = 0; i < 32; i += 8) {
        int r = c0 + y + i, c = r0 + x;
        if (r < cols && c < rows) out[(long)r * rows + c] = cvt_tf32f(tile[x][y + i]);
    }
}

// ---------------------------------------------------------------------------
// tf32 GEMM core. 128x128 tiles, BK=32, 256 threads, 3-stage cp.async,
// 2 CTAs/SM. TRANSB=1: C = A[M,K]*B[N,K]^T. TRANSB=0: C = A[M,K]*B[K,N].
// CVTA/CVTB: apply cvt.rna.tf32 to fragments (skip when operand pre-rounded).
// EPI 0: alpha*acc.  EPI 1: scores mask.  EPI 2: tf32-rounded store.
// ---------------------------------------------------------------------------
#define STAGES 3
#define STG_FLOATS 9216
#define B_OFF 4608
#define SMEM_BYTES (STAGES * STG_FLOATS * 4)

template<bool TRANSB, bool CVTA, bool CVTB, int EPI>
__device__ __forceinline__ void gemm_core(
    const float* __restrict__ A, const float* __restrict__ B, float* __restrict__ C,
    int K, int lda, int ldb, int ldc, float alpha,
    const unsigned char* __restrict__ qm, const unsigned char* __restrict__ km)
{
    extern __shared__ float smf[];
    const unsigned smb = (unsigned)__cvta_generic_to_shared(smf);

    const int tid  = threadIdx.x;
    const int lane = tid & 31;
    const int wid  = tid >> 5;
    const int wm   = wid & 3;
    const int wn   = wid >> 2;
    const int lc   = lane & 3;
    const int lr   = lane >> 2;
    const int bm   = blockIdx.y * 128;
    const int bn   = blockIdx.x * 128;

    const int ldrow = tid >> 3;            // 0..31
    const int ldc4  = (tid & 7) << 2;      // 0..28 step 4

    const unsigned a_lane = smb +
        (unsigned)((wm * 32 + ((lane >> 3) & 1) * 8 + (lane & 7)) * 36 + (lane >> 4) * 4) * 4u;
    const unsigned b_lane = smb +
        (unsigned)(B_OFF + (wn * 64 + ((lane >> 4) & 1) * 8 + (lane & 7)) * 36
                   + ((lane >> 3) & 1) * 4) * 4u;

    float d[2][8][4];
#pragma unroll
    for (int mt = 0; mt < 2; mt++)
#pragma unroll
        for (int nt = 0; nt < 8; nt++)
#pragma unroll
            for (int i = 0; i < 4; i++) d[mt][nt][i] = 0.f;

    const int ntile = K >> 5;

#define ISSUE_TILE(T, ST)                                                           \
    do {                                                                            \
        const int k0_ = (T) << 5;                                                   \
        const unsigned sg_ = smb + (unsigned)(ST) * (STG_FLOATS * 4);               \
        const float* Ap_ = A + (long)(bm + ldrow) * lda + (k0_ + ldc4);             \
        const unsigned ad_ = sg_ + (unsigned)(ldrow * 36 + ldc4) * 4u;              \
        _Pragma("unroll")                                                           \
        for (int i_ = 0; i_ < 4; i_++)                                              \
            cpa16(ad_ + i_ * (32 * 36 * 4), Ap_ + (long)i_ * 32 * lda);             \
        if (TRANSB) {                                                               \
            const float* Bp_ = B + (long)(bn + ldrow) * ldb + (k0_ + ldc4);         \
            const unsigned bd_ = sg_ + (unsigned)(B_OFF + ldrow * 36 + ldc4) * 4u;  \
            _Pragma("unroll")                                                       \
            for (int i_ = 0; i_ < 4; i_++)                                          \
                cpa16(bd_ + i_ * (32 * 36 * 4), Bp_ + (long)i_ * 32 * ldb);         \
        } else {                                                                    \
            const float* Bp_ = B + (long)(k0_ + ldrow) * ldb + (bn + ldc4);         \
            const unsigned bd_ = sg_ + (unsigned)(B_OFF + ldrow * 136 + ldc4) * 4u; \
            _Pragma("unroll")                                                       \
            for (int i_ = 0; i_ < 4; i_++)                                          \
                cpa16(bd_ + i_ * 128, Bp_ + i_ * 32);                               \
        }                                                                           \
    } while (0)

#pragma unroll
    for (int s = 0; s < STAGES - 1; s++) {
        if (s < ntile) ISSUE_TILE(s, s);
        asm volatile("cp.async.commit_group;");
    }

    int stq = 0;
    for (int t = 0; t < ntile; t++) {
        asm volatile("cp.async.wait_group %0;" :: "n"(STAGES - 2));
        __syncthreads();
        {
            int tp = t + STAGES - 1;
            if (tp < ntile) {
                int stp = stq + STAGES - 1; if (stp >= STAGES) stp -= STAGES;
                ISSUE_TILE(tp, stp);
            }
        }
        asm volatile("cp.async.commit_group;");

        const unsigned sgb = (unsigned)stq * (STG_FLOATS * 4);
        const unsigned sa = a_lane + sgb;
        const unsigned sb = b_lane + sgb;
        const int bbase = stq * STG_FLOATS + B_OFF;
#pragma unroll
        for (int kk = 0; kk < 4; kk++) {
            unsigned af[2][4];
#pragma unroll
            for (int mt = 0; mt < 2; mt++) {
                unsigned a0, a1, a2, a3;
                ldm4(a0, a1, a2, a3, sa + mt * (16 * 36 * 4) + kk * 32);
                if (CVTA) {
                    af[mt][0] = cvt_tf32(a0); af[mt][1] = cvt_tf32(a1);
                    af[mt][2] = cvt_tf32(a2); af[mt][3] = cvt_tf32(a3);
                } else {
                    af[mt][0] = a0; af[mt][1] = a1; af[mt][2] = a2; af[mt][3] = a3;
                }
            }
            if (TRANSB) {
#pragma unroll
                for (int p = 0; p < 4; p++) {
                    unsigned b0, b1, b2, b3;
                    ldm4(b0, b1, b2, b3, sb + p * (16 * 36 * 4) + kk * 32);
                    unsigned bf0[2], bf1[2];
                    if (CVTB) {
                        bf0[0] = cvt_tf32(b0); bf0[1] = cvt_tf32(b1);
                        bf1[0] = cvt_tf32(b2); bf1[1] = cvt_tf32(b3);
                    } else {
                        bf0[0] = b0; bf0[1] = b1; bf1[0] = b2; bf1[1] = b3;
                    }
                    mma8(d[0][2 * p + 0], af[0], bf0);
                    mma8(d[0][2 * p + 1], af[0], bf1);
                    mma8(d[1][2 * p + 0], af[1], bf0);
                    mma8(d[1][2 * p + 1], af[1], bf1);
                }
            } else {
                const int kb = (kk << 3) + lc;
#pragma unroll
                for (int nt = 0; nt < 8; nt++) {
                    const int n = wn * 64 + nt * 8 + lr;
                    unsigned bf[2];
                    float v0 = smf[bbase + kb * 136 + n];
                    float v1 = smf[bbase + (kb + 4) * 136 + n];
                    if (CVTB) { v0 = cvt_tf32f(v0); v1 = cvt_tf32f(v1); }
                    bf[0] = __float_as_uint(v0);
                    bf[1] = __float_as_uint(v1);
                    mma8(d[0][nt], af[0], bf);
                    mma8(d[1][nt], af[1], bf);
                }
            }
        }
        if (++stq == STAGES) stq = 0;
    }
#undef ISSUE_TILE

    // epilogue
#pragma unroll
    for (int mt = 0; mt < 2; mt++) {
        const int m0 = bm + wm * 32 + mt * 16 + lr;
        const bool qa = (EPI == 1) ? (qm[m0] != 0)     : true;
        const bool qb = (EPI == 1) ? (qm[m0 + 8] != 0) : true;
#pragma unroll
        for (int nt = 0; nt < 8; nt++) {
            const int n0 = bn + wn * 64 + nt * 8 + lc * 2;
            if (EPI == 1) {
                const bool k0m = km[n0] != 0;
                const bool k1m = km[n0 + 1] != 0;
                float2 v01, v23;
                v01.x = (qa && k0m) ? d[mt][nt][0] : -1e20f;
                v01.y = (qa && k1m) ? d[mt][nt][1] : -1e20f;
                v23.x = (qb && k0m) ? d[mt][nt][2] : -1e20f;
                v23.y = (qb && k1m) ? d[mt][nt][3] : -1e20f;
                *(float2*)(C + (long)m0 * ldc + n0)       = v01;
                *(float2*)(C + (long)(m0 + 8) * ldc + n0) = v23;
            } else if (EPI == 2) {
                float2 v01 = make_float2(cvt_tf32f(alpha * d[mt][nt][0]),
                                         cvt_tf32f(alpha * d[mt][nt][1]));
                float2 v23 = make_float2(cvt_tf32f(alpha * d[mt][nt][2]),
                                         cvt_tf32f(alpha * d[mt][nt][3]));
                *(float2*)(C + (long)m0 * ldc + n0)       = v01;
                *(float2*)(C + (long)(m0 + 8) * ldc + n0) = v23;
            } else {
                float2 v01 = make_float2(alpha * d[mt][nt][0], alpha * d[mt][nt][1]);
                float2 v23 = make_float2(alpha * d[mt][nt][2], alpha * d[mt][nt][3]);
                *(float2*)(C + (long)m0 * ldc + n0)       = v01;
                *(float2*)(C + (long)(m0 + 8) * ldc + n0) = v23;
            }
        }
    }
}

// Entry points --------------------------------------------------------------
// projections: pre-rounded inputs, rounded output
__global__ void __launch_bounds__(256, 2) k_proj(
    const float* __restrict__ A, const float* __restrict__ B, float* __restrict__ C,
    int K, int lda, int ldb, int ldc, float alpha)
{
    gemm_core<true, false, false, 2>(A, B, C, K, lda, ldb, ldc, alpha, nullptr, nullptr);
}

// Wout: pre-rounded operands, exact fp32 output
__global__ void __launch_bounds__(256, 2) k_wout(
    const float* __restrict__ A, const float* __restrict__ B, float* __restrict__ C,
    int K, int lda, int ldb, int ldc, float alpha)
{
    gemm_core<true, false, false, 0>(A, B, C, K, lda, ldb, ldc, alpha, nullptr, nullptr);
}

__global__ void __launch_bounds__(256, 2) k_scores()
{
    const int z = blockIdx.z, b = z >> 1, h = z & 1;
    gemm_core<true, false, false, 1>(
        g_Q + (long)b * NS * NE + h * NHD,
        g_Kf + (long)b * NL * NE + h * NHD,
        g_Sc + (long)z * NS * NL,
        NHD, NE, NE, NL, 1.0f,
        g_qm + b * NS, g_km + b * NL);
}

__global__ void __launch_bounds__(256, 2) k_dwv(const float* __restrict__ dw,
                                                float* __restrict__ part)
{
    const int z = blockIdx.z, b = z >> 2, c = z & 3;
    gemm_core<false, true, false, 0>(
        dw + (long)b * NS * NL + c * 1024,
        g_Vf + ((long)b * NL + c * 1024) * NE,
        part + (long)z * NS * NE,
        1024, NL, NE, NE, 1.0f, nullptr, nullptr);
}

// ---------------------------------------------------------------------------
// Dual softmax -> differential weights (dw exact fp32)
// ---------------------------------------------------------------------------
__global__ void __launch_bounds__(256) softmax_dw_kernel(float* __restrict__ dw_out)
{
    __shared__ float s0[NL];
    __shared__ float s1[NL];
    __shared__ float red[256];
    const int row = blockIdx.x;
    const int b = row >> 9;
    const int t = threadIdx.x;
    const float* r0 = g_Sc + ((long)(b * 2 + 0) * NS + (row & (NS - 1))) * NL;
    const float* r1 = g_Sc + ((long)(b * 2 + 1) * NS + (row & (NS - 1))) * NL;

    float m0 = -3.4e38f, m1 = -3.4e38f;
    for (int i = t * 4; i < NL; i += 1024) {
        float4 v0 = *(const float4*)(r0 + i);
        float4 v1 = *(const float4*)(r1 + i);
        *(float4*)&s0[i] = v0; *(float4*)&s1[i] = v1;
        m0 = fmaxf(m0, fmaxf(fmaxf(v0.x, v0.y), fmaxf(v0.z, v0.w)));
        m1 = fmaxf(m1, fmaxf(fmaxf(v1.x, v1.y), fmaxf(v1.z, v1.w)));
    }
    red[t] = m0; __syncthreads();
    for (int s = 128; s > 0; s >>= 1) { if (t < s) red[t] = fmaxf(red[t], red[t + s]); __syncthreads(); }
    m0 = red[0]; __syncthreads();
    red[t] = m1; __syncthreads();
    for (int s = 128; s > 0; s >>= 1) { if (t < s) red[t] = fmaxf(red[t], red[t + s]); __syncthreads(); }
    m1 = red[0]; __syncthreads();

    float sum0 = 0.f, sum1 = 0.f;
    for (int i = t; i < NL; i += 256) {
        float e0 = expf(s0[i] - m0); s0[i] = e0; sum0 += e0;
        float e1 = expf(s1[i] - m1); s1[i] = e1; sum1 += e1;
    }
    red[t] = sum0; __syncthreads();
    for (int s = 128; s > 0; s >>= 1) { if (t < s) red[t] += red[t + s]; __syncthreads(); }
    sum0 = red[0]; __syncthreads();
    red[t] = sum1; __syncthreads();
    for (int s = 128; s > 0; s >>= 1) { if (t < s) red[t] += red[t + s]; __syncthreads(); }
    sum1 = red[0]; __syncthreads();

    const float inv0 = 1.f / (sum0 + 1e-8f);
    const float inv1 = 1.f / (sum1 + 1e-8f);
    const float lam = g_lam;
    float mn = 3.4e38f;
    for (int i = t; i < NL; i += 256) {
        float v = s0[i] * inv0 - lam * (s1[i] * inv1);
        s0[i] = v;
        mn = fminf(mn, v);
    }
    red[t] = mn; __syncthreads();
    for (int s = 128; s > 0; s >>= 1) { if (t < s) red[t] = fminf(red[t], red[t + s]); __syncthreads(); }
    mn = red[0]; __syncthreads();

    const unsigned char qv = g_qm[row];
    const unsigned char* km = g_km + b * NL;
    float* o = dw_out + (long)row * NL;
    for (int i = t; i < NL; i += 256) {
        float v = s0[i] - mn + 1e-5f;
        if (!qv || !km[i]) v = 0.f;
        o[i] = v;
    }
}

// ---------------------------------------------------------------------------
// Sum 4 split-K partials + RMSNorm * rms_w * (1 - LAMBDA_INIT), tf32-rounded
// ---------------------------------------------------------------------------
__global__ void __launch_bounds__(256) rmsnorm4_kernel(const float* __restrict__ part,
                                                       float* __restrict__ O,
                                                       const float* __restrict__ w)
{
    __shared__ float red[256];
    __shared__ float buf[NE];
    const int row = blockIdx.x;
    const int b = row >> 9, s = row & (NS - 1);
    const int t = threadIdx.x;
    const long base0 = ((long)(b * 4 + 0) * NS + s) * NE;
    const long base1 = ((long)(b * 4 + 1) * NS + s) * NE;
    const long base2 = ((long)(b * 4 + 2) * NS + s) * NE;
    const long base3 = ((long)(b * 4 + 3) * NS + s) * NE;
    float ss = 0.f;
    for (int i = t; i < NE; i += 256) {
        float v = part[base0 + i] + part[base1 + i] + part[base2 + i] + part[base3 + i];
        buf[i] = v;
        ss += v * v;
    }
    red[t] = ss; __syncthreads();
    for (int st = 128; st > 0; st >>= 1) { if (t < st) red[t] += red[t + st]; __syncthreads(); }
    const float sc = (1.0f / sqrtf(red[0] / (float)NE + 1e-5f)) * 0.8f;
    float* o = O + (long)row * NE;
    for (int i = t; i < NE; i += 256) o[i] = cvt_tf32f(buf[i] * sc * w[i]);
}

// ---------------------------------------------------------------------------
// Launch
// ---------------------------------------------------------------------------
extern "C" void kernel_launch(void* const* d_in, const int* in_sizes, int n_in,
                              void* d_out, int out_size)
{
    const float* query = (const float*)d_in[0];
    const float* key   = (const float*)d_in[1];
    const void*  qmask = d_in[2];
    const void*  kmask = d_in[3];
    const float* Wq    = (const float*)d_in[4];
    const float* Wk    = (const float*)d_in[5];
    const float* Wv    = (const float*)d_in[6];
    const float* Wout  = (const float*)d_in[7];
    const float* lq1   = (const float*)d_in[8];
    const float* lk1   = (const float*)d_in[9];
    const float* lq2   = (const float*)d_in[10];
    const float* lk2   = (const float*)d_in[11];
    const float* rms_w = (const float*)d_in[12];

    float* out = (float*)d_out;
    float* dw  = out + (long)NB * NS * NE;

    void* p;
    float *Qinp, *Kinp, *Qp, *Kfp, *Vfp, *Op, *Scp, *WqTp, *WkTp, *WvTp, *WoTp;
    cudaGetSymbolAddress(&p, g_Qin); Qinp = (float*)p;
    cudaGetSymbolAddress(&p, g_Kin); Kinp = (float*)p;
    cudaGetSymbolAddress(&p, g_Q);   Qp   = (float*)p;
    cudaGetSymbolAddress(&p, g_Kf);  Kfp  = (float*)p;
    cudaGetSymbolAddress(&p, g_Vf);  Vfp  = (float*)p;
    cudaGetSymbolAddress(&p, g_O);   Op   = (float*)p;
    cudaGetSymbolAddress(&p, g_Sc);  Scp  = (float*)p;
    cudaGetSymbolAddress(&p, g_WqT); WqTp = (float*)p;
    cudaGetSymbolAddress(&p, g_WkT); WkTp = (float*)p;
    cudaGetSymbolAddress(&p, g_WvT); WvTp = (float*)p;
    cudaGetSymbolAddress(&p, g_WoT); WoTp = (float*)p;

    cudaFuncSetAttribute(k_proj,   cudaFuncAttributeMaxDynamicSharedMemorySize, SMEM_BYTES);
    cudaFuncSetAttribute(k_wout,   cudaFuncAttributeMaxDynamicSharedMemorySize, SMEM_BYTES);
    cudaFuncSetAttribute(k_scores, cudaFuncAttributeMaxDynamicSharedMemorySize, SMEM_BYTES);
    cudaFuncSetAttribute(k_dwv,    cudaFuncAttributeMaxDynamicSharedMemorySize, SMEM_BYTES);

    // 0) tf32-round inputs + weight transposes (rounded at write)
    round_copy_kernel<<<(NB * NS * NE / 4 + 255) / 256, 256>>>(query, Qinp, NB * NS * NE / 4);
    round_copy_kernel<<<(NB * NL * NGE / 4 + 255) / 256, 256>>>(key, Kinp, NB * NL * NGE / 4);
    dim3 tb(32, 8);
    transpose_kernel<<<dim3(24, 24), tb>>>(Wq,   WqTp, NE, NE);
    transpose_kernel<<<dim3(24, 1),  tb>>>(Wk,   WkTp, NGE, NE);
    transpose_kernel<<<dim3(24, 1),  tb>>>(Wv,   WvTp, NGE, NE);
    transpose_kernel<<<dim3(24, 24), tb>>>(Wout, WoTp, NE, NE);

    // 1) masks + lambda
    detect_mode_kernel<<<1, 256>>>((const unsigned int*)kmask, (NB * NL) / 4);
    expand_masks_kernel<<<(NB * NL + 255) / 256, 256>>>(qmask, kmask);
    lam_kernel<<<1, 256>>>(lq1, lk1, lq2, lk2);

    // 2) projections (cvt-free inner loops; rounded outputs)
    const float qscale = 1.0f / sqrtf((float)NHD);
    k_proj<<<dim3(NE / 128, (NB * NS) / 128), 256, SMEM_BYTES>>>(
        Qinp, WqTp, Qp, NE, NE, NE, NE, qscale);
    k_proj<<<dim3(NE / 128, (NB * NL) / 128), 256, SMEM_BYTES>>>(
        Kinp, WkTp, Kfp, NGE, NGE, NGE, NE, 1.0f);
    k_proj<<<dim3(NE / 128, (NB * NL) / 128), 256, SMEM_BYTES>>>(
        Kinp, WvTp, Vfp, NGE, NGE, NGE, NE, 1.0f);

    // 3) masked scores (cvt-free)
    k_scores<<<dim3(NL / 128, NS / 128, NB * 2), 256, SMEM_BYTES>>>();

    // 4) dual softmax -> differential weights (exact fp32, direct to d_out)
    softmax_dw_kernel<<<NB * NS, 256>>>(dw);

    // 5) o = dw @ V (NN; cvt on A only; split-K=4 over L, partials in g_Sc)
    k_dwv<<<dim3(NE / 128, NS / 128, NB * 4), 256, SMEM_BYTES>>>(dw, Scp);

    // 6) reduce + RMSNorm (rounded output)
    rmsnorm4_kernel<<<NB * NS, 256>>>(Scp, Op, rms_w);

    // 7) out = o @ Wout (cvt-free)
    k_wout<<<dim3(NE / 128, (NB * NS) / 128), 256, SMEM_BYTES>>>(
        Op, WoTp, out, NE, NE, NE, NE, 1.0f);
}

// round 11
// speedup vs baseline: 1.7028x; 1.3548x over previous
#include <cuda_runtime.h>
#include <cuda_fp16.h>
#include <math.h>

#define NB 8
#define NS 512
#define NL 4096
#define NE 768
#define NHD 384
#define NGE 32

// ---------------------------------------------------------------------------
// Static device scratch (fp16 staging for all GEMM operands)
// ---------------------------------------------------------------------------
__device__ __half g_Qin[NB * NS * NE];
__device__ __half g_Kin[NB * NL * NGE];
__device__ __half g_Qh [NB * NS * NE];
__device__ __half g_Kh [NB * NL * NE];
__device__ __half g_Vth[NB * NE * NL];     // V transposed [b][e][l]
__device__ __half g_dwh[NB * NS * NL];     // fp16 copy of dw
__device__ __half g_Oh [NB * NS * NE];
__device__ __half g_WqT[NE * NE];
__device__ __half g_WkT[NE * NGE];
__device__ __half g_WvT[NE * NGE];
__device__ __half g_WoT[NE * NE];
__device__ float  g_Sc [NB * 2 * NS * NL]; // fp32 scores; reused for split-K partials
__device__ unsigned char g_qm[NB * NS];
__device__ unsigned char g_km[NB * NL];
__device__ float g_lam;
__device__ int   g_mode;

// ---------------------------------------------------------------------------
// PTX helpers
// ---------------------------------------------------------------------------
__device__ __forceinline__ void cpa16(unsigned dst, const void* src)
{
    asm volatile("cp.async.cg.shared.global [%0], [%1], 16;" :: "r"(dst), "l"(src));
}
__device__ __forceinline__ void ldm4(unsigned& r0, unsigned& r1, unsigned& r2, unsigned& r3,
                                     unsigned addr)
{
    asm volatile("ldmatrix.sync.aligned.m8n8.x4.shared.b16 {%0,%1,%2,%3}, [%4];"
                 : "=r"(r0), "=r"(r1), "=r"(r2), "=r"(r3) : "r"(addr));
}
__device__ __forceinline__ void mma16(float* d, const unsigned* a, const unsigned* b)
{
    asm volatile(
        "mma.sync.aligned.m16n8k16.row.col.f32.f16.f16.f32 "
        "{%0,%1,%2,%3}, {%4,%5,%6,%7}, {%8,%9}, {%0,%1,%2,%3};"
        : "+f"(d[0]), "+f"(d[1]), "+f"(d[2]), "+f"(d[3])
        : "r"(a[0]), "r"(a[1]), "r"(a[2]), "r"(a[3]), "r"(b[0]), "r"(b[1]));
}

// ---------------------------------------------------------------------------
// Small helper kernels
// ---------------------------------------------------------------------------
__global__ void detect_mode_kernel(const unsigned int* __restrict__ w, int nwords)
{
    __shared__ int bad_i32, bad_f32, any_nz;
    if (threadIdx.x == 0) { bad_i32 = 0; bad_f32 = 0; any_nz = 0; }
    __syncthreads();
    for (int i = threadIdx.x; i < nwords; i += blockDim.x) {
        unsigned int v = w[i];
        if (v != 0u) {
            atomicOr(&any_nz, 1);
            if (v != 1u)           atomicOr(&bad_i32, 1);
            if (v != 0x3F800000u)  atomicOr(&bad_f32, 1);
        }
    }
    __syncthreads();
    if (threadIdx.x == 0) {
        int mode = 0;
        if (any_nz && !bad_i32)      mode = 1;
        else if (any_nz && !bad_f32) mode = 2;
        g_mode = mode;
    }
}

__device__ __forceinline__ unsigned char read_mask(const void* p, int i, int mode)
{
    if (mode == 1) return ((const int*)p)[i] != 0;
    if (mode == 2) return ((const float*)p)[i] != 0.0f;
    return ((const unsigned char*)p)[i] != 0;
}

__global__ void expand_masks_kernel(const void* __restrict__ qmask,
                                    const void* __restrict__ kmask)
{
    int i = blockIdx.x * blockDim.x + threadIdx.x;
    int mode = g_mode;
    if (i < NB * NS) g_qm[i] = read_mask(qmask, i, mode);
    if (i < NB * NL) g_km[i] = read_mask(kmask, i, mode);
}

__global__ void lam_kernel(const float* __restrict__ lq1, const float* __restrict__ lk1,
                           const float* __restrict__ lq2, const float* __restrict__ lk2)
{
    __shared__ float r1[256], r2[256];
    int t = threadIdx.x;
    float a = 0.f, b = 0.f;
    for (int i = t; i < NHD; i += 256) { a += lq1[i] * lk1[i]; b += lq2[i] * lk2[i]; }
    r1[t] = a; r2[t] = b; __syncthreads();
    for (int s = 128; s > 0; s >>= 1) {
        if (t < s) { r1[t] += r1[t + s]; r2[t] += r2[t + s]; }
        __syncthreads();
    }
    if (t == 0) g_lam = expf(r1[0]) - expf(r2[0]) + 0.2f;
}

// fp32 -> fp16 elementwise
__global__ void f2h_kernel(const float* __restrict__ in, __half* __restrict__ out, int n4)
{
    int i = blockIdx.x * blockDim.x + threadIdx.x;
    if (i < n4) {
        float4 v = ((const float4*)in)[i];
        __half2 h0 = __floats2half2_rn(v.x, v.y);
        __half2 h1 = __floats2half2_rn(v.z, v.w);
        ((__half2*)out)[2 * i]     = h0;
        ((__half2*)out)[2 * i + 1] = h1;
    }
}

// in[rows][cols] fp32 -> out[cols][rows] fp16
__global__ void transpose_h_kernel(const float* __restrict__ in, __half* __restrict__ out,
                                   int rows, int cols)
{
    __shared__ float tile[32][33];
    int c0 = blockIdx.x * 32, r0 = blockIdx.y * 32;
    int x = threadIdx.x, y = threadIdx.y;
    for (int i = 0; i < 32; i += 8) {
        int r = r0 + y + i, c = c0 + x;
        if (r < rows && c < cols) tile[y + i][x] = in[(long)r * cols + c];
    }
    __syncthreads();
    for (int i = 0; i < 32; i += 8) {
        int r = c0 + y + i, c = r0 + x;
        if (r < cols && c < rows) out[(long)r * rows + c] = __float2half_rn(tile[x][y + i]);
    }
}

// ---------------------------------------------------------------------------
// fp16 NT GEMM core: C[M,N] = alpha * A[M,K] * B[N,K]^T, fp32 accumulate.
// 128x128 block tiles, BK=32, 256 threads (8 warps, 32x64 warp tiles),
// 3-stage cp.async, 2 CTAs/SM.
// EPI 0: fp32 store.  EPI 1: scores mask (fp32).  EPI 2: fp16 store.
// smem row pitch = 40 halves (80 B) -> conflict-free ldmatrix.
// ---------------------------------------------------------------------------
#define STAGES 3
#define PITCH_B 80                       // bytes per 32-half row
#define OP_BYTES (128 * PITCH_B)         // 10240 per operand tile
#define STG_BYTES (2 * OP_BYTES)         // 20480 per stage
#define SMEM_BYTES (STAGES * STG_BYTES)  // 61440

template<int EPI>
__device__ __forceinline__ void gemm_h(
    const __half* __restrict__ A, const __half* __restrict__ B, void* __restrict__ Cv,
    int K, int lda, int ldb, int ldc, float alpha,
    const unsigned char* __restrict__ qm, const unsigned char* __restrict__ km)
{
    extern __shared__ char smc[];
    const unsigned smb = (unsigned)__cvta_generic_to_shared(smc);

    const int tid  = threadIdx.x;
    const int lane = tid & 31;
    const int wid  = tid >> 5;
    const int wm   = wid & 3;
    const int wn   = wid >> 2;
    const int lc   = lane & 3;
    const int lr   = lane >> 2;
    const int bm   = blockIdx.y * 128;
    const int bn   = blockIdx.x * 128;

    const int ldrow = tid >> 2;            // 0..63 (+64 per i)
    const int ldch  = tid & 3;             // 16B chunk within 64B row

    const unsigned a_lane = smb + (unsigned)((wm * 32 + (lane & 15)) * PITCH_B
                                             + (lane >> 4) * 16);
    const unsigned b_lane = smb + (unsigned)(OP_BYTES + (wn * 64 + (lane & 15)) * PITCH_B
                                             + (lane >> 4) * 16);

    float d[2][8][4];
#pragma unroll
    for (int mt = 0; mt < 2; mt++)
#pragma unroll
        for (int nt = 0; nt < 8; nt++)
#pragma unroll
            for (int i = 0; i < 4; i++) d[mt][nt][i] = 0.f;

    const int ntile = K >> 5;

#define ISSUE_TILE(T, ST)                                                          \
    do {                                                                           \
        const int k0_ = (T) << 5;                                                  \
        const unsigned sg_ = smb + (unsigned)(ST) * STG_BYTES;                     \
        _Pragma("unroll")                                                          \
        for (int i_ = 0; i_ < 2; i_++) {                                           \
            int row_ = ldrow + i_ * 64;                                            \
            unsigned off_ = (unsigned)(row_ * PITCH_B + ldch * 16);                \
            cpa16(sg_ + off_, A + (long)(bm + row_) * lda + k0_ + ldch * 8);       \
            cpa16(sg_ + OP_BYTES + off_,                                           \
                  B + (long)(bn + row_) * ldb + k0_ + ldch * 8);                   \
        }                                                                          \
    } while (0)

#pragma unroll
    for (int s = 0; s < STAGES - 1; s++) {
        if (s < ntile) ISSUE_TILE(s, s);
        asm volatile("cp.async.commit_group;");
    }

    int stq = 0;
    for (int t = 0; t < ntile; t++) {
        asm volatile("cp.async.wait_group %0;" :: "n"(STAGES - 2));
        __syncthreads();
        {
            int tp = t + STAGES - 1;
            if (tp < ntile) {
                int stp = stq + STAGES - 1; if (stp >= STAGES) stp -= STAGES;
                ISSUE_TILE(tp, stp);
            }
        }
        asm volatile("cp.async.commit_group;");

        const unsigned sgb = (unsigned)stq * STG_BYTES;
        const unsigned sa = a_lane + sgb;
        const unsigned sb = b_lane + sgb;
#pragma unroll
        for (int kk = 0; kk < 2; kk++) {           // two k16 steps per BK=32
            unsigned af[2][4];
#pragma unroll
            for (int mt = 0; mt < 2; mt++)
                ldm4(af[mt][0], af[mt][1], af[mt][2], af[mt][3],
                     sa + mt * (16 * PITCH_B) + kk * 32);
#pragma unroll
            for (int nb = 0; nb < 4; nb++) {
                unsigned b0, b1, b2, b3;
                ldm4(b0, b1, b2, b3, sb + nb * (16 * PITCH_B) + kk * 32);
                unsigned bf0[2] = { b0, b2 };      // n(nb*16 + 0..7)
                unsigned bf1[2] = { b1, b3 };      // n(nb*16 + 8..15)
                mma16(d[0][2 * nb + 0], af[0], bf0);
                mma16(d[0][2 * nb + 1], af[0], bf1);
                mma16(d[1][2 * nb + 0], af[1], bf0);
                mma16(d[1][2 * nb + 1], af[1], bf1);
            }
        }
        if (++stq == STAGES) stq = 0;
    }
#undef ISSUE_TILE

    // epilogue
#pragma unroll
    for (int mt = 0; mt < 2; mt++) {
        const int m0 = bm + wm * 32 + mt * 16 + lr;
        const bool qa = (EPI == 1) ? (qm[m0] != 0)     : true;
        const bool qb = (EPI == 1) ? (qm[m0 + 8] != 0) : true;
#pragma unroll
        for (int nt = 0; nt < 8; nt++) {
            const int n0 = bn + wn * 64 + nt * 8 + lc * 2;
            if (EPI == 2) {
                __half* Ch = (__half*)Cv;
                *(__half2*)(Ch + (long)m0 * ldc + n0) =
                    __floats2half2_rn(alpha * d[mt][nt][0], alpha * d[mt][nt][1]);
                *(__half2*)(Ch + (long)(m0 + 8) * ldc + n0) =
                    __floats2half2_rn(alpha * d[mt][nt][2], alpha * d[mt][nt][3]);
            } else if (EPI == 1) {
                float* C = (float*)Cv;
                const bool k0m = km[n0] != 0;
                const bool k1m = km[n0 + 1] != 0;
                float2 v01, v23;
                v01.x = (qa && k0m) ? d[mt][nt][0] : -1e20f;
                v01.y = (qa && k1m) ? d[mt][nt][1] : -1e20f;
                v23.x = (qb && k0m) ? d[mt][nt][2] : -1e20f;
                v23.y = (qb && k1m) ? d[mt][nt][3] : -1e20f;
                *(float2*)(C + (long)m0 * ldc + n0)       = v01;
                *(float2*)(C + (long)(m0 + 8) * ldc + n0) = v23;
            } else {
                float* C = (float*)Cv;
                float2 v01 = make_float2(alpha * d[mt][nt][0], alpha * d[mt][nt][1]);
                float2 v23 = make_float2(alpha * d[mt][nt][2], alpha * d[mt][nt][3]);
                *(float2*)(C + (long)m0 * ldc + n0)       = v01;
                *(float2*)(C + (long)(m0 + 8) * ldc + n0) = v23;
            }
        }
    }
}

// Entry points --------------------------------------------------------------
__global__ void __launch_bounds__(256, 2) k_proj_h(
    const __half* __restrict__ A, const __half* __restrict__ B, __half* __restrict__ C,
    int K, int lda, int ldb, int ldc, long sA, long sB, long sC, float alpha)
{
    gemm_h<2>(A + (long)blockIdx.z * sA, B + (long)blockIdx.z * sB,
              C + (long)blockIdx.z * sC, K, lda, ldb, ldc, alpha, nullptr, nullptr);
}

__global__ void __launch_bounds__(256, 2) k_scores_h()
{
    const int z = blockIdx.z, b = z >> 1, h = z & 1;
    gemm_h<1>(g_Qh + (long)b * NS * NE + h * NHD,
              g_Kh + (long)b * NL * NE + h * NHD,
              g_Sc + (long)z * NS * NL,
              NHD, NE, NE, NL, 1.0f,
              g_qm + b * NS, g_km + b * NL);
}

__global__ void __launch_bounds__(256, 2) k_dwv_h(float* __restrict__ part)
{
    const int z = blockIdx.z, b = z >> 2, c = z & 3;
    gemm_h<0>(g_dwh + (long)b * NS * NL + c * 1024,
              g_Vth + (long)b * NE * NL + c * 1024,
              part + (long)z * NS * NE,
              1024, NL, NL, NE, 1.0f, nullptr, nullptr);
}

__global__ void __launch_bounds__(256, 2) k_wout_h(float* __restrict__ out)
{
    gemm_h<0>(g_Oh, g_WoT, out, NE, NE, NE, NE, 1.0f, nullptr, nullptr);
}

// ---------------------------------------------------------------------------
// Dual softmax -> differential weights (fp32 to d_out + fp16 scratch copy)
// ---------------------------------------------------------------------------
__global__ void __launch_bounds__(256) softmax_dw_kernel(float* __restrict__ dw_out)
{
    __shared__ float s0[NL];
    __shared__ float s1[NL];
    __shared__ float red[256];
    const int row = blockIdx.x;
    const int b = row >> 9;
    const int t = threadIdx.x;
    const float* r0 = g_Sc + ((long)(b * 2 + 0) * NS + (row & (NS - 1))) * NL;
    const float* r1 = g_Sc + ((long)(b * 2 + 1) * NS + (row & (NS - 1))) * NL;

    float m0 = -3.4e38f, m1 = -3.4e38f;
    for (int i = t * 4; i < NL; i += 1024) {
        float4 v0 = *(const float4*)(r0 + i);
        float4 v1 = *(const float4*)(r1 + i);
        *(float4*)&s0[i] = v0; *(float4*)&s1[i] = v1;
        m0 = fmaxf(m0, fmaxf(fmaxf(v0.x, v0.y), fmaxf(v0.z, v0.w)));
        m1 = fmaxf(m1, fmaxf(fmaxf(v1.x, v1.y), fmaxf(v1.z, v1.w)));
    }
    red[t] = m0; __syncthreads();
    for (int s = 128; s > 0; s >>= 1) { if (t < s) red[t] = fmaxf(red[t], red[t + s]); __syncthreads(); }
    m0 = red[0]; __syncthreads();
    red[t] = m1; __syncthreads();
    for (int s = 128; s > 0; s >>= 1) { if (t < s) red[t] = fmaxf(red[t], red[t + s]); __syncthreads(); }
    m1 = red[0]; __syncthreads();

    float sum0 = 0.f, sum1 = 0.f;
    for (int i = t; i < NL; i += 256) {
        float e0 = expf(s0[i] - m0); s0[i] = e0; sum0 += e0;
        float e1 = expf(s1[i] - m1); s1[i] = e1; sum1 += e1;
    }
    red[t] = sum0; __syncthreads();
    for (int s = 128; s > 0; s >>= 1) { if (t < s) red[t] += red[t + s]; __syncthreads(); }
    sum0 = red[0]; __syncthreads();
    red[t] = sum1; __syncthreads();
    for (int s = 128; s > 0; s >>= 1) { if (t < s) red[t] += red[t + s]; __syncthreads(); }
    sum1 = red[0]; __syncthreads();

    const float inv0 = 1.f / (sum0 + 1e-8f);
    const float inv1 = 1.f / (sum1 + 1e-8f);
    const float lam = g_lam;
    float mn = 3.4e38f;
    for (int i = t; i < NL; i += 256) {
        float v = s0[i] * inv0 - lam * (s1[i] * inv1);
        s0[i] = v;
        mn = fminf(mn, v);
    }
    red[t] = mn; __syncthreads();
    for (int s = 128; s > 0; s >>= 1) { if (t < s) red[t] = fminf(red[t], red[t + s]); __syncthreads(); }
    mn = red[0]; __syncthreads();

    const unsigned char qv = g_qm[row];
    const unsigned char* km = g_km + b * NL;
    float*  o  = dw_out + (long)row * NL;
    __half* oh = g_dwh  + (long)row * NL;
    for (int i = t; i < NL; i += 256) {
        float v = s0[i] - mn + 1e-5f;
        if (!qv || !km[i]) v = 0.f;
        o[i]  = v;
        oh[i] = __float2half_rn(v);
    }
}

// ---------------------------------------------------------------------------
// Sum 4 split-K partials + RMSNorm * rms_w * (1 - LAMBDA_INIT) -> fp16 O
// ---------------------------------------------------------------------------
__global__ void __launch_bounds__(256) rmsnorm4_kernel(const float* __restrict__ part,
                                                       __half* __restrict__ O,
                                                       const float* __restrict__ w)
{
    __shared__ float red[256];
    __shared__ float buf[NE];
    const int row = blockIdx.x;
    const int b = row >> 9, s = row & (NS - 1);
    const int t = threadIdx.x;
    const long base0 = ((long)(b * 4 + 0) * NS + s) * NE;
    const long base1 = ((long)(b * 4 + 1) * NS + s) * NE;
    const long base2 = ((long)(b * 4 + 2) * NS + s) * NE;
    const long base3 = ((long)(b * 4 + 3) * NS + s) * NE;
    float ss = 0.f;
    for (int i = t; i < NE; i += 256) {
        float v = part[base0 + i] + part[base1 + i] + part[base2 + i] + part[base3 + i];
        buf[i] = v;
        ss += v * v;
    }
    red[t] = ss; __syncthreads();
    for (int st = 128; st > 0; st >>= 1) { if (t < st) red[t] += red[t + st]; __syncthreads(); }
    const float sc = (1.0f / sqrtf(red[0] / (float)NE + 1e-5f)) * 0.8f;
    __half* o = O + (long)row * NE;
    for (int i = t; i < NE; i += 256) o[i] = __float2half_rn(buf[i] * sc * w[i]);
}

// ---------------------------------------------------------------------------
// Launch
// ---------------------------------------------------------------------------
extern "C" void kernel_launch(void* const* d_in, const int* in_sizes, int n_in,
                              void* d_out, int out_size)
{
    const float* query = (const float*)d_in[0];
    const float* key   = (const float*)d_in[1];
    const void*  qmask = d_in[2];
    const void*  kmask = d_in[3];
    const float* Wq    = (const float*)d_in[4];
    const float* Wk    = (const float*)d_in[5];
    const float* Wv    = (const float*)d_in[6];
    const float* Wout  = (const float*)d_in[7];
    const float* lq1   = (const float*)d_in[8];
    const float* lk1   = (const float*)d_in[9];
    const float* lq2   = (const float*)d_in[10];
    const float* lk2   = (const float*)d_in[11];
    const float* rms_w = (const float*)d_in[12];

    float* out = (float*)d_out;
    float* dw  = out + (long)NB * NS * NE;

    void* p;
    __half *Qinp, *Kinp, *Qhp, *Khp, *Vthp, *Ohp, *WqTp, *WkTp, *WvTp, *WoTp;
    float *Scp;
    cudaGetSymbolAddress(&p, g_Qin); Qinp = (__half*)p;
    cudaGetSymbolAddress(&p, g_Kin); Kinp = (__half*)p;
    cudaGetSymbolAddress(&p, g_Qh);  Qhp  = (__half*)p;
    cudaGetSymbolAddress(&p, g_Kh);  Khp  = (__half*)p;
    cudaGetSymbolAddress(&p, g_Vth); Vthp = (__half*)p;
    cudaGetSymbolAddress(&p, g_Oh);  Ohp  = (__half*)p;
    cudaGetSymbolAddress(&p, g_WqT); WqTp = (__half*)p;
    cudaGetSymbolAddress(&p, g_WkT); WkTp = (__half*)p;
    cudaGetSymbolAddress(&p, g_WvT); WvTp = (__half*)p;
    cudaGetSymbolAddress(&p, g_WoT); WoTp = (__half*)p;
    cudaGetSymbolAddress(&p, g_Sc);  Scp  = (float*)p;

    cudaFuncSetAttribute(k_proj_h,   cudaFuncAttributeMaxDynamicSharedMemorySize, SMEM_BYTES);
    cudaFuncSetAttribute(k_scores_h, cudaFuncAttributeMaxDynamicSharedMemorySize, SMEM_BYTES);
    cudaFuncSetAttribute(k_dwv_h,    cudaFuncAttributeMaxDynamicSharedMemorySize, SMEM_BYTES);
    cudaFuncSetAttribute(k_wout_h,   cudaFuncAttributeMaxDynamicSharedMemorySize, SMEM_BYTES);

    // 0) fp16 staging of inputs + transposed weights
    f2h_kernel<<<(NB * NS * NE / 4 + 255) / 256, 256>>>(query, Qinp, NB * NS * NE / 4);
    f2h_kernel<<<(NB * NL * NGE / 4 + 255) / 256, 256>>>(key, Kinp, NB * NL * NGE / 4);
    dim3 tb(32, 8);
    transpose_h_kernel<<<dim3(24, 24), tb>>>(Wq,   WqTp, NE, NE);
    transpose_h_kernel<<<dim3(24, 1),  tb>>>(Wk,   WkTp, NGE, NE);
    transpose_h_kernel<<<dim3(24, 1),  tb>>>(Wv,   WvTp, NGE, NE);
    transpose_h_kernel<<<dim3(24, 24), tb>>>(Wout, WoTp, NE, NE);

    // 1) masks + lambda
    detect_mode_kernel<<<1, 256>>>((const unsigned int*)kmask, (NB * NL) / 4);
    expand_masks_kernel<<<(NB * NL + 255) / 256, 256>>>(qmask, kmask);
    lam_kernel<<<1, 256>>>(lq1, lk1, lq2, lk2);

    // 2) projections (fp16 in/out, fp32 accum)
    const float qscale = 1.0f / sqrtf((float)NHD);
    k_proj_h<<<dim3(NE / 128, (NB * NS) / 128, 1), 256, SMEM_BYTES>>>(
        Qinp, WqTp, Qhp, NE, NE, NE, NE, 0, 0, 0, qscale);
    k_proj_h<<<dim3(NE / 128, (NB * NL) / 128, 1), 256, SMEM_BYTES>>>(
        Kinp, WkTp, Khp, NGE, NGE, NGE, NE, 0, 0, 0, 1.0f);
    // Vt[b][e][l] = (key @ Wv)^T : A = WvT [NE x NGE], B = key_h (z-batched)
    k_proj_h<<<dim3(NL / 128, NE / 128, NB), 256, SMEM_BYTES>>>(
        WvTp, Kinp, Vthp, NGE, NGE, NGE, NL,
        0, (long)NL * NGE, (long)NE * NL, 1.0f);

    // 3) masked scores (fp32 out)
    k_scores_h<<<dim3(NL / 128, NS / 128, NB * 2), 256, SMEM_BYTES>>>();

    // 4) dual softmax -> dw (fp32 to d_out + fp16 scratch)
    softmax_dw_kernel<<<NB * NS, 256>>>(dw);

    // 5) o = dw @ V (split-K=4, fp32 partials in g_Sc)
    k_dwv_h<<<dim3(NE / 128, NS / 128, NB * 4), 256, SMEM_BYTES>>>(Scp);

    // 6) reduce + RMSNorm -> fp16 O
    rmsnorm4_kernel<<<NB * NS, 256>>>(Scp, Ohp, rms_w);

    // 7) out = O @ Wout (fp32 out)
    k_wout_h<<<dim3(NE / 128, (NB * NS) / 128), 256, SMEM_BYTES>>>(out);
}

// round 12
// speedup vs baseline: 1.7174x; 1.0086x over previous
#include <cuda_runtime.h>
#include <cuda_fp16.h>
#include <math.h>

#define NB 8
#define NS 512
#define NL 4096
#define NE 768
#define NHD 384
#define NGE 32

// ---------------------------------------------------------------------------
// Static device scratch
// ---------------------------------------------------------------------------
__device__ __half g_Qin[NB * NS * NE];
__device__ __half g_Kin[NB * NL * NGE];
__device__ __half g_Qh [NB * NS * NE];
__device__ __half g_Kh [NB * NL * NE];
__device__ __half g_Vth[NB * NE * NL];      // V transposed [b][e][l]
__device__ __half g_dwh[NB * NS * NL];      // fp16 copy of dw
__device__ __half g_Oh [NB * NS * NE];
__device__ __half g_Sch[NB * 2 * NS * NL];  // fp16 masked scores
__device__ float  g_Part[NB * 2 * NS * NE]; // split-K=2 fp32 partials
__device__ __half g_WqT[NE * NE];
__device__ __half g_WkT[NE * NGE];
__device__ __half g_WvT[NE * NGE];
__device__ __half g_WoT[NE * NE];
__device__ unsigned char g_qm[NB * NS];
__device__ unsigned char g_km[NB * NL];
__device__ float g_lam;
__device__ int   g_mode;

#define MASKVAL (-60000.0f)

// ---------------------------------------------------------------------------
// PTX helpers
// ---------------------------------------------------------------------------
__device__ __forceinline__ void cpa16(unsigned dst, const void* src)
{
    asm volatile("cp.async.cg.shared.global [%0], [%1], 16;" :: "r"(dst), "l"(src));
}
__device__ __forceinline__ void ldm4(unsigned& r0, unsigned& r1, unsigned& r2, unsigned& r3,
                                     unsigned addr)
{
    asm volatile("ldmatrix.sync.aligned.m8n8.x4.shared.b16 {%0,%1,%2,%3}, [%4];"
                 : "=r"(r0), "=r"(r1), "=r"(r2), "=r"(r3) : "r"(addr));
}
__device__ __forceinline__ void mma16(float* d, const unsigned* a, const unsigned* b)
{
    asm volatile(
        "mma.sync.aligned.m16n8k16.row.col.f32.f16.f16.f32 "
        "{%0,%1,%2,%3}, {%4,%5,%6,%7}, {%8,%9}, {%0,%1,%2,%3};"
        : "+f"(d[0]), "+f"(d[1]), "+f"(d[2]), "+f"(d[3])
        : "r"(a[0]), "r"(a[1]), "r"(a[2]), "r"(a[3]), "r"(b[0]), "r"(b[1]));
}

// ---------------------------------------------------------------------------
// Small helper kernels
// ---------------------------------------------------------------------------
__global__ void detect_mode_kernel(const unsigned int* __restrict__ w, int nwords)
{
    __shared__ int bad_i32, bad_f32, any_nz;
    if (threadIdx.x == 0) { bad_i32 = 0; bad_f32 = 0; any_nz = 0; }
    __syncthreads();
    for (int i = threadIdx.x; i < nwords; i += blockDim.x) {
        unsigned int v = w[i];
        if (v != 0u) {
            atomicOr(&any_nz, 1);
            if (v != 1u)           atomicOr(&bad_i32, 1);
            if (v != 0x3F800000u)  atomicOr(&bad_f32, 1);
        }
    }
    __syncthreads();
    if (threadIdx.x == 0) {
        int mode = 0;
        if (any_nz && !bad_i32)      mode = 1;
        else if (any_nz && !bad_f32) mode = 2;
        g_mode = mode;
    }
}

__device__ __forceinline__ unsigned char read_mask(const void* p, int i, int mode)
{
    if (mode == 1) return ((const int*)p)[i] != 0;
    if (mode == 2) return ((const float*)p)[i] != 0.0f;
    return ((const unsigned char*)p)[i] != 0;
}

__global__ void expand_masks_kernel(const void* __restrict__ qmask,
                                    const void* __restrict__ kmask)
{
    int i = blockIdx.x * blockDim.x + threadIdx.x;
    int mode = g_mode;
    if (i < NB * NS) g_qm[i] = read_mask(qmask, i, mode);
    if (i < NB * NL) g_km[i] = read_mask(kmask, i, mode);
}

__global__ void lam_kernel(const float* __restrict__ lq1, const float* __restrict__ lk1,
                           const float* __restrict__ lq2, const float* __restrict__ lk2)
{
    __shared__ float r1[256], r2[256];
    int t = threadIdx.x;
    float a = 0.f, b = 0.f;
    for (int i = t; i < NHD; i += 256) { a += lq1[i] * lk1[i]; b += lq2[i] * lk2[i]; }
    r1[t] = a; r2[t] = b; __syncthreads();
    for (int s = 128; s > 0; s >>= 1) {
        if (t < s) { r1[t] += r1[t + s]; r2[t] += r2[t + s]; }
        __syncthreads();
    }
    if (t == 0) g_lam = expf(r1[0]) - expf(r2[0]) + 0.2f;
}

__global__ void f2h_kernel(const float* __restrict__ in, __half* __restrict__ out, int n4)
{
    int i = blockIdx.x * blockDim.x + threadIdx.x;
    if (i < n4) {
        float4 v = ((const float4*)in)[i];
        ((__half2*)out)[2 * i]     = __floats2half2_rn(v.x, v.y);
        ((__half2*)out)[2 * i + 1] = __floats2half2_rn(v.z, v.w);
    }
}

__global__ void transpose_h_kernel(const float* __restrict__ in, __half* __restrict__ out,
                                   int rows, int cols)
{
    __shared__ float tile[32][33];
    int c0 = blockIdx.x * 32, r0 = blockIdx.y * 32;
    int x = threadIdx.x, y = threadIdx.y;
    for (int i = 0; i < 32; i += 8) {
        int r = r0 + y + i, c = c0 + x;
        if (r < rows && c < cols) tile[y + i][x] = in[(long)r * cols + c];
    }
    __syncthreads();
    for (int i = 0; i < 32; i += 8) {
        int r = c0 + y + i, c = r0 + x;
        if (r < cols && c < rows) out[(long)r * rows + c] = __float2half_rn(tile[x][y + i]);
    }
}

// ---------------------------------------------------------------------------
// fp16 NT GEMM core: C[M,N] = alpha * A[M,K] * B[N,K]^T, fp32 accumulate.
// 128x128 tiles, BK=32, 256 threads, 3-stage cp.async, 2 CTAs/SM.
// EPI 0: fp32 store.  EPI 2: fp16 store.  EPI 3: fp16 masked-scores store.
// ---------------------------------------------------------------------------
#define STAGES 3
#define PITCH_B 80
#define OP_BYTES (128 * PITCH_B)
#define STG_BYTES (2 * OP_BYTES)
#define SMEM_BYTES (STAGES * STG_BYTES)

template<int EPI>
__device__ __forceinline__ void gemm_h(
    const __half* __restrict__ A, const __half* __restrict__ B, void* __restrict__ Cv,
    int K, int lda, int ldb, int ldc, float alpha,
    const unsigned char* __restrict__ qm, const unsigned char* __restrict__ km)
{
    extern __shared__ char smc[];
    const unsigned smb = (unsigned)__cvta_generic_to_shared(smc);

    const int tid  = threadIdx.x;
    const int lane = tid & 31;
    const int wid  = tid >> 5;
    const int wm   = wid & 3;
    const int wn   = wid >> 2;
    const int lc   = lane & 3;
    const int lr   = lane >> 2;
    const int bm   = blockIdx.y * 128;
    const int bn   = blockIdx.x * 128;

    const int ldrow = tid >> 2;
    const int ldch  = tid & 3;

    const unsigned a_lane = smb + (unsigned)((wm * 32 + (lane & 15)) * PITCH_B
                                             + (lane >> 4) * 16);
    const unsigned b_lane = smb + (unsigned)(OP_BYTES + (wn * 64 + (lane & 15)) * PITCH_B
                                             + (lane >> 4) * 16);

    float d[2][8][4];
#pragma unroll
    for (int mt = 0; mt < 2; mt++)
#pragma unroll
        for (int nt = 0; nt < 8; nt++)
#pragma unroll
            for (int i = 0; i < 4; i++) d[mt][nt][i] = 0.f;

    const int ntile = K >> 5;

#define ISSUE_TILE(T, ST)                                                          \
    do {                                                                           \
        const int k0_ = (T) << 5;                                                  \
        const unsigned sg_ = smb + (unsigned)(ST) * STG_BYTES;                     \
        _Pragma("unroll")                                                          \
        for (int i_ = 0; i_ < 2; i_++) {                                           \
            int row_ = ldrow + i_ * 64;                                            \
            unsigned off_ = (unsigned)(row_ * PITCH_B + ldch * 16);                \
            cpa16(sg_ + off_, A + (long)(bm + row_) * lda + k0_ + ldch * 8);       \
            cpa16(sg_ + OP_BYTES + off_,                                           \
                  B + (long)(bn + row_) * ldb + k0_ + ldch * 8);                   \
        }                                                                          \
    } while (0)

#pragma unroll
    for (int s = 0; s < STAGES - 1; s++) {
        if (s < ntile) ISSUE_TILE(s, s);
        asm volatile("cp.async.commit_group;");
    }

    int stq = 0;
    for (int t = 0; t < ntile; t++) {
        asm volatile("cp.async.wait_group %0;" :: "n"(STAGES - 2));
        __syncthreads();
        {
            int tp = t + STAGES - 1;
            if (tp < ntile) {
                int stp = stq + STAGES - 1; if (stp >= STAGES) stp -= STAGES;
                ISSUE_TILE(tp, stp);
            }
        }
        asm volatile("cp.async.commit_group;");

        const unsigned sgb = (unsigned)stq * STG_BYTES;
        const unsigned sa = a_lane + sgb;
        const unsigned sb = b_lane + sgb;
#pragma unroll
        for (int kk = 0; kk < 2; kk++) {
            unsigned af[2][4];
#pragma unroll
            for (int mt = 0; mt < 2; mt++)
                ldm4(af[mt][0], af[mt][1], af[mt][2], af[mt][3],
                     sa + mt * (16 * PITCH_B) + kk * 32);
#pragma unroll
            for (int nb = 0; nb < 4; nb++) {
                unsigned b0, b1, b2, b3;
                ldm4(b0, b1, b2, b3, sb + nb * (16 * PITCH_B) + kk * 32);
                unsigned bf0[2] = { b0, b2 };
                unsigned bf1[2] = { b1, b3 };
                mma16(d[0][2 * nb + 0], af[0], bf0);
                mma16(d[0][2 * nb + 1], af[0], bf1);
                mma16(d[1][2 * nb + 0], af[1], bf0);
                mma16(d[1][2 * nb + 1], af[1], bf1);
            }
        }
        if (++stq == STAGES) stq = 0;
    }
#undef ISSUE_TILE

    // epilogue
#pragma unroll
    for (int mt = 0; mt < 2; mt++) {
        const int m0 = bm + wm * 32 + mt * 16 + lr;
        const bool qa = (EPI == 3) ? (qm[m0] != 0)     : true;
        const bool qb = (EPI == 3) ? (qm[m0 + 8] != 0) : true;
#pragma unroll
        for (int nt = 0; nt < 8; nt++) {
            const int n0 = bn + wn * 64 + nt * 8 + lc * 2;
            if (EPI == 2) {
                __half* Ch = (__half*)Cv;
                *(__half2*)(Ch + (long)m0 * ldc + n0) =
                    __floats2half2_rn(alpha * d[mt][nt][0], alpha * d[mt][nt][1]);
                *(__half2*)(Ch + (long)(m0 + 8) * ldc + n0) =
                    __floats2half2_rn(alpha * d[mt][nt][2], alpha * d[mt][nt][3]);
            } else if (EPI == 3) {
                __half* Ch = (__half*)Cv;
                const bool k0m = km[n0] != 0;
                const bool k1m = km[n0 + 1] != 0;
                float v0 = (qa && k0m) ? d[mt][nt][0] : MASKVAL;
                float v1 = (qa && k1m) ? d[mt][nt][1] : MASKVAL;
                float v2 = (qb && k0m) ? d[mt][nt][2] : MASKVAL;
                float v3 = (qb && k1m) ? d[mt][nt][3] : MASKVAL;
                *(__half2*)(Ch + (long)m0 * ldc + n0)       = __floats2half2_rn(v0, v1);
                *(__half2*)(Ch + (long)(m0 + 8) * ldc + n0) = __floats2half2_rn(v2, v3);
            } else {
                float* C = (float*)Cv;
                float2 v01 = make_float2(alpha * d[mt][nt][0], alpha * d[mt][nt][1]);
                float2 v23 = make_float2(alpha * d[mt][nt][2], alpha * d[mt][nt][3]);
                *(float2*)(C + (long)m0 * ldc + n0)       = v01;
                *(float2*)(C + (long)(m0 + 8) * ldc + n0) = v23;
            }
        }
    }
}

// Entry points --------------------------------------------------------------
__global__ void __launch_bounds__(256, 2) k_proj_h(
    const __half* __restrict__ A, const __half* __restrict__ B, __half* __restrict__ C,
    int K, int lda, int ldb, int ldc, long sA, long sB, long sC, float alpha)
{
    gemm_h<2>(A + (long)blockIdx.z * sA, B + (long)blockIdx.z * sB,
              C + (long)blockIdx.z * sC, K, lda, ldb, ldc, alpha, nullptr, nullptr);
}

__global__ void __launch_bounds__(256, 2) k_scores_h()
{
    const int z = blockIdx.z, b = z >> 1, h = z & 1;
    gemm_h<3>(g_Qh + (long)b * NS * NE + h * NHD,
              g_Kh + (long)b * NL * NE + h * NHD,
              g_Sch + (long)z * NS * NL,
              NHD, NE, NE, NL, 1.0f,
              g_qm + b * NS, g_km + b * NL);
}

__global__ void __launch_bounds__(256, 2) k_dwv_h(float* __restrict__ part)
{
    const int z = blockIdx.z, b = z >> 1, c = z & 1;
    gemm_h<0>(g_dwh + (long)b * NS * NL + c * 2048,
              g_Vth + (long)b * NE * NL + c * 2048,
              part + (long)z * NS * NE,
              2048, NL, NL, NE, 1.0f, nullptr, nullptr);
}

__global__ void __launch_bounds__(256, 2) k_wout_h(float* __restrict__ out)
{
    gemm_h<0>(g_Oh, g_WoT, out, NE, NE, NE, NE, 1.0f, nullptr, nullptr);
}

// ---------------------------------------------------------------------------
// Dual softmax -> differential weights (fp16 scores in; fp32 dw + fp16 copy out)
// ---------------------------------------------------------------------------
__global__ void __launch_bounds__(256) softmax_dw_kernel(float* __restrict__ dw_out)
{
    __shared__ float s0[NL];
    __shared__ float s1[NL];
    __shared__ float red[256];
    const int row = blockIdx.x;
    const int b = row >> 9;
    const int t = threadIdx.x;
    const __half* r0 = g_Sch + ((long)(b * 2 + 0) * NS + (row & (NS - 1))) * NL;
    const __half* r1 = g_Sch + ((long)(b * 2 + 1) * NS + (row & (NS - 1))) * NL;

    float m0 = -3.4e38f, m1 = -3.4e38f;
    for (int i = t * 8; i < NL; i += 2048) {
        uint4 u0 = *(const uint4*)(r0 + i);
        uint4 u1 = *(const uint4*)(r1 + i);
        const unsigned* w0 = (const unsigned*)&u0;
        const unsigned* w1 = (const unsigned*)&u1;
#pragma unroll
        for (int j = 0; j < 4; j++) {
            float2 f0 = __half22float2(*(const __half2*)&w0[j]);
            float2 f1 = __half22float2(*(const __half2*)&w1[j]);
            s0[i + 2 * j]     = f0.x; s0[i + 2 * j + 1] = f0.y;
            s1[i + 2 * j]     = f1.x; s1[i + 2 * j + 1] = f1.y;
            m0 = fmaxf(m0, fmaxf(f0.x, f0.y));
            m1 = fmaxf(m1, fmaxf(f1.x, f1.y));
        }
    }
    red[t] = m0; __syncthreads();
    for (int s = 128; s > 0; s >>= 1) { if (t < s) red[t] = fmaxf(red[t], red[t + s]); __syncthreads(); }
    m0 = red[0]; __syncthreads();
    red[t] = m1; __syncthreads();
    for (int s = 128; s > 0; s >>= 1) { if (t < s) red[t] = fmaxf(red[t], red[t + s]); __syncthreads(); }
    m1 = red[0]; __syncthreads();

    float sum0 = 0.f, sum1 = 0.f;
    for (int i = t; i < NL; i += 256) {
        float e0 = expf(s0[i] - m0); s0[i] = e0; sum0 += e0;
        float e1 = expf(s1[i] - m1); s1[i] = e1; sum1 += e1;
    }
    red[t] = sum0; __syncthreads();
    for (int s = 128; s > 0; s >>= 1) { if (t < s) red[t] += red[t + s]; __syncthreads(); }
    sum0 = red[0]; __syncthreads();
    red[t] = sum1; __syncthreads();
    for (int s = 128; s > 0; s >>= 1) { if (t < s) red[t] += red[t + s]; __syncthreads(); }
    sum1 = red[0]; __syncthreads();

    const float inv0 = 1.f / (sum0 + 1e-8f);
    const float inv1 = 1.f / (sum1 + 1e-8f);
    const float lam = g_lam;
    float mn = 3.4e38f;
    for (int i = t; i < NL; i += 256) {
        float v = s0[i] * inv0 - lam * (s1[i] * inv1);
        s0[i] = v;
        mn = fminf(mn, v);
    }
    red[t] = mn; __syncthreads();
    for (int s = 128; s > 0; s >>= 1) { if (t < s) red[t] = fminf(red[t], red[t + s]); __syncthreads(); }
    mn = red[0]; __syncthreads();

    const unsigned char qv = g_qm[row];
    const unsigned char* km = g_km + b * NL;
    float*  o  = dw_out + (long)row * NL;
    __half* oh = g_dwh  + (long)row * NL;
    for (int i = t; i < NL; i += 256) {
        float v = s0[i] - mn + 1e-5f;
        if (!qv || !km[i]) v = 0.f;
        o[i]  = v;
        oh[i] = __float2half_rn(v);
    }
}

// ---------------------------------------------------------------------------
// Sum 2 split-K partials + RMSNorm * rms_w * (1 - LAMBDA_INIT) -> fp16 O
// ---------------------------------------------------------------------------
__global__ void __launch_bounds__(256) rmsnorm2_kernel(const float* __restrict__ part,
                                                       __half* __restrict__ O,
                                                       const float* __restrict__ w)
{
    __shared__ float red[256];
    __shared__ float buf[NE];
    const int row = blockIdx.x;
    const int b = row >> 9, s = row & (NS - 1);
    const int t = threadIdx.x;
    const long base0 = ((long)(b * 2 + 0) * NS + s) * NE;
    const long base1 = ((long)(b * 2 + 1) * NS + s) * NE;
    float ss = 0.f;
    for (int i = t; i < NE; i += 256) {
        float v = part[base0 + i] + part[base1 + i];
        buf[i] = v;
        ss += v * v;
    }
    red[t] = ss; __syncthreads();
    for (int st = 128; st > 0; st >>= 1) { if (t < st) red[t] += red[t + st]; __syncthreads(); }
    const float sc = (1.0f / sqrtf(red[0] / (float)NE + 1e-5f)) * 0.8f;
    __half* o = O + (long)row * NE;
    for (int i = t; i < NE; i += 256) o[i] = __float2half_rn(buf[i] * sc * w[i]);
}

// ---------------------------------------------------------------------------
// Launch
// ---------------------------------------------------------------------------
extern "C" void kernel_launch(void* const* d_in, const int* in_sizes, int n_in,
                              void* d_out, int out_size)
{
    const float* query = (const float*)d_in[0];
    const float* key   = (const float*)d_in[1];
    const void*  qmask = d_in[2];
    const void*  kmask = d_in[3];
    const float* Wq    = (const float*)d_in[4];
    const float* Wk    = (const float*)d_in[5];
    const float* Wv    = (const float*)d_in[6];
    const float* Wout  = (const float*)d_in[7];
    const float* lq1   = (const float*)d_in[8];
    const float* lk1   = (const float*)d_in[9];
    const float* lq2   = (const float*)d_in[10];
    const float* lk2   = (const float*)d_in[11];
    const float* rms_w = (const float*)d_in[12];

    float* out = (float*)d_out;
    float* dw  = out + (long)NB * NS * NE;

    void* p;
    __half *Qinp, *Kinp, *WqTp, *WkTp, *WvTp, *WoTp, *Vthp, *Ohp;
    float *Partp;
    cudaGetSymbolAddress(&p, g_Qin);  Qinp  = (__half*)p;
    cudaGetSymbolAddress(&p, g_Kin);  Kinp  = (__half*)p;
    cudaGetSymbolAddress(&p, g_WqT);  WqTp  = (__half*)p;
    cudaGetSymbolAddress(&p, g_WkT);  WkTp  = (__half*)p;
    cudaGetSymbolAddress(&p, g_WvT);  WvTp  = (__half*)p;
    cudaGetSymbolAddress(&p, g_WoT);  WoTp  = (__half*)p;
    cudaGetSymbolAddress(&p, g_Vth);  Vthp  = (__half*)p;
    cudaGetSymbolAddress(&p, g_Oh);   Ohp   = (__half*)p;
    cudaGetSymbolAddress(&p, g_Part); Partp = (float*)p;
    __half *Qhp, *Khp;
    cudaGetSymbolAddress(&p, g_Qh);   Qhp   = (__half*)p;
    cudaGetSymbolAddress(&p, g_Kh);   Khp   = (__half*)p;

    cudaFuncSetAttribute(k_proj_h,   cudaFuncAttributeMaxDynamicSharedMemorySize, SMEM_BYTES);
    cudaFuncSetAttribute(k_scores_h, cudaFuncAttributeMaxDynamicSharedMemorySize, SMEM_BYTES);
    cudaFuncSetAttribute(k_dwv_h,    cudaFuncAttributeMaxDynamicSharedMemorySize, SMEM_BYTES);
    cudaFuncSetAttribute(k_wout_h,   cudaFuncAttributeMaxDynamicSharedMemorySize, SMEM_BYTES);

    // 0) fp16 staging of inputs + transposed weights
    f2h_kernel<<<(NB * NS * NE / 4 + 255) / 256, 256>>>(query, Qinp, NB * NS * NE / 4);
    f2h_kernel<<<(NB * NL * NGE / 4 + 255) / 256, 256>>>(key, Kinp, NB * NL * NGE / 4);
    dim3 tb(32, 8);
    transpose_h_kernel<<<dim3(24, 24), tb>>>(Wq,   WqTp, NE, NE);
    transpose_h_kernel<<<dim3(24, 1),  tb>>>(Wk,   WkTp, NGE, NE);
    transpose_h_kernel<<<dim3(24, 1),  tb>>>(Wv,   WvTp, NGE, NE);
    transpose_h_kernel<<<dim3(24, 24), tb>>>(Wout, WoTp, NE, NE);

    // 1) masks + lambda
    detect_mode_kernel<<<1, 256>>>((const unsigned int*)kmask, (NB * NL) / 4);
    expand_masks_kernel<<<(NB * NL + 255) / 256, 256>>>(qmask, kmask);
    lam_kernel<<<1, 256>>>(lq1, lk1, lq2, lk2);

    // 2) projections
    const float qscale = 1.0f / sqrtf((float)NHD);
    k_proj_h<<<dim3(NE / 128, (NB * NS) / 128, 1), 256, SMEM_BYTES>>>(
        Qinp, WqTp, Qhp, NE, NE, NE, NE, 0, 0, 0, qscale);
    k_proj_h<<<dim3(NE / 128, (NB * NL) / 128, 1), 256, SMEM_BYTES>>>(
        Kinp, WkTp, Khp, NGE, NGE, NGE, NE, 0, 0, 0, 1.0f);
    k_proj_h<<<dim3(NL / 128, NE / 128, NB), 256, SMEM_BYTES>>>(
        WvTp, Kinp, Vthp, NGE, NGE, NGE, NL,
        0, (long)NL * NGE, (long)NE * NL, 1.0f);

    // 3) masked scores -> fp16
    k_scores_h<<<dim3(NL / 128, NS / 128, NB * 2), 256, SMEM_BYTES>>>();

    // 4) dual softmax -> dw
    softmax_dw_kernel<<<NB * NS, 256>>>(dw);

    // 5) o = dw @ V (split-K=2, fp32 partials)
    k_dwv_h<<<dim3(NE / 128, NS / 128, NB * 2), 256, SMEM_BYTES>>>(Partp);

    // 6) reduce + RMSNorm -> fp16 O
    rmsnorm2_kernel<<<NB * NS, 256>>>(Partp, Ohp, rms_w);

    // 7) out = O @ Wout (fp32 out)
    k_wout_h<<<dim3(NE / 128, (NB * NS) / 128), 256, SMEM_BYTES>>>(out);
}

// round 13
// speedup vs baseline: 1.7975x; 1.0466x over previous
#include <cuda_runtime.h>
#include <cuda_fp16.h>
#include <math.h>

#define NB 8
#define NS 512
#define NL 4096
#define NE 768
#define NHD 384
#define NGE 32

// ---------------------------------------------------------------------------
// Static device scratch
// ---------------------------------------------------------------------------
__device__ __half g_Qin[NB * NS * NE];
__device__ __half g_Kin[NB * NL * NGE];
__device__ __half g_Qh [NB * NS * NE];
__device__ __half g_Kh [NB * NL * NE];
__device__ __half g_Vth[NB * NE * NL];      // V transposed [b][e][l]
__device__ __half g_dwh[NB * NS * NL];      // fp16 copy of dw
__device__ __half g_Oh [NB * NS * NE];
__device__ __half g_Sch[NB * 2 * NS * NL];  // fp16 masked scores
__device__ float  g_Part[NB * 4 * NS * NE]; // split-K=4 fp32 partials
__device__ __half g_WqT[NE * NE];
__device__ __half g_WkT[NE * NGE];
__device__ __half g_WvT[NE * NGE];
__device__ __half g_WoT[NE * NE];
__device__ unsigned char g_qm[NB * NS];
__device__ unsigned char g_km[NB * NL];
__device__ float g_lam;
__device__ int   g_mode;

#define MASKVAL (-60000.0f)

// ---------------------------------------------------------------------------
// PTX helpers
// ---------------------------------------------------------------------------
__device__ __forceinline__ void cpa16(unsigned dst, const void* src)
{
    asm volatile("cp.async.cg.shared.global [%0], [%1], 16;" :: "r"(dst), "l"(src));
}
__device__ __forceinline__ void ldm4(unsigned& r0, unsigned& r1, unsigned& r2, unsigned& r3,
                                     unsigned addr)
{
    asm volatile("ldmatrix.sync.aligned.m8n8.x4.shared.b16 {%0,%1,%2,%3}, [%4];"
                 : "=r"(r0), "=r"(r1), "=r"(r2), "=r"(r3) : "r"(addr));
}
__device__ __forceinline__ void mma16(float* d, const unsigned* a, const unsigned* b)
{
    asm volatile(
        "mma.sync.aligned.m16n8k16.row.col.f32.f16.f16.f32 "
        "{%0,%1,%2,%3}, {%4,%5,%6,%7}, {%8,%9}, {%0,%1,%2,%3};"
        : "+f"(d[0]), "+f"(d[1]), "+f"(d[2]), "+f"(d[3])
        : "r"(a[0]), "r"(a[1]), "r"(a[2]), "r"(a[3]), "r"(b[0]), "r"(b[1]));
}

// ---------------------------------------------------------------------------
// Small helper kernels
// ---------------------------------------------------------------------------
__global__ void detect_mode_kernel(const unsigned int* __restrict__ w, int nwords)
{
    __shared__ int bad_i32, bad_f32, any_nz;
    if (threadIdx.x == 0) { bad_i32 = 0; bad_f32 = 0; any_nz = 0; }
    __syncthreads();
    for (int i = threadIdx.x; i < nwords; i += blockDim.x) {
        unsigned int v = w[i];
        if (v != 0u) {
            atomicOr(&any_nz, 1);
            if (v != 1u)           atomicOr(&bad_i32, 1);
            if (v != 0x3F800000u)  atomicOr(&bad_f32, 1);
        }
    }
    __syncthreads();
    if (threadIdx.x == 0) {
        int mode = 0;
        if (any_nz && !bad_i32)      mode = 1;
        else if (any_nz && !bad_f32) mode = 2;
        g_mode = mode;
    }
}

__device__ __forceinline__ unsigned char read_mask(const void* p, int i, int mode)
{
    if (mode == 1) return ((const int*)p)[i] != 0;
    if (mode == 2) return ((const float*)p)[i] != 0.0f;
    return ((const unsigned char*)p)[i] != 0;
}

__global__ void expand_masks_kernel(const void* __restrict__ qmask,
                                    const void* __restrict__ kmask)
{
    int i = blockIdx.x * blockDim.x + threadIdx.x;
    int mode = g_mode;
    if (i < NB * NS) g_qm[i] = read_mask(qmask, i, mode);
    if (i < NB * NL) g_km[i] = read_mask(kmask, i, mode);
}

__global__ void lam_kernel(const float* __restrict__ lq1, const float* __restrict__ lk1,
                           const float* __restrict__ lq2, const float* __restrict__ lk2)
{
    __shared__ float r1[256], r2[256];
    int t = threadIdx.x;
    float a = 0.f, b = 0.f;
    for (int i = t; i < NHD; i += 256) { a += lq1[i] * lk1[i]; b += lq2[i] * lk2[i]; }
    r1[t] = a; r2[t] = b; __syncthreads();
    for (int s = 128; s > 0; s >>= 1) {
        if (t < s) { r1[t] += r1[t + s]; r2[t] += r2[t + s]; }
        __syncthreads();
    }
    if (t == 0) g_lam = expf(r1[0]) - expf(r2[0]) + 0.2f;
}

__global__ void f2h_kernel(const float* __restrict__ in, __half* __restrict__ out, int n4)
{
    int i = blockIdx.x * blockDim.x + threadIdx.x;
    if (i < n4) {
        float4 v = ((const float4*)in)[i];
        ((__half2*)out)[2 * i]     = __floats2half2_rn(v.x, v.y);
        ((__half2*)out)[2 * i + 1] = __floats2half2_rn(v.z, v.w);
    }
}

__global__ void transpose_h_kernel(const float* __restrict__ in, __half* __restrict__ out,
                                   int rows, int cols)
{
    __shared__ float tile[32][33];
    int c0 = blockIdx.x * 32, r0 = blockIdx.y * 32;
    int x = threadIdx.x, y = threadIdx.y;
    for (int i = 0; i < 32; i += 8) {
        int r = r0 + y + i, c = c0 + x;
        if (r < rows && c < cols) tile[y + i][x] = in[(long)r * cols + c];
    }
    __syncthreads();
    for (int i = 0; i < 32; i += 8) {
        int r = c0 + y + i, c = r0 + x;
        if (r < cols && c < rows) out[(long)r * rows + c] = __float2half_rn(tile[x][y + i]);
    }
}

// ---------------------------------------------------------------------------
// fp16 NT GEMM core, templated on BKH (K-tile in halves: 32 or 64).
// C[M,N] = alpha * A[M,K] * B[N,K]^T, fp32 accumulate.
// 128x128 tiles, 256 threads (8 warps, 32x64 warp tiles), 3-stage cp.async,
// 2 CTAs/SM. EPI 0: fp32.  EPI 2: fp16.  EPI 3: fp16 masked scores.
// pitch = BKH+8 halves -> conflict-free ldmatrix.
// ---------------------------------------------------------------------------
#define STAGES 3
#define SMEM_OF(BKH) (STAGES * 2 * 128 * ((BKH) + 8) * 2)

template<int BKH, int EPI>
__device__ __forceinline__ void gemm_h(
    const __half* __restrict__ A, const __half* __restrict__ B, void* __restrict__ Cv,
    int K, int lda, int ldb, int ldc, float alpha,
    const unsigned char* __restrict__ qm, const unsigned char* __restrict__ km)
{
    constexpr int PITCHB   = (BKH + 8) * 2;      // bytes per row
    constexpr int OPB      = 128 * PITCHB;       // bytes per operand tile
    constexpr int STGB     = 2 * OPB;            // bytes per stage
    constexpr int CPR      = BKH / 8;            // 16B chunks per row
    constexpr int LDITER   = BKH / 16;           // cp.async iters (256 thr x 16B)
    constexpr int KKS      = BKH / 16;           // k16 steps per tile

    extern __shared__ char smc[];
    const unsigned smb = (unsigned)__cvta_generic_to_shared(smc);

    const int tid  = threadIdx.x;
    const int lane = tid & 31;
    const int wid  = tid >> 5;
    const int wm   = wid & 3;
    const int wn   = wid >> 2;
    const int lc   = lane & 3;
    const int lr   = lane >> 2;
    const int bm   = blockIdx.y * 128;
    const int bn   = blockIdx.x * 128;

    const unsigned a_lane = smb + (unsigned)((wm * 32 + (lane & 15)) * PITCHB
                                             + (lane >> 4) * 16);
    const unsigned b_lane = smb + (unsigned)(OPB + (wn * 64 + (lane & 15)) * PITCHB
                                             + (lane >> 4) * 16);

    float d[2][8][4];
#pragma unroll
    for (int mt = 0; mt < 2; mt++)
#pragma unroll
        for (int nt = 0; nt < 8; nt++)
#pragma unroll
            for (int i = 0; i < 4; i++) d[mt][nt][i] = 0.f;

    const int ntile = K / BKH;

#define ISSUE_TILE(T, ST)                                                          \
    do {                                                                           \
        const int k0_ = (T) * BKH;                                                 \
        const unsigned sg_ = smb + (unsigned)(ST) * STGB;                          \
        _Pragma("unroll")                                                          \
        for (int i_ = 0; i_ < LDITER; i_++) {                                      \
            int idx_ = i_ * 256 + tid;                                             \
            int row_ = idx_ / CPR, ch_ = idx_ % CPR;                               \
            unsigned off_ = (unsigned)(row_ * PITCHB + ch_ * 16);                  \
            cpa16(sg_ + off_, A + (long)(bm + row_) * lda + k0_ + ch_ * 8);        \
            cpa16(sg_ + OPB + off_, B + (long)(bn + row_) * ldb + k0_ + ch_ * 8);  \
        }                                                                          \
    } while (0)

#pragma unroll
    for (int s = 0; s < STAGES - 1; s++) {
        if (s < ntile) ISSUE_TILE(s, s);
        asm volatile("cp.async.commit_group;");
    }

    int stq = 0;
    for (int t = 0; t < ntile; t++) {
        asm volatile("cp.async.wait_group %0;" :: "n"(STAGES - 2));
        __syncthreads();
        {
            int tp = t + STAGES - 1;
            if (tp < ntile) {
                int stp = stq + STAGES - 1; if (stp >= STAGES) stp -= STAGES;
                ISSUE_TILE(tp, stp);
            }
        }
        asm volatile("cp.async.commit_group;");

        const unsigned sgb = (unsigned)stq * STGB;
        const unsigned sa = a_lane + sgb;
        const unsigned sb = b_lane + sgb;
#pragma unroll
        for (int kk = 0; kk < KKS; kk++) {
            unsigned af[2][4];
#pragma unroll
            for (int mt = 0; mt < 2; mt++)
                ldm4(af[mt][0], af[mt][1], af[mt][2], af[mt][3],
                     sa + mt * (16 * PITCHB) + kk * 32);
#pragma unroll
            for (int nb = 0; nb < 4; nb++) {
                unsigned b0, b1, b2, b3;
                ldm4(b0, b1, b2, b3, sb + nb * (16 * PITCHB) + kk * 32);
                unsigned bf0[2] = { b0, b2 };
                unsigned bf1[2] = { b1, b3 };
                mma16(d[0][2 * nb + 0], af[0], bf0);
                mma16(d[0][2 * nb + 1], af[0], bf1);
                mma16(d[1][2 * nb + 0], af[1], bf0);
                mma16(d[1][2 * nb + 1], af[1], bf1);
            }
        }
        if (++stq == STAGES) stq = 0;
    }
#undef ISSUE_TILE

    // epilogue
#pragma unroll
    for (int mt = 0; mt < 2; mt++) {
        const int m0 = bm + wm * 32 + mt * 16 + lr;
        const bool qa = (EPI == 3) ? (qm[m0] != 0)     : true;
        const bool qb = (EPI == 3) ? (qm[m0 + 8] != 0) : true;
#pragma unroll
        for (int nt = 0; nt < 8; nt++) {
            const int n0 = bn + wn * 64 + nt * 8 + lc * 2;
            if (EPI == 2) {
                __half* Ch = (__half*)Cv;
                *(__half2*)(Ch + (long)m0 * ldc + n0) =
                    __floats2half2_rn(alpha * d[mt][nt][0], alpha * d[mt][nt][1]);
                *(__half2*)(Ch + (long)(m0 + 8) * ldc + n0) =
                    __floats2half2_rn(alpha * d[mt][nt][2], alpha * d[mt][nt][3]);
            } else if (EPI == 3) {
                __half* Ch = (__half*)Cv;
                const bool k0m = km[n0] != 0;
                const bool k1m = km[n0 + 1] != 0;
                float v0 = (qa && k0m) ? d[mt][nt][0] : MASKVAL;
                float v1 = (qa && k1m) ? d[mt][nt][1] : MASKVAL;
                float v2 = (qb && k0m) ? d[mt][nt][2] : MASKVAL;
                float v3 = (qb && k1m) ? d[mt][nt][3] : MASKVAL;
                *(__half2*)(Ch + (long)m0 * ldc + n0)       = __floats2half2_rn(v0, v1);
                *(__half2*)(Ch + (long)(m0 + 8) * ldc + n0) = __floats2half2_rn(v2, v3);
            } else {
                float* C = (float*)Cv;
                float2 v01 = make_float2(alpha * d[mt][nt][0], alpha * d[mt][nt][1]);
                float2 v23 = make_float2(alpha * d[mt][nt][2], alpha * d[mt][nt][3]);
                *(float2*)(C + (long)m0 * ldc + n0)       = v01;
                *(float2*)(C + (long)(m0 + 8) * ldc + n0) = v23;
            }
        }
    }
}

// Entry points --------------------------------------------------------------
// Q projection (K=768) -> fp16, BK=64
__global__ void __launch_bounds__(256, 2) k_projq_h(float unused)
{
    const float qscale = 0.051031036307982884f;   // 1/sqrt(384)
    gemm_h<64, 2>(g_Qin, g_WqT, g_Qh, NE, NE, NE, NE, qscale, nullptr, nullptr);
}

// K/V projections (K=32) -> fp16, BK=32 (z-batched for V-transposed)
__global__ void __launch_bounds__(256, 2) k_proj32_h(
    const __half* __restrict__ A, const __half* __restrict__ B, __half* __restrict__ C,
    int lda, int ldb, int ldc, long sA, long sB, long sC)
{
    gemm_h<32, 2>(A + (long)blockIdx.z * sA, B + (long)blockIdx.z * sB,
                  C + (long)blockIdx.z * sC, NGE, lda, ldb, ldc, 1.0f, nullptr, nullptr);
}

__global__ void __launch_bounds__(256, 2) k_scores_h()
{
    const int z = blockIdx.z, b = z >> 1, h = z & 1;
    gemm_h<64, 3>(g_Qh + (long)b * NS * NE + h * NHD,
                  g_Kh + (long)b * NL * NE + h * NHD,
                  g_Sch + (long)z * NS * NL,
                  NHD, NE, NE, NL, 1.0f,
                  g_qm + b * NS, g_km + b * NL);
}

__global__ void __launch_bounds__(256, 2) k_dwv_h(float* __restrict__ part)
{
    const int z = blockIdx.z, b = z >> 2, c = z & 3;
    gemm_h<64, 0>(g_dwh + (long)b * NS * NL + c * 1024,
                  g_Vth + (long)b * NE * NL + c * 1024,
                  part + (long)z * NS * NE,
                  1024, NL, NL, NE, 1.0f, nullptr, nullptr);
}

__global__ void __launch_bounds__(256, 2) k_wout_h(float* __restrict__ out)
{
    gemm_h<64, 0>(g_Oh, g_WoT, out, NE, NE, NE, NE, 1.0f, nullptr, nullptr);
}

// ---------------------------------------------------------------------------
// Dual softmax -> differential weights
// ---------------------------------------------------------------------------
__global__ void __launch_bounds__(256) softmax_dw_kernel(float* __restrict__ dw_out)
{
    __shared__ float s0[NL];
    __shared__ float s1[NL];
    __shared__ float red[256];
    const int row = blockIdx.x;
    const int b = row >> 9;
    const int t = threadIdx.x;
    const __half* r0 = g_Sch + ((long)(b * 2 + 0) * NS + (row & (NS - 1))) * NL;
    const __half* r1 = g_Sch + ((long)(b * 2 + 1) * NS + (row & (NS - 1))) * NL;

    float m0 = -3.4e38f, m1 = -3.4e38f;
    for (int i = t * 8; i < NL; i += 2048) {
        uint4 u0 = *(const uint4*)(r0 + i);
        uint4 u1 = *(const uint4*)(r1 + i);
        const unsigned* w0 = (const unsigned*)&u0;
        const unsigned* w1 = (const unsigned*)&u1;
#pragma unroll
        for (int j = 0; j < 4; j++) {
            float2 f0 = __half22float2(*(const __half2*)&w0[j]);
            float2 f1 = __half22float2(*(const __half2*)&w1[j]);
            s0[i + 2 * j]     = f0.x; s0[i + 2 * j + 1] = f0.y;
            s1[i + 2 * j]     = f1.x; s1[i + 2 * j + 1] = f1.y;
            m0 = fmaxf(m0, fmaxf(f0.x, f0.y));
            m1 = fmaxf(m1, fmaxf(f1.x, f1.y));
        }
    }
    red[t] = m0; __syncthreads();
    for (int s = 128; s > 0; s >>= 1) { if (t < s) red[t] = fmaxf(red[t], red[t + s]); __syncthreads(); }
    m0 = red[0]; __syncthreads();
    red[t] = m1; __syncthreads();
    for (int s = 128; s > 0; s >>= 1) { if (t < s) red[t] = fmaxf(red[t], red[t + s]); __syncthreads(); }
    m1 = red[0]; __syncthreads();

    float sum0 = 0.f, sum1 = 0.f;
    for (int i = t; i < NL; i += 256) {
        float e0 = expf(s0[i] - m0); s0[i] = e0; sum0 += e0;
        float e1 = expf(s1[i] - m1); s1[i] = e1; sum1 += e1;
    }
    red[t] = sum0; __syncthreads();
    for (int s = 128; s > 0; s >>= 1) { if (t < s) red[t] += red[t + s]; __syncthreads(); }
    sum0 = red[0]; __syncthreads();
    red[t] = sum1; __syncthreads();
    for (int s = 128; s > 0; s >>= 1) { if (t < s) red[t] += red[t + s]; __syncthreads(); }
    sum1 = red[0]; __syncthreads();

    const float inv0 = 1.f / (sum0 + 1e-8f);
    const float inv1 = 1.f / (sum1 + 1e-8f);
    const float lam = g_lam;
    float mn = 3.4e38f;
    for (int i = t; i < NL; i += 256) {
        float v = s0[i] * inv0 - lam * (s1[i] * inv1);
        s0[i] = v;
        mn = fminf(mn, v);
    }
    red[t] = mn; __syncthreads();
    for (int s = 128; s > 0; s >>= 1) { if (t < s) red[t] = fminf(red[t], red[t + s]); __syncthreads(); }
    mn = red[0]; __syncthreads();

    const unsigned char qv = g_qm[row];
    const unsigned char* km = g_km + b * NL;
    float*  o  = dw_out + (long)row * NL;
    __half* oh = g_dwh  + (long)row * NL;
    for (int i = t; i < NL; i += 256) {
        float v = s0[i] - mn + 1e-5f;
        if (!qv || !km[i]) v = 0.f;
        o[i]  = v;
        oh[i] = __float2half_rn(v);
    }
}

// ---------------------------------------------------------------------------
// Sum 4 split-K partials + RMSNorm * rms_w * (1 - LAMBDA_INIT) -> fp16 O
// ---------------------------------------------------------------------------
__global__ void __launch_bounds__(256) rmsnorm4_kernel(const float* __restrict__ part,
                                                       __half* __restrict__ O,
                                                       const float* __restrict__ w)
{
    __shared__ float red[256];
    __shared__ float buf[NE];
    const int row = blockIdx.x;
    const int b = row >> 9, s = row & (NS - 1);
    const int t = threadIdx.x;
    const long base0 = ((long)(b * 4 + 0) * NS + s) * NE;
    const long base1 = ((long)(b * 4 + 1) * NS + s) * NE;
    const long base2 = ((long)(b * 4 + 2) * NS + s) * NE;
    const long base3 = ((long)(b * 4 + 3) * NS + s) * NE;
    float ss = 0.f;
    for (int i = t; i < NE; i += 256) {
        float v = part[base0 + i] + part[base1 + i] + part[base2 + i] + part[base3 + i];
        buf[i] = v;
        ss += v * v;
    }
    red[t] = ss; __syncthreads();
    for (int st = 128; st > 0; st >>= 1) { if (t < st) red[t] += red[t + st]; __syncthreads(); }
    const float sc = (1.0f / sqrtf(red[0] / (float)NE + 1e-5f)) * 0.8f;
    __half* o = O + (long)row * NE;
    for (int i = t; i < NE; i += 256) o[i] = __float2half_rn(buf[i] * sc * w[i]);
}

// ---------------------------------------------------------------------------
// Launch
// ---------------------------------------------------------------------------
extern "C" void kernel_launch(void* const* d_in, const int* in_sizes, int n_in,
                              void* d_out, int out_size)
{
    const float* query = (const float*)d_in[0];
    const float* key   = (const float*)d_in[1];
    const void*  qmask = d_in[2];
    const void*  kmask = d_in[3];
    const float* Wq    = (const float*)d_in[4];
    const float* Wk    = (const float*)d_in[5];
    const float* Wv    = (const float*)d_in[6];
    const float* Wout  = (const float*)d_in[7];
    const float* lq1   = (const float*)d_in[8];
    const float* lk1   = (const float*)d_in[9];
    const float* lq2   = (const float*)d_in[10];
    const float* lk2   = (const float*)d_in[11];
    const float* rms_w = (const float*)d_in[12];

    float* out = (float*)d_out;
    float* dw  = out + (long)NB * NS * NE;

    void* p;
    __half *Qinp, *Kinp, *WqTp, *WkTp, *WvTp, *WoTp, *Khp, *Vthp, *Ohp;
    float *Partp;
    cudaGetSymbolAddress(&p, g_Qin);  Qinp  = (__half*)p;
    cudaGetSymbolAddress(&p, g_Kin);  Kinp  = (__half*)p;
    cudaGetSymbolAddress(&p, g_WqT);  WqTp  = (__half*)p;
    cudaGetSymbolAddress(&p, g_WkT);  WkTp  = (__half*)p;
    cudaGetSymbolAddress(&p, g_WvT);  WvTp  = (__half*)p;
    cudaGetSymbolAddress(&p, g_WoT);  WoTp  = (__half*)p;
    cudaGetSymbolAddress(&p, g_Kh);   Khp   = (__half*)p;
    cudaGetSymbolAddress(&p, g_Vth);  Vthp  = (__half*)p;
    cudaGetSymbolAddress(&p, g_Oh);   Ohp   = (__half*)p;
    cudaGetSymbolAddress(&p, g_Part); Partp = (float*)p;

    const int SM32 = SMEM_OF(32);   // 61440
    const int SM64 = SMEM_OF(64);   // 110592
    cudaFuncSetAttribute(k_projq_h,  cudaFuncAttributeMaxDynamicSharedMemorySize, SM64);
    cudaFuncSetAttribute(k_proj32_h, cudaFuncAttributeMaxDynamicSharedMemorySize, SM32);
    cudaFuncSetAttribute(k_scores_h, cudaFuncAttributeMaxDynamicSharedMemorySize, SM64);
    cudaFuncSetAttribute(k_dwv_h,    cudaFuncAttributeMaxDynamicSharedMemorySize, SM64);
    cudaFuncSetAttribute(k_wout_h,   cudaFuncAttributeMaxDynamicSharedMemorySize, SM64);

    // 0) fp16 staging of inputs + transposed weights
    f2h_kernel<<<(NB * NS * NE / 4 + 255) / 256, 256>>>(query, Qinp, NB * NS * NE / 4);
    f2h_kernel<<<(NB * NL * NGE / 4 + 255) / 256, 256>>>(key, Kinp, NB * NL * NGE / 4);
    dim3 tb(32, 8);
    transpose_h_kernel<<<dim3(24, 24), tb>>>(Wq,   WqTp, NE, NE);
    transpose_h_kernel<<<dim3(24, 1),  tb>>>(Wk,   WkTp, NGE, NE);
    transpose_h_kernel<<<dim3(24, 1),  tb>>>(Wv,   WvTp, NGE, NE);
    transpose_h_kernel<<<dim3(24, 24), tb>>>(Wout, WoTp, NE, NE);

    // 1) masks + lambda
    detect_mode_kernel<<<1, 256>>>((const unsigned int*)kmask, (NB * NL) / 4);
    expand_masks_kernel<<<(NB * NL + 255) / 256, 256>>>(qmask, kmask);
    lam_kernel<<<1, 256>>>(lq1, lk1, lq2, lk2);

    // 2) projections
    k_projq_h<<<dim3(NE / 128, (NB * NS) / 128), 256, SM64>>>(0.f);
    k_proj32_h<<<dim3(NE / 128, (NB * NL) / 128, 1), 256, SM32>>>(
        Kinp, WkTp, Khp, NGE, NGE, NE, 0, 0, 0);
    k_proj32_h<<<dim3(NL / 128, NE / 128, NB), 256, SM32>>>(
        WvTp, Kinp, Vthp, NGE, NGE, NL,
        0, (long)NL * NGE, (long)NE * NL);

    // 3) masked scores -> fp16
    k_scores_h<<<dim3(NL / 128, NS / 128, NB * 2), 256, SM64>>>();

    // 4) dual softmax -> dw
    softmax_dw_kernel<<<NB * NS, 256>>>(dw);

    // 5) o = dw @ V (split-K=4, fp32 partials)
    k_dwv_h<<<dim3(NE / 128, NS / 128, NB * 4), 256, SM64>>>(Partp);

    // 6) reduce + RMSNorm -> fp16 O
    rmsnorm4_kernel<<<NB * NS, 256>>>(Partp, Ohp, rms_w);

    // 7) out = O @ Wout (fp32 out)
    k_wout_h<<<dim3(NE / 128, (NB * NS) / 128), 256, SM64>>>(out);
}

// round 14
// speedup vs baseline: 2.0359x; 1.1326x over previous
#include <cuda_runtime.h>
#include <cuda_fp16.h>
#include <math.h>

#define NB 8
#define NS 512
#define NL 4096
#define NE 768
#define NHD 384
#define NGE 32

// ---------------------------------------------------------------------------
// Static device scratch
// ---------------------------------------------------------------------------
__device__ __half g_Qin[NB * NS * NE];
__device__ __half g_Kin[NB * NL * NGE];
__device__ __half g_Qh [NB * NS * NE];
__device__ __half g_Kh [NB * NL * NE];
__device__ __half g_Vth[NB * NE * NL];      // V transposed [b][e][l]
__device__ __half g_dwh[NB * NS * NL];      // fp16 copy of dw
__device__ __half g_Oh [NB * NS * NE];
__device__ __half g_Sch[NB * 2 * NS * NL];  // fp16 masked scores
__device__ float  g_Part[NB * 4 * NS * NE]; // split-K=4 fp32 partials
__device__ __half g_WqT[NE * NE];
__device__ __half g_WkT[NE * NGE];
__device__ __half g_WvT[NE * NGE];
__device__ __half g_WoT[NE * NE];
__device__ unsigned char g_qm[NB * NS];
__device__ unsigned char g_km[NB * NL];
__device__ float g_lam;
__device__ int   g_mode;

#define MASKVAL (-60000.0f)

// ---------------------------------------------------------------------------
// PTX helpers
// ---------------------------------------------------------------------------
__device__ __forceinline__ void cpa16(unsigned dst, const void* src)
{
    asm volatile("cp.async.cg.shared.global [%0], [%1], 16;" :: "r"(dst), "l"(src));
}
__device__ __forceinline__ void ldm4(unsigned& r0, unsigned& r1, unsigned& r2, unsigned& r3,
                                     unsigned addr)
{
    asm volatile("ldmatrix.sync.aligned.m8n8.x4.shared.b16 {%0,%1,%2,%3}, [%4];"
                 : "=r"(r0), "=r"(r1), "=r"(r2), "=r"(r3) : "r"(addr));
}
__device__ __forceinline__ void mma16(float* d, const unsigned* a, const unsigned* b)
{
    asm volatile(
        "mma.sync.aligned.m16n8k16.row.col.f32.f16.f16.f32 "
        "{%0,%1,%2,%3}, {%4,%5,%6,%7}, {%8,%9}, {%0,%1,%2,%3};"
        : "+f"(d[0]), "+f"(d[1]), "+f"(d[2]), "+f"(d[3])
        : "r"(a[0]), "r"(a[1]), "r"(a[2]), "r"(a[3]), "r"(b[0]), "r"(b[1]));
}

// ---------------------------------------------------------------------------
// prep1: block 0 = mask dtype detection, block 1 = lambda
// ---------------------------------------------------------------------------
__global__ void prep1_kernel(const unsigned int* __restrict__ kmask_w, int nwords,
                             const float* __restrict__ lq1, const float* __restrict__ lk1,
                             const float* __restrict__ lq2, const float* __restrict__ lk2)
{
    const int t = threadIdx.x;
    if (blockIdx.x == 0) {
        __shared__ int bad_i32, bad_f32, any_nz;
        if (t == 0) { bad_i32 = 0; bad_f32 = 0; any_nz = 0; }
        __syncthreads();
        for (int i = t; i < nwords; i += blockDim.x) {
            unsigned int v = kmask_w[i];
            if (v != 0u) {
                atomicOr(&any_nz, 1);
                if (v != 1u)           atomicOr(&bad_i32, 1);
                if (v != 0x3F800000u)  atomicOr(&bad_f32, 1);
            }
        }
        __syncthreads();
        if (t == 0) {
            int mode = 0;
            if (any_nz && !bad_i32)      mode = 1;
            else if (any_nz && !bad_f32) mode = 2;
            g_mode = mode;
        }
    } else {
        __shared__ float r1[256], r2[256];
        float a = 0.f, b = 0.f;
        for (int i = t; i < NHD; i += 256) { a += lq1[i] * lk1[i]; b += lq2[i] * lk2[i]; }
        r1[t] = a; r2[t] = b; __syncthreads();
        for (int s = 128; s > 0; s >>= 1) {
            if (t < s) { r1[t] += r1[t + s]; r2[t] += r2[t + s]; }
            __syncthreads();
        }
        if (t == 0) g_lam = expf(r1[0]) - expf(r2[0]) + 0.2f;
    }
}

// ---------------------------------------------------------------------------
// prep2: fused f2h(query), f2h(key), 4 weight transposes, mask expansion.
// Block ranges (all 256 threads):
//   [0,3072)      f2h query (786432 float4s)
//   [3072,4096)   f2h key   (262144 float4s)
//   [4096,4672)   transpose Wq  (24x24)
//   [4672,4696)   transpose Wk  (24x1)
//   [4696,4720)   transpose Wv  (24x1)
//   [4720,5296)   transpose Wout(24x24)
//   [5296,5424)   expand masks (128 blocks)
// ---------------------------------------------------------------------------
__device__ __forceinline__ unsigned char read_mask(const void* p, int i, int mode)
{
    if (mode == 1) return ((const int*)p)[i] != 0;
    if (mode == 2) return ((const float*)p)[i] != 0.0f;
    return ((const unsigned char*)p)[i] != 0;
}

__device__ __forceinline__ void do_f2h(const float* __restrict__ in,
                                       __half* __restrict__ out, int idx, int n4)
{
    if (idx < n4) {
        float4 v = ((const float4*)in)[idx];
        ((__half2*)out)[2 * idx]     = __floats2half2_rn(v.x, v.y);
        ((__half2*)out)[2 * idx + 1] = __floats2half2_rn(v.z, v.w);
    }
}

__device__ __forceinline__ void do_transpose(const float* __restrict__ in,
                                             __half* __restrict__ out,
                                             int rows, int cols, int bx, int by)
{
    __shared__ float tile[32][33];
    const int t = threadIdx.x;
    const int x = t & 31, y = t >> 5;
    const int c0 = bx * 32, r0 = by * 32;
    for (int i = 0; i < 32; i += 8) {
        int r = r0 + y + i, c = c0 + x;
        if (r < rows && c < cols) tile[y + i][x] = in[(long)r * cols + c];
    }
    __syncthreads();
    for (int i = 0; i < 32; i += 8) {
        int r = c0 + y + i, c = r0 + x;
        if (r < cols && c < rows) out[(long)r * rows + c] = __float2half_rn(tile[x][y + i]);
    }
}

__global__ void prep2_kernel(const float* __restrict__ query, const float* __restrict__ key,
                             const void* __restrict__ qmask, const void* __restrict__ kmask,
                             const float* __restrict__ Wq, const float* __restrict__ Wk,
                             const float* __restrict__ Wv, const float* __restrict__ Wout)
{
    const int blk = blockIdx.x;
    const int t = threadIdx.x;
    if (blk < 3072) {
        do_f2h(query, g_Qin, blk * 256 + t, NB * NS * NE / 4);
    } else if (blk < 4096) {
        do_f2h(key, g_Kin, (blk - 3072) * 256 + t, NB * NL * NGE / 4);
    } else if (blk < 4672) {
        int r = blk - 4096;
        do_transpose(Wq, g_WqT, NE, NE, r % 24, r / 24);
    } else if (blk < 4696) {
        do_transpose(Wk, g_WkT, NGE, NE, blk - 4672, 0);
    } else if (blk < 4720) {
        do_transpose(Wv, g_WvT, NGE, NE, blk - 4696, 0);
    } else if (blk < 5296) {
        int r = blk - 4720;
        do_transpose(Wout, g_WoT, NE, NE, r % 24, r / 24);
    } else {
        int i = (blk - 5296) * 256 + t;
        int mode = g_mode;
        if (i < NB * NS) g_qm[i] = read_mask(qmask, i, mode);
        if (i < NB * NL) g_km[i] = read_mask(kmask, i, mode);
    }
}

// ---------------------------------------------------------------------------
// fp16 NT GEMM core, templated on BKH (K-tile in halves: 32 or 64).
// ---------------------------------------------------------------------------
#define STAGES 3
#define SMEM_OF(BKH) (STAGES * 2 * 128 * ((BKH) + 8) * 2)

template<int BKH, int EPI>
__device__ __forceinline__ void gemm_h(
    const __half* __restrict__ A, const __half* __restrict__ B, void* __restrict__ Cv,
    int K, int lda, int ldb, int ldc, float alpha,
    const unsigned char* __restrict__ qm, const unsigned char* __restrict__ km)
{
    constexpr int PITCHB   = (BKH + 8) * 2;
    constexpr int OPB      = 128 * PITCHB;
    constexpr int STGB     = 2 * OPB;
    constexpr int CPR      = BKH / 8;
    constexpr int LDITER   = BKH / 16;
    constexpr int KKS      = BKH / 16;

    extern __shared__ char smc[];
    const unsigned smb = (unsigned)__cvta_generic_to_shared(smc);

    const int tid  = threadIdx.x;
    const int lane = tid & 31;
    const int wid  = tid >> 5;
    const int wm   = wid & 3;
    const int wn   = wid >> 2;
    const int lc   = lane & 3;
    const int lr   = lane >> 2;
    const int bm   = blockIdx.y * 128;
    const int bn   = blockIdx.x * 128;

    const unsigned a_lane = smb + (unsigned)((wm * 32 + (lane & 15)) * PITCHB
                                             + (lane >> 4) * 16);
    const unsigned b_lane = smb + (unsigned)(OPB + (wn * 64 + (lane & 15)) * PITCHB
                                             + (lane >> 4) * 16);

    float d[2][8][4];
#pragma unroll
    for (int mt = 0; mt < 2; mt++)
#pragma unroll
        for (int nt = 0; nt < 8; nt++)
#pragma unroll
            for (int i = 0; i < 4; i++) d[mt][nt][i] = 0.f;

    const int ntile = K / BKH;

#define ISSUE_TILE(T, ST)                                                          \
    do {                                                                           \
        const int k0_ = (T) * BKH;                                                 \
        const unsigned sg_ = smb + (unsigned)(ST) * STGB;                          \
        _Pragma("unroll")                                                          \
        for (int i_ = 0; i_ < LDITER; i_++) {                                      \
            int idx_ = i_ * 256 + tid;                                             \
            int row_ = idx_ / CPR, ch_ = idx_ % CPR;                               \
            unsigned off_ = (unsigned)(row_ * PITCHB + ch_ * 16);                  \
            cpa16(sg_ + off_, A + (long)(bm + row_) * lda + k0_ + ch_ * 8);        \
            cpa16(sg_ + OPB + off_, B + (long)(bn + row_) * ldb + k0_ + ch_ * 8);  \
        }                                                                          \
    } while (0)

#pragma unroll
    for (int s = 0; s < STAGES - 1; s++) {
        if (s < ntile) ISSUE_TILE(s, s);
        asm volatile("cp.async.commit_group;");
    }

    int stq = 0;
    for (int t = 0; t < ntile; t++) {
        asm volatile("cp.async.wait_group %0;" :: "n"(STAGES - 2));
        __syncthreads();
        {
            int tp = t + STAGES - 1;
            if (tp < ntile) {
                int stp = stq + STAGES - 1; if (stp >= STAGES) stp -= STAGES;
                ISSUE_TILE(tp, stp);
            }
        }
        asm volatile("cp.async.commit_group;");

        const unsigned sgb = (unsigned)stq * STGB;
        const unsigned sa = a_lane + sgb;
        const unsigned sb = b_lane + sgb;
#pragma unroll
        for (int kk = 0; kk < KKS; kk++) {
            unsigned af[2][4];
#pragma unroll
            for (int mt = 0; mt < 2; mt++)
                ldm4(af[mt][0], af[mt][1], af[mt][2], af[mt][3],
                     sa + mt * (16 * PITCHB) + kk * 32);
#pragma unroll
            for (int nb = 0; nb < 4; nb++) {
                unsigned b0, b1, b2, b3;
                ldm4(b0, b1, b2, b3, sb + nb * (16 * PITCHB) + kk * 32);
                unsigned bf0[2] = { b0, b2 };
                unsigned bf1[2] = { b1, b3 };
                mma16(d[0][2 * nb + 0], af[0], bf0);
                mma16(d[0][2 * nb + 1], af[0], bf1);
                mma16(d[1][2 * nb + 0], af[1], bf0);
                mma16(d[1][2 * nb + 1], af[1], bf1);
            }
        }
        if (++stq == STAGES) stq = 0;
    }
#undef ISSUE_TILE

#pragma unroll
    for (int mt = 0; mt < 2; mt++) {
        const int m0 = bm + wm * 32 + mt * 16 + lr;
        const bool qa = (EPI == 3) ? (qm[m0] != 0)     : true;
        const bool qb = (EPI == 3) ? (qm[m0 + 8] != 0) : true;
#pragma unroll
        for (int nt = 0; nt < 8; nt++) {
            const int n0 = bn + wn * 64 + nt * 8 + lc * 2;
            if (EPI == 2) {
                __half* Ch = (__half*)Cv;
                *(__half2*)(Ch + (long)m0 * ldc + n0) =
                    __floats2half2_rn(alpha * d[mt][nt][0], alpha * d[mt][nt][1]);
                *(__half2*)(Ch + (long)(m0 + 8) * ldc + n0) =
                    __floats2half2_rn(alpha * d[mt][nt][2], alpha * d[mt][nt][3]);
            } else if (EPI == 3) {
                __half* Ch = (__half*)Cv;
                const bool k0m = km[n0] != 0;
                const bool k1m = km[n0 + 1] != 0;
                float v0 = (qa && k0m) ? d[mt][nt][0] : MASKVAL;
                float v1 = (qa && k1m) ? d[mt][nt][1] : MASKVAL;
                float v2 = (qb && k0m) ? d[mt][nt][2] : MASKVAL;
                float v3 = (qb && k1m) ? d[mt][nt][3] : MASKVAL;
                *(__half2*)(Ch + (long)m0 * ldc + n0)       = __floats2half2_rn(v0, v1);
                *(__half2*)(Ch + (long)(m0 + 8) * ldc + n0) = __floats2half2_rn(v2, v3);
            } else {
                float* C = (float*)Cv;
                float2 v01 = make_float2(alpha * d[mt][nt][0], alpha * d[mt][nt][1]);
                float2 v23 = make_float2(alpha * d[mt][nt][2], alpha * d[mt][nt][3]);
                *(float2*)(C + (long)m0 * ldc + n0)       = v01;
                *(float2*)(C + (long)(m0 + 8) * ldc + n0) = v23;
            }
        }
    }
}

// Entry points --------------------------------------------------------------
__global__ void __launch_bounds__(256, 2) k_projq_h(float unused)
{
    const float qscale = 0.051031036307982884f;   // 1/sqrt(384)
    gemm_h<64, 2>(g_Qin, g_WqT, g_Qh, NE, NE, NE, NE, qscale, nullptr, nullptr);
}

__global__ void __launch_bounds__(256, 2) k_proj32_h(
    const __half* __restrict__ A, const __half* __restrict__ B, __half* __restrict__ C,
    int lda, int ldb, int ldc, long sA, long sB, long sC)
{
    gemm_h<32, 2>(A + (long)blockIdx.z * sA, B + (long)blockIdx.z * sB,
                  C + (long)blockIdx.z * sC, NGE, lda, ldb, ldc, 1.0f, nullptr, nullptr);
}

__global__ void __launch_bounds__(256, 2) k_scores_h()
{
    const int z = blockIdx.z, b = z >> 1, h = z & 1;
    gemm_h<64, 3>(g_Qh + (long)b * NS * NE + h * NHD,
                  g_Kh + (long)b * NL * NE + h * NHD,
                  g_Sch + (long)z * NS * NL,
                  NHD, NE, NE, NL, 1.0f,
                  g_qm + b * NS, g_km + b * NL);
}

__global__ void __launch_bounds__(256, 2) k_dwv_h(float* __restrict__ part)
{
    const int z = blockIdx.z, b = z >> 2, c = z & 3;
    gemm_h<64, 0>(g_dwh + (long)b * NS * NL + c * 1024,
                  g_Vth + (long)b * NE * NL + c * 1024,
                  part + (long)z * NS * NE,
                  1024, NL, NL, NE, 1.0f, nullptr, nullptr);
}

__global__ void __launch_bounds__(256, 2) k_wout_h(float* __restrict__ out)
{
    gemm_h<64, 0>(g_Oh, g_WoT, out, NE, NE, NE, NE, 1.0f, nullptr, nullptr);
}

// ---------------------------------------------------------------------------
// Register-resident dual softmax -> differential weights.
// One block (256 thr) per (b,s) row; each thread owns 16 elements per head
// (two uint4 chunks of 8 halves at i = 8t + 2048j). Shuffle+smem reductions.
// ---------------------------------------------------------------------------
__device__ __forceinline__ float blk_red(float v, float* sm, int t, int op)
{
    // op 0: max, 1: sum, 2: min
#pragma unroll
    for (int o = 16; o; o >>= 1) {
        float u = __shfl_xor_sync(0xFFFFFFFFu, v, o);
        v = (op == 0) ? fmaxf(v, u) : (op == 1) ? v + u : fminf(v, u);
    }
    if ((t & 31) == 0) sm[t >> 5] = v;
    __syncthreads();
    float r = sm[0];
#pragma unroll
    for (int w = 1; w < 8; w++) {
        float u = sm[w];
        r = (op == 0) ? fmaxf(r, u) : (op == 1) ? r + u : fminf(r, u);
    }
    __syncthreads();
    return r;
}

__global__ void __launch_bounds__(256) softmax_dw_kernel(float* __restrict__ dw_out)
{
    __shared__ float sm[8];
    const int row = blockIdx.x;
    const int b = row >> 9;
    const int t = threadIdx.x;
    const __half* r0 = g_Sch + ((long)(b * 2 + 0) * NS + (row & (NS - 1))) * NL;
    const __half* r1 = g_Sch + ((long)(b * 2 + 1) * NS + (row & (NS - 1))) * NL;

    float v0[16], v1[16];
    float m0 = -3.4e38f, m1 = -3.4e38f;
#pragma unroll
    for (int j = 0; j < 2; j++) {
        const int i = 8 * t + 2048 * j;
        uint4 u0 = *(const uint4*)(r0 + i);
        uint4 u1 = *(const uint4*)(r1 + i);
        const unsigned* w0 = (const unsigned*)&u0;
        const unsigned* w1 = (const unsigned*)&u1;
#pragma unroll
        for (int k = 0; k < 4; k++) {
            float2 f0 = __half22float2(*(const __half2*)&w0[k]);
            float2 f1 = __half22float2(*(const __half2*)&w1[k]);
            v0[8 * j + 2 * k]     = f0.x; v0[8 * j + 2 * k + 1] = f0.y;
            v1[8 * j + 2 * k]     = f1.x; v1[8 * j + 2 * k + 1] = f1.y;
            m0 = fmaxf(m0, fmaxf(f0.x, f0.y));
            m1 = fmaxf(m1, fmaxf(f1.x, f1.y));
        }
    }
    m0 = blk_red(m0, sm, t, 0);
    m1 = blk_red(m1, sm, t, 0);

    float sum0 = 0.f, sum1 = 0.f;
#pragma unroll
    for (int k = 0; k < 16; k++) {
        v0[k] = expf(v0[k] - m0); sum0 += v0[k];
        v1[k] = expf(v1[k] - m1); sum1 += v1[k];
    }
    sum0 = blk_red(sum0, sm, t, 1);
    sum1 = blk_red(sum1, sm, t, 1);

    const float inv0 = 1.f / (sum0 + 1e-8f);
    const float inv1 = 1.f / (sum1 + 1e-8f);
    const float lam = g_lam;
    float mn = 3.4e38f;
#pragma unroll
    for (int k = 0; k < 16; k++) {
        v0[k] = v0[k] * inv0 - lam * (v1[k] * inv1);
        mn = fminf(mn, v0[k]);
    }
    mn = blk_red(mn, sm, t, 2);

    const unsigned char qv = g_qm[row];
    const unsigned char* km = g_km + b * NL;
    float*  o  = dw_out + (long)row * NL;
    __half* oh = g_dwh  + (long)row * NL;
#pragma unroll
    for (int j = 0; j < 2; j++) {
        const int i = 8 * t + 2048 * j;
        uint2 kmu = *(const uint2*)(km + i);
        const unsigned char* kb = (const unsigned char*)&kmu;
        float r[8];
        unsigned hh[4];
#pragma unroll
        for (int k = 0; k < 8; k++) {
            float v = v0[8 * j + k] - mn + 1e-5f;
            if (!qv || !kb[k]) v = 0.f;
            r[k] = v;
        }
#pragma unroll
        for (int k = 0; k < 4; k++) {
            __half2 h = __floats2half2_rn(r[2 * k], r[2 * k + 1]);
            hh[k] = *(const unsigned*)&h;
        }
        *(float4*)(o + i)     = make_float4(r[0], r[1], r[2], r[3]);
        *(float4*)(o + i + 4) = make_float4(r[4], r[5], r[6], r[7]);
        *(uint4*)(oh + i) = make_uint4(hh[0], hh[1], hh[2], hh[3]);
    }
}

// ---------------------------------------------------------------------------
// Sum 4 split-K partials + RMSNorm * rms_w * (1 - LAMBDA_INIT) -> fp16 O
// ---------------------------------------------------------------------------
__global__ void __launch_bounds__(256) rmsnorm4_kernel(const float* __restrict__ part,
                                                       __half* __restrict__ O,
                                                       const float* __restrict__ w)
{
    __shared__ float red[256];
    __shared__ float buf[NE];
    const int row = blockIdx.x;
    const int b = row >> 9, s = row & (NS - 1);
    const int t = threadIdx.x;
    const long base0 = ((long)(b * 4 + 0) * NS + s) * NE;
    const long base1 = ((long)(b * 4 + 1) * NS + s) * NE;
    const long base2 = ((long)(b * 4 + 2) * NS + s) * NE;
    const long base3 = ((long)(b * 4 + 3) * NS + s) * NE;
    float ss = 0.f;
    for (int i = t; i < NE; i += 256) {
        float v = part[base0 + i] + part[base1 + i] + part[base2 + i] + part[base3 + i];
        buf[i] = v;
        ss += v * v;
    }
    red[t] = ss; __syncthreads();
    for (int st = 128; st > 0; st >>= 1) { if (t < st) red[t] += red[t + st]; __syncthreads(); }
    const float sc = (1.0f / sqrtf(red[0] / (float)NE + 1e-5f)) * 0.8f;
    __half* o = O + (long)row * NE;
    for (int i = t; i < NE; i += 256) o[i] = __float2half_rn(buf[i] * sc * w[i]);
}

// ---------------------------------------------------------------------------
// Launch
// ---------------------------------------------------------------------------
extern "C" void kernel_launch(void* const* d_in, const int* in_sizes, int n_in,
                              void* d_out, int out_size)
{
    const float* query = (const float*)d_in[0];
    const float* key   = (const float*)d_in[1];
    const void*  qmask = d_in[2];
    const void*  kmask = d_in[3];
    const float* Wq    = (const float*)d_in[4];
    const float* Wk    = (const float*)d_in[5];
    const float* Wv    = (const float*)d_in[6];
    const float* Wout  = (const float*)d_in[7];
    const float* lq1   = (const float*)d_in[8];
    const float* lk1   = (const float*)d_in[9];
    const float* lq2   = (const float*)d_in[10];
    const float* lk2   = (const float*)d_in[11];
    const float* rms_w = (const float*)d_in[12];

    float* out = (float*)d_out;
    float* dw  = out + (long)NB * NS * NE;

    void* p;
    __half *Qinp, *Kinp, *WkTp, *WvTp, *Khp, *Vthp, *Ohp;
    float *Partp;
    cudaGetSymbolAddress(&p, g_Qin);  Qinp  = (__half*)p;
    cudaGetSymbolAddress(&p, g_Kin);  Kinp  = (__half*)p;
    cudaGetSymbolAddress(&p, g_WkT);  WkTp  = (__half*)p;
    cudaGetSymbolAddress(&p, g_WvT);  WvTp  = (__half*)p;
    cudaGetSymbolAddress(&p, g_Kh);   Khp   = (__half*)p;
    cudaGetSymbolAddress(&p, g_Vth);  Vthp  = (__half*)p;
    cudaGetSymbolAddress(&p, g_Oh);   Ohp   = (__half*)p;
    cudaGetSymbolAddress(&p, g_Part); Partp = (float*)p;

    const int SM32 = SMEM_OF(32);
    const int SM64 = SMEM_OF(64);
    cudaFuncSetAttribute(k_projq_h,  cudaFuncAttributeMaxDynamicSharedMemorySize, SM64);
    cudaFuncSetAttribute(k_proj32_h, cudaFuncAttributeMaxDynamicSharedMemorySize, SM32);
    cudaFuncSetAttribute(k_scores_h, cudaFuncAttributeMaxDynamicSharedMemorySize, SM64);
    cudaFuncSetAttribute(k_dwv_h,    cudaFuncAttributeMaxDynamicSharedMemorySize, SM64);
    cudaFuncSetAttribute(k_wout_h,   cudaFuncAttributeMaxDynamicSharedMemorySize, SM64);

    // 0) fused prep
    prep1_kernel<<<2, 256>>>((const unsigned int*)kmask, (NB * NL) / 4,
                             lq1, lk1, lq2, lk2);
    prep2_kernel<<<5424, 256>>>(query, key, qmask, kmask, Wq, Wk, Wv, Wout);

    // 1) projections
    k_projq_h<<<dim3(NE / 128, (NB * NS) / 128), 256, SM64>>>(0.f);
    k_proj32_h<<<dim3(NE / 128, (NB * NL) / 128, 1), 256, SM32>>>(
        Kinp, WkTp, Khp, NGE, NGE, NE, 0, 0, 0);
    k_proj32_h<<<dim3(NL / 128, NE / 128, NB), 256, SM32>>>(
        WvTp, Kinp, Vthp, NGE, NGE, NL,
        0, (long)NL * NGE, (long)NE * NL);

    // 2) masked scores -> fp16
    k_scores_h<<<dim3(NL / 128, NS / 128, NB * 2), 256, SM64>>>();

    // 3) dual softmax -> dw (fp32 to d_out + fp16 copy)
    softmax_dw_kernel<<<NB * NS, 256>>>(dw);

    // 4) o = dw @ V (split-K=4, fp32 partials)
    k_dwv_h<<<dim3(NE / 128, NS / 128, NB * 4), 256, SM64>>>(Partp);

    // 5) reduce + RMSNorm -> fp16 O
    rmsnorm4_kernel<<<NB * NS, 256>>>(Partp, Ohp, rms_w);

    // 6) out = O @ Wout (fp32 out)
    k_wout_h<<<dim3(NE / 128, (NB * NS) / 128), 256, SM64>>>(out);
}

// round 15
// speedup vs baseline: 2.1469x; 1.0545x over previous
#include <cuda_runtime.h>
#include <cuda_fp16.h>
#include <math.h>

#define NB 8
#define NS 512
#define NL 4096
#define NE 768
#define NHD 384
#define NGE 32

// ---------------------------------------------------------------------------
// Static device scratch
// ---------------------------------------------------------------------------
__device__ __half g_Qin[NB * NS * NE];
__device__ __half g_Kin[NB * NL * NGE];
__device__ __half g_Qh [NB * NS * NE];
__device__ __half g_Kh [NB * NL * NE];
__device__ __half g_Vth[NB * NE * NL];      // V transposed [b][e][l]
__device__ __half g_dwh[NB * NS * NL];      // fp16 copy of dw
__device__ __half g_Oh [NB * NS * NE];
__device__ __half g_Sch[NB * 2 * NS * NL];  // fp16 masked scores
__device__ float  g_Part[NB * 4 * NS * NE]; // split-K=4 fp32 partials
__device__ __half g_WqT[NE * NE];
__device__ __half g_WkT[NE * NGE];
__device__ __half g_WvT[NE * NGE];
__device__ __half g_WoT[NE * NE];
__device__ unsigned char g_qm[NB * NS];
__device__ unsigned char g_km[NB * NL];
__device__ float g_lam;
__device__ int   g_mode;

#define MASKVAL (-60000.0f)

// ---------------------------------------------------------------------------
// PTX helpers
// ---------------------------------------------------------------------------
__device__ __forceinline__ void cpa16(unsigned dst, const void* src)
{
    asm volatile("cp.async.cg.shared.global [%0], [%1], 16;" :: "r"(dst), "l"(src));
}
__device__ __forceinline__ void ldm4(unsigned& r0, unsigned& r1, unsigned& r2, unsigned& r3,
                                     unsigned addr)
{
    asm volatile("ldmatrix.sync.aligned.m8n8.x4.shared.b16 {%0,%1,%2,%3}, [%4];"
                 : "=r"(r0), "=r"(r1), "=r"(r2), "=r"(r3) : "r"(addr));
}
__device__ __forceinline__ void mma16(float* d, const unsigned* a, const unsigned* b)
{
    asm volatile(
        "mma.sync.aligned.m16n8k16.row.col.f32.f16.f16.f32 "
        "{%0,%1,%2,%3}, {%4,%5,%6,%7}, {%8,%9}, {%0,%1,%2,%3};"
        : "+f"(d[0]), "+f"(d[1]), "+f"(d[2]), "+f"(d[3])
        : "r"(a[0]), "r"(a[1]), "r"(a[2]), "r"(a[3]), "r"(b[0]), "r"(b[1]));
}

// ---------------------------------------------------------------------------
// prep1: block 0 = mask dtype detection, block 1 = lambda
// ---------------------------------------------------------------------------
__global__ void prep1_kernel(const unsigned int* __restrict__ kmask_w, int nwords,
                             const float* __restrict__ lq1, const float* __restrict__ lk1,
                             const float* __restrict__ lq2, const float* __restrict__ lk2)
{
    const int t = threadIdx.x;
    if (blockIdx.x == 0) {
        __shared__ int bad_i32, bad_f32, any_nz;
        if (t == 0) { bad_i32 = 0; bad_f32 = 0; any_nz = 0; }
        __syncthreads();
        for (int i = t; i < nwords; i += blockDim.x) {
            unsigned int v = kmask_w[i];
            if (v != 0u) {
                atomicOr(&any_nz, 1);
                if (v != 1u)           atomicOr(&bad_i32, 1);
                if (v != 0x3F800000u)  atomicOr(&bad_f32, 1);
            }
        }
        __syncthreads();
        if (t == 0) {
            int mode = 0;
            if (any_nz && !bad_i32)      mode = 1;
            else if (any_nz && !bad_f32) mode = 2;
            g_mode = mode;
        }
    } else {
        __shared__ float r1[256], r2[256];
        float a = 0.f, b = 0.f;
        for (int i = t; i < NHD; i += 256) { a += lq1[i] * lk1[i]; b += lq2[i] * lk2[i]; }
        r1[t] = a; r2[t] = b; __syncthreads();
        for (int s = 128; s > 0; s >>= 1) {
            if (t < s) { r1[t] += r1[t + s]; r2[t] += r2[t + s]; }
            __syncthreads();
        }
        if (t == 0) g_lam = expf(r1[0]) - expf(r2[0]) + 0.2f;
    }
}

// ---------------------------------------------------------------------------
// prep2: fused f2h + weight transposes + mask expansion (block dispatch)
// ---------------------------------------------------------------------------
__device__ __forceinline__ unsigned char read_mask(const void* p, int i, int mode)
{
    if (mode == 1) return ((const int*)p)[i] != 0;
    if (mode == 2) return ((const float*)p)[i] != 0.0f;
    return ((const unsigned char*)p)[i] != 0;
}

__device__ __forceinline__ void do_f2h(const float* __restrict__ in,
                                       __half* __restrict__ out, int idx, int n4)
{
    if (idx < n4) {
        float4 v = ((const float4*)in)[idx];
        ((__half2*)out)[2 * idx]     = __floats2half2_rn(v.x, v.y);
        ((__half2*)out)[2 * idx + 1] = __floats2half2_rn(v.z, v.w);
    }
}

__device__ __forceinline__ void do_transpose(const float* __restrict__ in,
                                             __half* __restrict__ out,
                                             int rows, int cols, int bx, int by)
{
    __shared__ float tile[32][33];
    const int t = threadIdx.x;
    const int x = t & 31, y = t >> 5;
    const int c0 = bx * 32, r0 = by * 32;
    for (int i = 0; i < 32; i += 8) {
        int r = r0 + y + i, c = c0 + x;
        if (r < rows && c < cols) tile[y + i][x] = in[(long)r * cols + c];
    }
    __syncthreads();
    for (int i = 0; i < 32; i += 8) {
        int r = c0 + y + i, c = r0 + x;
        if (r < cols && c < rows) out[(long)r * rows + c] = __float2half_rn(tile[x][y + i]);
    }
}

__global__ void prep2_kernel(const float* __restrict__ query, const float* __restrict__ key,
                             const void* __restrict__ qmask, const void* __restrict__ kmask,
                             const float* __restrict__ Wq, const float* __restrict__ Wk,
                             const float* __restrict__ Wv, const float* __restrict__ Wout)
{
    const int blk = blockIdx.x;
    const int t = threadIdx.x;
    if (blk < 3072) {
        do_f2h(query, g_Qin, blk * 256 + t, NB * NS * NE / 4);
    } else if (blk < 4096) {
        do_f2h(key, g_Kin, (blk - 3072) * 256 + t, NB * NL * NGE / 4);
    } else if (blk < 4672) {
        int r = blk - 4096;
        do_transpose(Wq, g_WqT, NE, NE, r % 24, r / 24);
    } else if (blk < 4696) {
        do_transpose(Wk, g_WkT, NGE, NE, blk - 4672, 0);
    } else if (blk < 4720) {
        do_transpose(Wv, g_WvT, NGE, NE, blk - 4696, 0);
    } else if (blk < 5296) {
        int r = blk - 4720;
        do_transpose(Wout, g_WoT, NE, NE, r % 24, r / 24);
    } else {
        int i = (blk - 5296) * 256 + t;
        int mode = g_mode;
        if (i < NB * NS) g_qm[i] = read_mask(qmask, i, mode);
        if (i < NB * NL) g_km[i] = read_mask(kmask, i, mode);
    }
}

// ---------------------------------------------------------------------------
// fp16 NT GEMM core, templated on BKH; explicit bm/bn (for fused dispatch).
// ---------------------------------------------------------------------------
#define STAGES 3
#define SMEM_OF(BKH) (STAGES * 2 * 128 * ((BKH) + 8) * 2)

template<int BKH, int EPI>
__device__ __forceinline__ void gemm_h(
    const __half* __restrict__ A, const __half* __restrict__ B, void* __restrict__ Cv,
    int K, int lda, int ldb, int ldc, float alpha, int bm, int bn,
    const unsigned char* __restrict__ qm, const unsigned char* __restrict__ km)
{
    constexpr int PITCHB   = (BKH + 8) * 2;
    constexpr int OPB      = 128 * PITCHB;
    constexpr int STGB     = 2 * OPB;
    constexpr int CPR      = BKH / 8;
    constexpr int LDITER   = BKH / 16;
    constexpr int KKS      = BKH / 16;

    extern __shared__ char smc[];
    const unsigned smb = (unsigned)__cvta_generic_to_shared(smc);

    const int tid  = threadIdx.x;
    const int lane = tid & 31;
    const int wid  = tid >> 5;
    const int wm   = wid & 3;
    const int wn   = wid >> 2;
    const int lc   = lane & 3;
    const int lr   = lane >> 2;

    const unsigned a_lane = smb + (unsigned)((wm * 32 + (lane & 15)) * PITCHB
                                             + (lane >> 4) * 16);
    const unsigned b_lane = smb + (unsigned)(OPB + (wn * 64 + (lane & 15)) * PITCHB
                                             + (lane >> 4) * 16);

    float d[2][8][4];
#pragma unroll
    for (int mt = 0; mt < 2; mt++)
#pragma unroll
        for (int nt = 0; nt < 8; nt++)
#pragma unroll
            for (int i = 0; i < 4; i++) d[mt][nt][i] = 0.f;

    const int ntile = K / BKH;

#define ISSUE_TILE(T, ST)                                                          \
    do {                                                                           \
        const int k0_ = (T) * BKH;                                                 \
        const unsigned sg_ = smb + (unsigned)(ST) * STGB;                          \
        _Pragma("unroll")                                                          \
        for (int i_ = 0; i_ < LDITER; i_++) {                                      \
            int idx_ = i_ * 256 + tid;                                             \
            int row_ = idx_ / CPR, ch_ = idx_ % CPR;                               \
            unsigned off_ = (unsigned)(row_ * PITCHB + ch_ * 16);                  \
            cpa16(sg_ + off_, A + (long)(bm + row_) * lda + k0_ + ch_ * 8);        \
            cpa16(sg_ + OPB + off_, B + (long)(bn + row_) * ldb + k0_ + ch_ * 8);  \
        }                                                                          \
    } while (0)

#pragma unroll
    for (int s = 0; s < STAGES - 1; s++) {
        if (s < ntile) ISSUE_TILE(s, s);
        asm volatile("cp.async.commit_group;");
    }

    int stq = 0;
    for (int t = 0; t < ntile; t++) {
        asm volatile("cp.async.wait_group %0;" :: "n"(STAGES - 2));
        __syncthreads();
        {
            int tp = t + STAGES - 1;
            if (tp < ntile) {
                int stp = stq + STAGES - 1; if (stp >= STAGES) stp -= STAGES;
                ISSUE_TILE(tp, stp);
            }
        }
        asm volatile("cp.async.commit_group;");

        const unsigned sgb = (unsigned)stq * STGB;
        const unsigned sa = a_lane + sgb;
        const unsigned sb = b_lane + sgb;
#pragma unroll
        for (int kk = 0; kk < KKS; kk++) {
            unsigned af[2][4];
#pragma unroll
            for (int mt = 0; mt < 2; mt++)
                ldm4(af[mt][0], af[mt][1], af[mt][2], af[mt][3],
                     sa + mt * (16 * PITCHB) + kk * 32);
#pragma unroll
            for (int nb = 0; nb < 4; nb++) {
                unsigned b0, b1, b2, b3;
                ldm4(b0, b1, b2, b3, sb + nb * (16 * PITCHB) + kk * 32);
                unsigned bf0[2] = { b0, b2 };
                unsigned bf1[2] = { b1, b3 };
                mma16(d[0][2 * nb + 0], af[0], bf0);
                mma16(d[0][2 * nb + 1], af[0], bf1);
                mma16(d[1][2 * nb + 0], af[1], bf0);
                mma16(d[1][2 * nb + 1], af[1], bf1);
            }
        }
        if (++stq == STAGES) stq = 0;
    }
#undef ISSUE_TILE

#pragma unroll
    for (int mt = 0; mt < 2; mt++) {
        const int m0 = bm + wm * 32 + mt * 16 + lr;
        const bool qa = (EPI == 3) ? (qm[m0] != 0)     : true;
        const bool qb = (EPI == 3) ? (qm[m0 + 8] != 0) : true;
#pragma unroll
        for (int nt = 0; nt < 8; nt++) {
            const int n0 = bn + wn * 64 + nt * 8 + lc * 2;
            if (EPI == 2) {
                __half* Ch = (__half*)Cv;
                *(__half2*)(Ch + (long)m0 * ldc + n0) =
                    __floats2half2_rn(alpha * d[mt][nt][0], alpha * d[mt][nt][1]);
                *(__half2*)(Ch + (long)(m0 + 8) * ldc + n0) =
                    __floats2half2_rn(alpha * d[mt][nt][2], alpha * d[mt][nt][3]);
            } else if (EPI == 3) {
                __half* Ch = (__half*)Cv;
                const bool k0m = km[n0] != 0;
                const bool k1m = km[n0 + 1] != 0;
                float v0 = (qa && k0m) ? d[mt][nt][0] : MASKVAL;
                float v1 = (qa && k1m) ? d[mt][nt][1] : MASKVAL;
                float v2 = (qb && k0m) ? d[mt][nt][2] : MASKVAL;
                float v3 = (qb && k1m) ? d[mt][nt][3] : MASKVAL;
                *(__half2*)(Ch + (long)m0 * ldc + n0)       = __floats2half2_rn(v0, v1);
                *(__half2*)(Ch + (long)(m0 + 8) * ldc + n0) = __floats2half2_rn(v2, v3);
            } else {
                float* C = (float*)Cv;
                float2 v01 = make_float2(alpha * d[mt][nt][0], alpha * d[mt][nt][1]);
                float2 v23 = make_float2(alpha * d[mt][nt][2], alpha * d[mt][nt][3]);
                *(float2*)(C + (long)m0 * ldc + n0)       = v01;
                *(float2*)(C + (long)(m0 + 8) * ldc + n0) = v23;
            }
        }
    }
}

// ---------------------------------------------------------------------------
// Fused projections: one launch, block-range dispatch.
//   [0,192)       Q proj  (K=768, BK=64): bx = blk%6, by = blk/6
//   [192,1728)    K proj  (K=32):  idx=blk-192,  bx = idx%6,  by = idx/6
//   [1728,3264)   Vt proj (K=32):  idx=blk-1728, bx = idx%32, by = (idx/32)%6, bz = idx/192
// ---------------------------------------------------------------------------
__global__ void __launch_bounds__(256, 2) k_proj_all()
{
    const int blk = blockIdx.x;
    if (blk < 192) {
        const float qscale = 0.051031036307982884f;   // 1/sqrt(384)
        gemm_h<64, 2>(g_Qin, g_WqT, g_Qh, NE, NE, NE, NE, qscale,
                      (blk / 6) * 128, (blk % 6) * 128, nullptr, nullptr);
    } else if (blk < 1728) {
        const int idx = blk - 192;
        gemm_h<32, 2>(g_Kin, g_WkT, g_Kh, NGE, NGE, NGE, NE, 1.0f,
                      (idx / 6) * 128, (idx % 6) * 128, nullptr, nullptr);
    } else {
        const int idx = blk - 1728;
        const int bz = idx / 192;
        gemm_h<32, 2>(g_WvT, g_Kin + (long)bz * NL * NGE,
                      g_Vth + (long)bz * NE * NL, NGE, NGE, NGE, NL, 1.0f,
                      ((idx / 32) % 6) * 128, (idx % 32) * 128, nullptr, nullptr);
    }
}

__global__ void __launch_bounds__(256, 2) k_scores_h()
{
    const int z = blockIdx.z, b = z >> 1, h = z & 1;
    gemm_h<64, 3>(g_Qh + (long)b * NS * NE + h * NHD,
                  g_Kh + (long)b * NL * NE + h * NHD,
                  g_Sch + (long)z * NS * NL,
                  NHD, NE, NE, NL, 1.0f,
                  blockIdx.y * 128, blockIdx.x * 128,
                  g_qm + b * NS, g_km + b * NL);
}

__global__ void __launch_bounds__(256, 2) k_dwv_h(float* __restrict__ part)
{
    const int z = blockIdx.z, b = z >> 2, c = z & 3;
    gemm_h<64, 0>(g_dwh + (long)b * NS * NL + c * 1024,
                  g_Vth + (long)b * NE * NL + c * 1024,
                  part + (long)z * NS * NE,
                  1024, NL, NL, NE, 1.0f,
                  blockIdx.y * 128, blockIdx.x * 128, nullptr, nullptr);
}

__global__ void __launch_bounds__(256, 2) k_wout_h(float* __restrict__ out)
{
    gemm_h<64, 0>(g_Oh, g_WoT, out, NE, NE, NE, NE, 1.0f,
                  blockIdx.y * 128, blockIdx.x * 128, nullptr, nullptr);
}

// ---------------------------------------------------------------------------
// Register-resident dual softmax -> differential weights
// ---------------------------------------------------------------------------
__device__ __forceinline__ float blk_red(float v, float* sm, int t, int op)
{
#pragma unroll
    for (int o = 16; o; o >>= 1) {
        float u = __shfl_xor_sync(0xFFFFFFFFu, v, o);
        v = (op == 0) ? fmaxf(v, u) : (op == 1) ? v + u : fminf(v, u);
    }
    if ((t & 31) == 0) sm[t >> 5] = v;
    __syncthreads();
    float r = sm[0];
#pragma unroll
    for (int w = 1; w < 8; w++) {
        float u = sm[w];
        r = (op == 0) ? fmaxf(r, u) : (op == 1) ? r + u : fminf(r, u);
    }
    __syncthreads();
    return r;
}

__global__ void __launch_bounds__(256) softmax_dw_kernel(float* __restrict__ dw_out)
{
    __shared__ float sm[8];
    const int row = blockIdx.x;
    const int b = row >> 9;
    const int t = threadIdx.x;
    const __half* r0 = g_Sch + ((long)(b * 2 + 0) * NS + (row & (NS - 1))) * NL;
    const __half* r1 = g_Sch + ((long)(b * 2 + 1) * NS + (row & (NS - 1))) * NL;

    float v0[16], v1[16];
    float m0 = -3.4e38f, m1 = -3.4e38f;
#pragma unroll
    for (int j = 0; j < 2; j++) {
        const int i = 8 * t + 2048 * j;
        uint4 u0 = *(const uint4*)(r0 + i);
        uint4 u1 = *(const uint4*)(r1 + i);
        const unsigned* w0 = (const unsigned*)&u0;
        const unsigned* w1 = (const unsigned*)&u1;
#pragma unroll
        for (int k = 0; k < 4; k++) {
            float2 f0 = __half22float2(*(const __half2*)&w0[k]);
            float2 f1 = __half22float2(*(const __half2*)&w1[k]);
            v0[8 * j + 2 * k]     = f0.x; v0[8 * j + 2 * k + 1] = f0.y;
            v1[8 * j + 2 * k]     = f1.x; v1[8 * j + 2 * k + 1] = f1.y;
            m0 = fmaxf(m0, fmaxf(f0.x, f0.y));
            m1 = fmaxf(m1, fmaxf(f1.x, f1.y));
        }
    }
    m0 = blk_red(m0, sm, t, 0);
    m1 = blk_red(m1, sm, t, 0);

    float sum0 = 0.f, sum1 = 0.f;
#pragma unroll
    for (int k = 0; k < 16; k++) {
        v0[k] = expf(v0[k] - m0); sum0 += v0[k];
        v1[k] = expf(v1[k] - m1); sum1 += v1[k];
    }
    sum0 = blk_red(sum0, sm, t, 1);
    sum1 = blk_red(sum1, sm, t, 1);

    const float inv0 = 1.f / (sum0 + 1e-8f);
    const float inv1 = 1.f / (sum1 + 1e-8f);
    const float lam = g_lam;
    float mn = 3.4e38f;
#pragma unroll
    for (int k = 0; k < 16; k++) {
        v0[k] = v0[k] * inv0 - lam * (v1[k] * inv1);
        mn = fminf(mn, v0[k]);
    }
    mn = blk_red(mn, sm, t, 2);

    const unsigned char qv = g_qm[row];
    const unsigned char* km = g_km + b * NL;
    float*  o  = dw_out + (long)row * NL;
    __half* oh = g_dwh  + (long)row * NL;
#pragma unroll
    for (int j = 0; j < 2; j++) {
        const int i = 8 * t + 2048 * j;
        uint2 kmu = *(const uint2*)(km + i);
        const unsigned char* kb = (const unsigned char*)&kmu;
        float r[8];
        unsigned hh[4];
#pragma unroll
        for (int k = 0; k < 8; k++) {
            float v = v0[8 * j + k] - mn + 1e-5f;
            if (!qv || !kb[k]) v = 0.f;
            r[k] = v;
        }
#pragma unroll
        for (int k = 0; k < 4; k++) {
            __half2 h = __floats2half2_rn(r[2 * k], r[2 * k + 1]);
            hh[k] = *(const unsigned*)&h;
        }
        *(float4*)(o + i)     = make_float4(r[0], r[1], r[2], r[3]);
        *(float4*)(o + i + 4) = make_float4(r[4], r[5], r[6], r[7]);
        *(uint4*)(oh + i) = make_uint4(hh[0], hh[1], hh[2], hh[3]);
    }
}

// ---------------------------------------------------------------------------
// Sum 4 split-K partials + RMSNorm * rms_w * (1 - LAMBDA_INIT) -> fp16 O
// ---------------------------------------------------------------------------
__global__ void __launch_bounds__(256) rmsnorm4_kernel(const float* __restrict__ part,
                                                       __half* __restrict__ O,
                                                       const float* __restrict__ w)
{
    __shared__ float red[256];
    __shared__ float buf[NE];
    const int row = blockIdx.x;
    const int b = row >> 9, s = row & (NS - 1);
    const int t = threadIdx.x;
    const long base0 = ((long)(b * 4 + 0) * NS + s) * NE;
    const long base1 = ((long)(b * 4 + 1) * NS + s) * NE;
    const long base2 = ((long)(b * 4 + 2) * NS + s) * NE;
    const long base3 = ((long)(b * 4 + 3) * NS + s) * NE;
    float ss = 0.f;
    for (int i = t; i < NE; i += 256) {
        float v = part[base0 + i] + part[base1 + i] + part[base2 + i] + part[base3 + i];
        buf[i] = v;
        ss += v * v;
    }
    red[t] = ss; __syncthreads();
    for (int st = 128; st > 0; st >>= 1) { if (t < st) red[t] += red[t + st]; __syncthreads(); }
    const float sc = (1.0f / sqrtf(red[0] / (float)NE + 1e-5f)) * 0.8f;
    __half* o = O + (long)row * NE;
    for (int i = t; i < NE; i += 256) o[i] = __float2half_rn(buf[i] * sc * w[i]);
}

// ---------------------------------------------------------------------------
// Launch
// ---------------------------------------------------------------------------
extern "C" void kernel_launch(void* const* d_in, const int* in_sizes, int n_in,
                              void* d_out, int out_size)
{
    const float* query = (const float*)d_in[0];
    const float* key   = (const float*)d_in[1];
    const void*  qmask = d_in[2];
    const void*  kmask = d_in[3];
    const float* Wq    = (const float*)d_in[4];
    const float* Wk    = (const float*)d_in[5];
    const float* Wv    = (const float*)d_in[6];
    const float* Wout  = (const float*)d_in[7];
    const float* lq1   = (const float*)d_in[8];
    const float* lk1   = (const float*)d_in[9];
    const float* lq2   = (const float*)d_in[10];
    const float* lk2   = (const float*)d_in[11];
    const float* rms_w = (const float*)d_in[12];

    float* out = (float*)d_out;
    float* dw  = out + (long)NB * NS * NE;

    void* p;
    __half *Ohp;
    float *Partp;
    cudaGetSymbolAddress(&p, g_Oh);   Ohp   = (__half*)p;
    cudaGetSymbolAddress(&p, g_Part); Partp = (float*)p;

    const int SM64 = SMEM_OF(64);
    cudaFuncSetAttribute(k_proj_all, cudaFuncAttributeMaxDynamicSharedMemorySize, SM64);
    cudaFuncSetAttribute(k_scores_h, cudaFuncAttributeMaxDynamicSharedMemorySize, SM64);
    cudaFuncSetAttribute(k_dwv_h,    cudaFuncAttributeMaxDynamicSharedMemorySize, SM64);
    cudaFuncSetAttribute(k_wout_h,   cudaFuncAttributeMaxDynamicSharedMemorySize, SM64);

    // 0) fused prep
    prep1_kernel<<<2, 256>>>((const unsigned int*)kmask, (NB * NL) / 4,
                             lq1, lk1, lq2, lk2);
    prep2_kernel<<<5424, 256>>>(query, key, qmask, kmask, Wq, Wk, Wv, Wout);

    // 1) all projections in one launch
    k_proj_all<<<3264, 256, SM64>>>();

    // 2) masked scores -> fp16
    k_scores_h<<<dim3(NL / 128, NS / 128, NB * 2), 256, SM64>>>();

    // 3) dual softmax -> dw (fp32 to d_out + fp16 copy)
    softmax_dw_kernel<<<NB * NS, 256>>>(dw);

    // 4) o = dw @ V (split-K=4, fp32 partials)
    k_dwv_h<<<dim3(NE / 128, NS / 128, NB * 4), 256, SM64>>>(Partp);

    // 5) reduce + RMSNorm -> fp16 O
    rmsnorm4_kernel<<<NB * NS, 256>>>(Partp, Ohp, rms_w);

    // 6) out = O @ Wout (fp32 out)
    k_wout_h<<<dim3(NE / 128, (NB * NS) / 128), 256, SM64>>>(out);
}